// round 11
// baseline (speedup 1.0000x reference)
#include <cuda_runtime.h>
#include <cuda_fp16.h>
#include <math.h>
#include <cstdint>

// ---------------- problem constants ----------------
#define NQS   576
#define BATCH 16
#define MMD   1024
#define HIDD  4096
#define ROWS  (BATCH*NQS)        // 9216
#define HEADS 8
#define DH    128
#define NBH   (BATCH*HEADS)      // 128
#define KVS   2048               // merged K|V projection row stride

// ---------------- HMMA GEMM tiling (R6 proven: 128x128, 256 thr, 2 CTA/SM) ----------------
#define BM 128
#define BN 128
#define BK 64
#define STAGES 3
#define STAGE_BYTES ((BM+BN)*128)                    // 32 KB
#define SMEM_DYN (STAGES*STAGE_BYTES + 2048)
#define FA_SMEM (96*1024 + 1024)

// ---------------- scratch (device globals) ----------------
__device__ __align__(16) float  g_qp [NQS*MMD];              // fp16 q
__device__ __align__(16) float  g_kp [ROWS*MMD];             // fp16 kvproj (9216 x 2048)
__device__ __align__(16) float  g_vp [ROWS*MMD];             // fp16 pos16 + posk scratch
__device__ __align__(16) float  g_gates[ROWS*2];
__device__ __align__(16) __half g_x16   [ROWS*MMD];
__device__ __align__(16) __half g_kv16  [ROWS*MMD];
__device__ __align__(16) __half g_qn16  [NQS*MMD];
__device__ __align__(16) __half g_attn16[ROWS*MMD];
__device__ __align__(16) __half g_e1in16[ROWS*MMD];
__device__ __align__(16) __half g_h16   [(size_t)ROWS*HIDD];
__device__ __align__(16) __half g_ipw16 [3*MMD*MMD];
__device__ __align__(16) __half g_ow16  [MMD*MMD];
__device__ __align__(16) __half g_w116  [HIDD*MMD];
__device__ __align__(16) __half g_w216  [(size_t)HIDD*HIDD];

// ---------------- helpers ----------------
__device__ __forceinline__ uint32_t smem_to_u32(const void* p) {
    uint32_t a;
    asm("{ .reg .u64 t; cvta.to.shared.u64 t, %1; cvt.u32.u64 %0, t; }" : "=r"(a) : "l"(p));
    return a;
}
#define SWZ(o) ((o) ^ (((o) >> 3) & 0x70))

__device__ __forceinline__ void cp16(uint32_t dst, const void* src, uint32_t sz) {
    asm volatile("cp.async.cg.shared.global [%0], [%1], 16, %2;\n" :: "r"(dst), "l"(src), "r"(sz));
}
#define CP_COMMIT() asm volatile("cp.async.commit_group;\n")
#define CP_WAIT(n)  asm volatile("cp.async.wait_group %0;\n" :: "n"(n))

#define LDSM_X4(r0,r1,r2,r3,addr) \
    asm volatile("ldmatrix.sync.aligned.m8n8.x4.shared.b16 {%0,%1,%2,%3}, [%4];" \
        : "=r"(r0), "=r"(r1), "=r"(r2), "=r"(r3) : "r"(addr))
#define LDSM_X4_T(r0,r1,r2,r3,addr) \
    asm volatile("ldmatrix.sync.aligned.m8n8.x4.trans.shared.b16 {%0,%1,%2,%3}, [%4];" \
        : "=r"(r0), "=r"(r1), "=r"(r2), "=r"(r3) : "r"(addr))

#define MMA16816(c, a0,a1,a2,a3, b0,b1) \
    asm volatile("mma.sync.aligned.m16n8k16.row.col.f32.f16.f16.f32 " \
        "{%0,%1,%2,%3},{%4,%5,%6,%7},{%8,%9},{%0,%1,%2,%3};" \
        : "+f"((c)[0]), "+f"((c)[1]), "+f"((c)[2]), "+f"((c)[3]) \
        : "r"(a0), "r"(a1), "r"(a2), "r"(a3), "r"(b0), "r"(b1))

__device__ __forceinline__ float gelu_exact(float v) {
    return 0.5f * v * (1.0f + erff(v * 0.7071067811865476f));
}
__device__ __forceinline__ float softplusf_(float x) {
    return fmaxf(x, 0.0f) + log1pf(expf(-fabsf(x)));
}
__device__ __forceinline__ uint32_t pack_h2(float a, float b) {
    __half2 h = __floats2half2_rn(a, b);
    return *(uint32_t*)&h;
}

// ---------------- split fp32 -> fp16 conversions ----------------
#define N4_IPW (3*MMD*MMD/4)
#define N4_OW  (MMD*MMD/4)
#define N4_POS (NQS*MMD/4)
#define N4_W1  (HIDD*MMD/4)
#define N4_W2  (HIDD*HIDD/4)
#define N4_A   (N4_IPW+N4_OW+N4_POS)
#define N4_B   (N4_W1+N4_W2)

// main-stream: ipw + ow + pos
__global__ void __launch_bounds__(256) f2h_a_kernel(
    const float* __restrict__ ipw, __half* __restrict__ ipw16,
    const float* __restrict__ ow,  __half* __restrict__ ow16,
    const float* __restrict__ pos, __half* __restrict__ pos16)
{
    int i = blockIdx.x * blockDim.x + threadIdx.x;
    if (i >= N4_A) return;
    const float* src; __half* dst;
    if (i < N4_IPW) { src = ipw; dst = ipw16; }
    else if ((i -= N4_IPW) < N4_OW) { src = ow; dst = ow16; }
    else { i -= N4_OW; src = pos; dst = pos16; }
    float4 v = ((const float4*)src)[i];
    uint2 p;
    *((__half2*)&p.x) = __floats2half2_rn(v.x, v.y);
    *((__half2*)&p.y) = __floats2half2_rn(v.z, v.w);
    ((uint2*)dst)[i] = p;
}

// side-stream: W1 + W2
__global__ void __launch_bounds__(256) f2h_b_kernel(
    const float* __restrict__ W1, __half* __restrict__ w116,
    const float* __restrict__ W2, __half* __restrict__ w216)
{
    int i = blockIdx.x * blockDim.x + threadIdx.x;
    if (i >= N4_B) return;
    const float* src; __half* dst;
    if (i < N4_W1) { src = W1; dst = w116; }
    else { i -= N4_W1; src = W2; dst = w216; }
    float4 v = ((const float4*)src)[i];
    uint2 p;
    *((__half2*)&p.x) = __floats2half2_rn(v.x, v.y);
    *((__half2*)&p.y) = __floats2half2_rn(v.z, v.w);
    ((uint2*)dst)[i] = p;
}

// ---------------- fused LN(x) + gating + x16 emission: one read of x ----------------
__global__ void __launch_bounds__(256) lnxg_kernel(
    const float* __restrict__ x, const float* __restrict__ g,
    const float* __restrict__ b,
    const float* __restrict__ wg, const float* __restrict__ wn,
    const float* __restrict__ noise,
    __half* __restrict__ kv16, __half* __restrict__ x16,
    float* __restrict__ gates)
{
    const int row = blockIdx.x;
    const int t = threadIdx.x;

    const float4 xv = *(const float4*)(x + (size_t)row * MMD + t * 4);
    float s  = xv.x + xv.y + xv.z + xv.w;
    float ss = xv.x*xv.x + xv.y*xv.y + xv.z*xv.z + xv.w*xv.w;

    float4 wg0 = *(const float4*)(wg + 8*t);
    float4 wg1 = *(const float4*)(wg + 8*t + 4);
    float4 wn0 = *(const float4*)(wn + 8*t);
    float4 wn1 = *(const float4*)(wn + 8*t + 4);
    float d0 = xv.x*wg0.x + xv.y*wg0.z + xv.z*wg1.x + xv.w*wg1.z;
    float d1 = xv.x*wg0.y + xv.y*wg0.w + xv.z*wg1.y + xv.w*wg1.w;
    float d2 = xv.x*wn0.x + xv.y*wn0.z + xv.z*wn1.x + xv.w*wn1.z;
    float d3 = xv.x*wn0.y + xv.y*wn0.w + xv.z*wn1.y + xv.w*wn1.w;

    // emit x16 (free: x already in registers)
    uint2 ox;
    ox.x = pack_h2(xv.x, xv.y); ox.y = pack_h2(xv.z, xv.w);
    *(uint2*)(x16 + (size_t)row * MMD + t * 4) = ox;

    __shared__ float red[6][8];
    float vals[6] = {s, ss, d0, d1, d2, d3};
    #pragma unroll
    for (int j = 0; j < 6; j++)
        #pragma unroll
        for (int o = 16; o; o >>= 1)
            vals[j] += __shfl_xor_sync(0xffffffffu, vals[j], o);
    int wid = t >> 5, lid = t & 31;
    if (lid == 0)
        #pragma unroll
        for (int j = 0; j < 6; j++) red[j][wid] = vals[j];
    __syncthreads();

    float S = 0.f, SS = 0.f;
    #pragma unroll
    for (int w = 0; w < 8; w++) { S += red[0][w]; SS += red[1][w]; }
    float mu = S / MMD;
    float rstd = rsqrtf(SS / MMD - mu * mu + 1e-5f);

    float4 gv = *(const float4*)(g + t * 4);
    float4 bv = *(const float4*)(b + t * 4);
    uint2 o1;
    o1.x = pack_h2((xv.x - mu) * rstd * gv.x + bv.x, (xv.y - mu) * rstd * gv.y + bv.y);
    o1.y = pack_h2((xv.z - mu) * rstd * gv.z + bv.z, (xv.w - mu) * rstd * gv.w + bv.w);
    *(uint2*)(kv16 + (size_t)row * MMD + t * 4) = o1;

    if (t == 0) {
        float td[4] = {0.f, 0.f, 0.f, 0.f};
        #pragma unroll
        for (int w = 0; w < 8; w++)
            #pragma unroll
            for (int j = 0; j < 4; j++) td[j] += red[2 + j][w];
        float sp0 = softplusf_(td[2]) + 0.01f;
        float sp1 = softplusf_(td[3]) + 0.01f;
        float l0 = td[0] + noise[2*row]   * sp0;
        float l1 = td[1] + noise[2*row+1] * sp1;
        float mx = fmaxf(l0, l1);
        float e0 = expf(l0 - mx), e1 = expf(l1 - mx);
        float is = 1.0f / (e0 + e1);
        float p0 = e0 * is, p1 = e1 * is;
        float inv = 1.0f / (p0 + p1 + 1e-6f);
        gates[2*row]   = p0 * inv;
        gates[2*row+1] = p1 * inv;
    }
}

// ---------------- LN(query) + pos -> fp16, vectorized ----------------
__global__ void __launch_bounds__(256) lnq_kernel(
    const float* __restrict__ q, const float* __restrict__ g,
    const float* __restrict__ b, const float* __restrict__ pos,
    __half* __restrict__ qn16)
{
    const int row = blockIdx.x;
    const int t = threadIdx.x;
    const float4 xv = *(const float4*)(q + (size_t)row * MMD + t * 4);
    float s  = xv.x + xv.y + xv.z + xv.w;
    float ss = xv.x*xv.x + xv.y*xv.y + xv.z*xv.z + xv.w*xv.w;
    __shared__ float red[2][8];
    #pragma unroll
    for (int o = 16; o; o >>= 1) {
        s  += __shfl_xor_sync(0xffffffffu, s,  o);
        ss += __shfl_xor_sync(0xffffffffu, ss, o);
    }
    int wid = t >> 5, lid = t & 31;
    if (lid == 0) { red[0][wid] = s; red[1][wid] = ss; }
    __syncthreads();
    float S = 0.f, SS = 0.f;
    #pragma unroll
    for (int w = 0; w < 8; w++) { S += red[0][w]; SS += red[1][w]; }
    float mu = S / MMD;
    float rstd = rsqrtf(SS / MMD - mu * mu + 1e-5f);
    float4 gv = *(const float4*)(g + t * 4);
    float4 bv = *(const float4*)(b + t * 4);
    float4 pv = *(const float4*)(pos + (size_t)row * MMD + t * 4);
    uint2 o;
    o.x = pack_h2((xv.x - mu) * rstd * gv.x + bv.x + pv.x,
                  (xv.y - mu) * rstd * gv.y + bv.y + pv.y);
    o.y = pack_h2((xv.z - mu) * rstd * gv.z + bv.z + pv.z,
                  (xv.w - mu) * rstd * gv.w + bv.w + pv.w);
    *(uint2*)(qn16 + (size_t)row * MMD + t * 4) = o;
}

// ---------------- fp16 HMMA GEMM 128x128 (256 thr): C = A @ B^T ----------------
// EPI: 1 = fp16 +bias store, 2 = fp16 = g0*gelu(v+bias), 3 = fp16 += g1*gelu(v+bias),
//      4 = fp32 = acc + (g0+g1)*bias,
//      5 = fp16 merged-KV: +posk[gm%576] for gn<1024, +bias[gn] otherwise
__device__ __forceinline__ void load_stage(
    uint32_t stg, const __half* __restrict__ A, const __half* __restrict__ B,
    int row0, int col0, int M, int K, int kt, int tid)
{
    uint32_t sA = stg;
    uint32_t sB = stg + BM * 128;
    #pragma unroll
    for (int t = 0; t < 4; t++) {
        int op = tid + t * 256;
        int row = op >> 3, c = op & 7;
        int gr = row0 + row;
        uint32_t sz = (gr < M) ? 16u : 0u;
        if (gr >= M) gr = M - 1;
        cp16(sA + SWZ(row * 128 + c * 16), A + (size_t)gr * K + kt + c * 8, sz);
    }
    #pragma unroll
    for (int t = 0; t < 4; t++) {
        int op = tid + t * 256;
        int row = op >> 3, c = op & 7;
        cp16(sB + SWZ(row * 128 + c * 16), B + (size_t)(col0 + row) * K + kt + c * 8, 16u);
    }
}

template<int EPI>
__global__ void __launch_bounds__(256) hgemm(
    const __half* __restrict__ A, const __half* __restrict__ B,
    float* __restrict__ Cf, __half* __restrict__ Ch,
    int M, int N, int K,
    const float* __restrict__ bias, const float* __restrict__ gates,
    const __half* __restrict__ aux)
{
    extern __shared__ char smem[];
    uint32_t sb0 = (smem_to_u32(smem) + 1023) & ~1023u;
    const int tid = threadIdx.x;
    const int lane = tid & 31, warp = tid >> 5;
    const int wm = warp >> 1, wn = warp & 1;
    const int row0 = blockIdx.y * BM, col0 = blockIdx.x * BN;

    const int a_row = wm * 32 + (lane & 15);
    const int a_kh  = (lane >> 4) << 3;
    const int b_row = wn * 64 + ((lane >> 4) << 3) + (lane & 7);
    const int b_kh  = ((lane >> 3) & 1) << 3;

    float acc[2][8][4];
    #pragma unroll
    for (int mi = 0; mi < 2; mi++)
        #pragma unroll
        for (int ni = 0; ni < 8; ni++)
            #pragma unroll
            for (int q = 0; q < 4; q++) acc[mi][ni][q] = 0.f;

    const int nchunk = K / BK;

    #pragma unroll
    for (int j = 0; j < STAGES - 1; j++) {
        load_stage(sb0 + j * STAGE_BYTES, A, B, row0, col0, M, K, j * BK, tid);
        CP_COMMIT();
    }

    for (int i = 0; i < nchunk; i++) {
        if (i + 1 == nchunk) CP_WAIT(0); else CP_WAIT(STAGES - 2);
        __syncthreads();

        uint32_t stg = sb0 + (i % STAGES) * STAGE_BYTES;
        uint32_t sA = stg, sB = stg + BM * 128;

        #pragma unroll
        for (int k16 = 0; k16 < BK / 16; k16++) {
            uint32_t a[2][4], b[4][4];
            #pragma unroll
            for (int mi = 0; mi < 2; mi++) {
                uint32_t addr = sA + SWZ((uint32_t)((a_row + mi * 16) * 128 + (k16 * 16 + a_kh) * 2));
                LDSM_X4(a[mi][0], a[mi][1], a[mi][2], a[mi][3], addr);
            }
            #pragma unroll
            for (int nq = 0; nq < 4; nq++) {
                uint32_t addr = sB + SWZ((uint32_t)((b_row + nq * 16) * 128 + (k16 * 16 + b_kh) * 2));
                LDSM_X4(b[nq][0], b[nq][1], b[nq][2], b[nq][3], addr);
            }
            #pragma unroll
            for (int mi = 0; mi < 2; mi++)
                #pragma unroll
                for (int nq = 0; nq < 4; nq++) {
                    MMA16816(acc[mi][2*nq],   a[mi][0], a[mi][1], a[mi][2], a[mi][3], b[nq][0], b[nq][1]);
                    MMA16816(acc[mi][2*nq+1], a[mi][0], a[mi][1], a[mi][2], a[mi][3], b[nq][2], b[nq][3]);
                }
        }

        int j = i + STAGES - 1;
        if (j < nchunk) {
            load_stage(sb0 + (j % STAGES) * STAGE_BYTES, A, B, row0, col0, M, K, j * BK, tid);
            CP_COMMIT();
        }
    }

    // ---------------- epilogue ----------------
    const int g = lane >> 2;
    const int cpair = (lane & 3) * 2;
    #pragma unroll
    for (int mi = 0; mi < 2; mi++) {
        #pragma unroll
        for (int half = 0; half < 2; half++) {
            int gm = row0 + wm * 32 + mi * 16 + g + half * 8;
            if (gm >= M) continue;
            float gsel = 0.f;
            if (EPI == 2) gsel = gates[2 * gm];
            if (EPI == 3) gsel = gates[2 * gm + 1];
            if (EPI == 4) gsel = gates[2 * gm] + gates[2 * gm + 1];
            #pragma unroll
            for (int ni = 0; ni < 8; ni++) {
                int gn = col0 + wn * 64 + ni * 8 + cpair;
                float a0 = acc[mi][ni][half * 2 + 0];
                float a1 = acc[mi][ni][half * 2 + 1];
                size_t idx = (size_t)gm * N + gn;
                if (EPI == 1) {
                    *(__half2*)(Ch + idx) = __floats2half2_rn(a0 + bias[gn], a1 + bias[gn + 1]);
                } else if (EPI == 2) {
                    *(__half2*)(Ch + idx) = __floats2half2_rn(
                        gsel * gelu_exact(a0 + bias[gn]), gsel * gelu_exact(a1 + bias[gn + 1]));
                } else if (EPI == 3) {
                    float2 o = __half22float2(*(__half2*)(Ch + idx));
                    *(__half2*)(Ch + idx) = __floats2half2_rn(
                        o.x + gsel * gelu_exact(a0 + bias[gn]),
                        o.y + gsel * gelu_exact(a1 + bias[gn + 1]));
                } else if (EPI == 4) {
                    *(float2*)(Cf + idx) = make_float2(a0 + gsel * bias[gn], a1 + gsel * bias[gn + 1]);
                } else {   // EPI == 5: merged K|V projection
                    float b0, b1;
                    if (gn < MMD) {
                        const __half2 pk = *(const __half2*)(aux + (size_t)(gm % NQS) * MMD + gn);
                        float2 pkf = __half22float2(pk);
                        b0 = pkf.x; b1 = pkf.y;
                    } else {
                        b0 = bias[gn]; b1 = bias[gn + 1];
                    }
                    *(__half2*)(Ch + idx) = __floats2half2_rn(a0 + b0, a1 + b1);
                }
            }
        }
    }
}

// ---------------- fused flash attention (kvproj layout: [row][K|V] stride 2048) ----------------
__global__ void __launch_bounds__(256) flash_attn(
    const __half* __restrict__ q16, const __half* __restrict__ kvproj,
    __half* __restrict__ attn)
{
    extern __shared__ char smem[];
    uint32_t sb = (smem_to_u32(smem) + 1023) & ~1023u;
    uint32_t sQ = sb;
    uint32_t sK = sb + 32 * 1024;
    uint32_t sV = sb + 64 * 1024;
    const int tid = threadIdx.x;
    const int lane = tid & 31, w = tid >> 5;
    const int z = blockIdx.y, b = z >> 3, h = z & 7;
    const __half* Q = q16 + h * DH;
    const __half* K = kvproj + (size_t)b * NQS * KVS + h * DH;
    const __half* V = kvproj + (size_t)b * NQS * KVS + MMD + h * DH;
    __half* O = attn + (size_t)b * NQS * MMD + h * DH;
    const int row0 = blockIdx.x * 128;

    #pragma unroll
    for (int t = 0; t < 8; t++) {
        int op = tid + t * 256;
        int r = op >> 4, c16 = op & 15;
        int gr = row0 + r; if (gr >= NQS) gr = NQS - 1;
        cp16(sQ + r * 256 + (uint32_t)((c16 ^ (r & 7)) << 4), Q + (size_t)gr * MMD + c16 * 8, 16u);
    }
    auto load_kv = [&](int buf, int kt) {
        uint32_t dK = sK + buf * 16384, dV = sV + buf * 16384;
        #pragma unroll
        for (int t = 0; t < 4; t++) {
            int op = tid + t * 256;
            int r = op >> 4, c16 = op & 15;
            cp16(dK + r * 256 + (uint32_t)((c16 ^ (r & 7)) << 4), K + (size_t)(kt + r) * KVS + c16 * 8, 16u);
        }
        #pragma unroll
        for (int t = 0; t < 4; t++) {
            int op = tid + t * 256;
            int r = op >> 4, c16 = op & 15;
            cp16(dV + r * 256 + (uint32_t)((c16 ^ (r & 7)) << 4), V + (size_t)(kt + r) * KVS + c16 * 8, 16u);
        }
    };
    load_kv(0, 0);
    CP_COMMIT();
    load_kv(1, 64);
    CP_COMMIT();

    const int g = lane >> 2, cq = (lane & 3) * 2;
    const int qrow = w * 16 + (lane & 15);
    const int qh   = lane >> 4;
    const int brsel = ((lane >> 4) << 3) + (lane & 7);
    const int bh    = (lane >> 3) & 1;
    const int v_krow = (lane & 7) + ((lane & 16) >> 1);
    const int v_c16h = (lane >> 3) & 1;

    float oacc[16][4];
    #pragma unroll
    for (int i = 0; i < 16; i++)
        #pragma unroll
        for (int q = 0; q < 4; q++) oacc[i][q] = 0.f;
    float m0 = -1e30f, m1 = -1e30f, l0 = 0.f, l1 = 0.f;
    const float scale = 0.08838834764831845f;

    const int NCH = NQS / 64;   // 9
    for (int i = 0; i < NCH; i++) {
        if (i + 1 < NCH) CP_WAIT(1); else CP_WAIT(0);
        __syncthreads();
        const int buf = i & 1;
        uint32_t bK = sK + buf * 16384, bV = sV + buf * 16384;

        float p[8][4];
        #pragma unroll
        for (int ni = 0; ni < 8; ni++)
            #pragma unroll
            for (int q = 0; q < 4; q++) p[ni][q] = 0.f;
        #pragma unroll
        for (int k16 = 0; k16 < 8; k16++) {
            uint32_t a0, a1, a2, a3;
            uint32_t qaddr = sQ + qrow * 256 + (uint32_t)(((2 * k16 + qh) ^ (qrow & 7)) << 4);
            LDSM_X4(a0, a1, a2, a3, qaddr);
            #pragma unroll
            for (int nq = 0; nq < 4; nq++) {
                int br = nq * 16 + brsel;
                uint32_t baddr = bK + br * 256 + (uint32_t)(((2 * k16 + bh) ^ (br & 7)) << 4);
                uint32_t b0, b1, b2, b3;
                LDSM_X4(b0, b1, b2, b3, baddr);
                MMA16816(p[2*nq],   a0, a1, a2, a3, b0, b1);
                MMA16816(p[2*nq+1], a0, a1, a2, a3, b2, b3);
            }
        }
        #pragma unroll
        for (int ni = 0; ni < 8; ni++)
            #pragma unroll
            for (int q = 0; q < 4; q++) p[ni][q] *= scale;

        float t0 = -1e30f, t1 = -1e30f;
        #pragma unroll
        for (int ni = 0; ni < 8; ni++) {
            t0 = fmaxf(t0, fmaxf(p[ni][0], p[ni][1]));
            t1 = fmaxf(t1, fmaxf(p[ni][2], p[ni][3]));
        }
        t0 = fmaxf(t0, __shfl_xor_sync(0xffffffffu, t0, 1));
        t0 = fmaxf(t0, __shfl_xor_sync(0xffffffffu, t0, 2));
        t1 = fmaxf(t1, __shfl_xor_sync(0xffffffffu, t1, 1));
        t1 = fmaxf(t1, __shfl_xor_sync(0xffffffffu, t1, 2));
        float nm0 = fmaxf(m0, t0), nm1 = fmaxf(m1, t1);
        float es0 = expf(m0 - nm0), es1 = expf(m1 - nm1);
        float s0 = 0.f, s1 = 0.f;
        #pragma unroll
        for (int ni = 0; ni < 8; ni++) {
            p[ni][0] = expf(p[ni][0] - nm0);
            p[ni][1] = expf(p[ni][1] - nm0);
            p[ni][2] = expf(p[ni][2] - nm1);
            p[ni][3] = expf(p[ni][3] - nm1);
            s0 += p[ni][0] + p[ni][1];
            s1 += p[ni][2] + p[ni][3];
        }
        s0 += __shfl_xor_sync(0xffffffffu, s0, 1);
        s0 += __shfl_xor_sync(0xffffffffu, s0, 2);
        s1 += __shfl_xor_sync(0xffffffffu, s1, 1);
        s1 += __shfl_xor_sync(0xffffffffu, s1, 2);
        l0 = l0 * es0 + s0;
        l1 = l1 * es1 + s1;
        m0 = nm0; m1 = nm1;
        #pragma unroll
        for (int ni = 0; ni < 16; ni++) {
            oacc[ni][0] *= es0; oacc[ni][1] *= es0;
            oacc[ni][2] *= es1; oacc[ni][3] *= es1;
        }

        #pragma unroll
        for (int kk = 0; kk < 4; kk++) {
            uint32_t a0 = pack_h2(p[2*kk][0],   p[2*kk][1]);
            uint32_t a1 = pack_h2(p[2*kk][2],   p[2*kk][3]);
            uint32_t a2 = pack_h2(p[2*kk+1][0], p[2*kk+1][1]);
            uint32_t a3 = pack_h2(p[2*kk+1][2], p[2*kk+1][3]);
            int vrow = kk * 16 + v_krow;
            #pragma unroll
            for (int ng = 0; ng < 8; ng++) {
                int c16 = ng * 2 + v_c16h;
                uint32_t addr = bV + vrow * 256 + (uint32_t)((c16 ^ (vrow & 7)) << 4);
                uint32_t r0, r1, r2, r3;
                LDSM_X4_T(r0, r1, r2, r3, addr);
                MMA16816(oacc[2*ng],   a0, a1, a2, a3, r0, r2);
                MMA16816(oacc[2*ng+1], a0, a1, a2, a3, r1, r3);
            }
        }

        if (i + 2 < NCH) {
            __syncthreads();
            load_kv(buf, (i + 2) * 64);
            CP_COMMIT();
        }
    }

    float inv0 = 1.0f / l0, inv1 = 1.0f / l1;
    int gm0 = row0 + w * 16 + g;
    int gm1 = gm0 + 8;
    #pragma unroll
    for (int ni = 0; ni < 16; ni++) {
        int gn = ni * 8 + cq;
        if (gm0 < NQS)
            *(__half2*)(O + (size_t)gm0 * MMD + gn) = __floats2half2_rn(oacc[ni][0] * inv0, oacc[ni][1] * inv0);
        if (gm1 < NQS)
            *(__half2*)(O + (size_t)gm1 * MMD + gn) = __floats2half2_rn(oacc[ni][2] * inv1, oacc[ni][3] * inv1);
    }
}

// ---------------- launch ----------------
extern "C" void kernel_launch(void* const* d_in, const int* in_sizes, int n_in,
                              void* d_out, int out_size)
{
    const float* x      = (const float*)d_in[0];
    const float* noise  = (const float*)d_in[1];
    const float* W1     = (const float*)d_in[2];
    const float* b1     = (const float*)d_in[3];
    const float* W2     = (const float*)d_in[4];
    const float* b2     = (const float*)d_in[5];
    const float* query  = (const float*)d_in[6];
    const float* pos    = (const float*)d_in[7];
    const float* ln_q_g = (const float*)d_in[8];
    const float* ln_q_b = (const float*)d_in[9];
    const float* ln_kv_g= (const float*)d_in[10];
    const float* ln_kv_b= (const float*)d_in[11];
    const float* ipw    = (const float*)d_in[12];
    const float* ipb    = (const float*)d_in[13];
    const float* ow     = (const float*)d_in[14];
    const float* ob     = (const float*)d_in[15];
    const float* wg     = (const float*)d_in[16];
    const float* wn     = (const float*)d_in[17];
    float* out = (float*)d_out;

    float *gates;
    __half *q16, *kvproj, *pos16, *posk;
    __half *x16, *kv16, *qn16, *attn16, *e1in16, *h16, *ipw16, *ow16, *w116, *w216;
    cudaGetSymbolAddress((void**)&q16,    g_qp);
    cudaGetSymbolAddress((void**)&kvproj, g_kp);
    cudaGetSymbolAddress((void**)&pos16,  g_vp);
    posk = pos16 + NQS * MMD;
    cudaGetSymbolAddress((void**)&gates,  g_gates);
    cudaGetSymbolAddress((void**)&x16,    g_x16);
    cudaGetSymbolAddress((void**)&kv16,   g_kv16);
    cudaGetSymbolAddress((void**)&qn16,   g_qn16);
    cudaGetSymbolAddress((void**)&attn16, g_attn16);
    cudaGetSymbolAddress((void**)&e1in16, g_e1in16);
    cudaGetSymbolAddress((void**)&h16,    g_h16);
    cudaGetSymbolAddress((void**)&ipw16,  g_ipw16);
    cudaGetSymbolAddress((void**)&ow16,   g_ow16);
    cudaGetSymbolAddress((void**)&w116,   g_w116);
    cudaGetSymbolAddress((void**)&w216,   g_w216);

    static cudaStream_t s1 = nullptr;
    static cudaEvent_t evFork0 = nullptr, evGates = nullptr, evJoin = nullptr;
    static bool attr_done = false;
    if (!attr_done) {
        cudaFuncSetAttribute(hgemm<1>, cudaFuncAttributeMaxDynamicSharedMemorySize, SMEM_DYN);
        cudaFuncSetAttribute(hgemm<2>, cudaFuncAttributeMaxDynamicSharedMemorySize, SMEM_DYN);
        cudaFuncSetAttribute(hgemm<3>, cudaFuncAttributeMaxDynamicSharedMemorySize, SMEM_DYN);
        cudaFuncSetAttribute(hgemm<4>, cudaFuncAttributeMaxDynamicSharedMemorySize, SMEM_DYN);
        cudaFuncSetAttribute(hgemm<5>, cudaFuncAttributeMaxDynamicSharedMemorySize, SMEM_DYN);
        cudaFuncSetAttribute(flash_attn, cudaFuncAttributeMaxDynamicSharedMemorySize, FA_SMEM);
        cudaStreamCreateWithFlags(&s1, cudaStreamNonBlocking);
        cudaEventCreateWithFlags(&evFork0, cudaEventDisableTiming);
        cudaEventCreateWithFlags(&evGates, cudaEventDisableTiming);
        cudaEventCreateWithFlags(&evJoin, cudaEventDisableTiming);
        attr_done = true;
    }

    // fork side stream immediately: W1/W2 conversion has no dependencies
    cudaEventRecord(evFork0, 0);
    cudaStreamWaitEvent(s1, evFork0, 0);
    f2h_b_kernel<<<(N4_B + 255)/256, 256, 0, s1>>>(W1, w116, W2, w216);

    // main: fused LN(x)+gating (+x16 emission)
    lnxg_kernel<<<ROWS, 256>>>(x, ln_kv_g, ln_kv_b, wg, wn, noise, kv16, x16, gates);
    cudaEventRecord(evGates, 0);

    // side: expert-0 FC1 (needs x16 + gates from lnxg, W1 from f2h_b)
    cudaStreamWaitEvent(s1, evGates, 0);
    hgemm<2><<<dim3(32, 72), 256, SMEM_DYN, s1>>>(x16, w116, nullptr, h16, ROWS, HIDD, MMD, b1, gates, nullptr);
    cudaEventRecord(evJoin, s1);

    // main: attention chain
    lnq_kernel<<<NQS, 256>>>(query, ln_q_g, ln_q_b, pos, qn16);
    f2h_a_kernel<<<(N4_A + 255)/256, 256>>>(ipw, ipw16, ow, ow16, pos, pos16);

    // Q projection + posk = pos @ Wk^T + bk (both small)
    hgemm<1><<<dim3(8, 5), 256, SMEM_DYN>>>(qn16,  ipw16,           nullptr, q16,  NQS, MMD, MMD, ipb,       nullptr, nullptr);
    hgemm<1><<<dim3(8, 5), 256, SMEM_DYN>>>(pos16, ipw16 + MMD*MMD, nullptr, posk, NQS, MMD, MMD, ipb + MMD, nullptr, nullptr);

    // merged K|V projection: kv16 @ [Wk;Wv]^T -> kvproj (9216 x 2048)
    hgemm<5><<<dim3(16, 72), 256, SMEM_DYN>>>(kv16, ipw16 + MMD*MMD, nullptr, kvproj, ROWS, KVS, MMD, ipb + MMD, nullptr, posk);

    flash_attn<<<dim3(5, NBH), 256, FA_SMEM>>>(q16, kvproj, attn16);

    hgemm<1><<<dim3(8, 72), 256, SMEM_DYN>>>(attn16, ow16, nullptr, e1in16, ROWS, MMD, MMD, ob, nullptr, nullptr);

    // join: FC1(e1) RMWs h16 written by side-stream FC1(x); FC2 needs w216 from side
    cudaStreamWaitEvent(0, evJoin, 0);
    hgemm<3><<<dim3(32, 72), 256, SMEM_DYN>>>(e1in16, w116, nullptr, h16, ROWS, HIDD, MMD, b1, gates, nullptr);
    hgemm<4><<<dim3(32, 72), 256, SMEM_DYN>>>(h16,    w216, out, nullptr, ROWS, HIDD, HIDD, b2, gates, nullptr);
}

// round 12
// speedup vs baseline: 1.0117x; 1.0117x over previous
#include <cuda_runtime.h>
#include <cuda_fp16.h>
#include <math.h>
#include <cstdint>

// ---------------- problem constants ----------------
#define NQS   576
#define BATCH 16
#define MMD   1024
#define HIDD  4096
#define ROWS  (BATCH*NQS)        // 9216
#define HEADS 8
#define DH    128
#define NBH   (BATCH*HEADS)      // 128

// ---------------- HMMA GEMM tiling (R6 proven: 128x128, 256 thr, 2 CTA/SM) ----------------
#define BM 128
#define BN 128
#define BK 64
#define STAGES 3
#define STAGE_BYTES ((BM+BN)*128)                    // 32 KB
#define SMEM_DYN (STAGES*STAGE_BYTES + 2048)
#define FA_SMEM (96*1024 + 1024)

// ---------------- scratch (device globals) ----------------
__device__ __align__(16) float  g_qp [NQS*MMD];              // fp16 q
__device__ __align__(16) float  g_kp [ROWS*MMD];             // fp16 k
__device__ __align__(16) float  g_vp [ROWS*MMD];             // fp16 v
__device__ __align__(16) float  g_gates[ROWS*2];
__device__ __align__(16) __half g_x16   [ROWS*MMD];
__device__ __align__(16) __half g_kv16  [ROWS*MMD];
__device__ __align__(16) __half g_kvp16 [ROWS*MMD];
__device__ __align__(16) __half g_qn16  [NQS*MMD];
__device__ __align__(16) __half g_attn16[ROWS*MMD];
__device__ __align__(16) __half g_e1in16[ROWS*MMD];
__device__ __align__(16) __half g_h16   [(size_t)ROWS*HIDD];
__device__ __align__(16) __half g_ipw16 [3*MMD*MMD];
__device__ __align__(16) __half g_ow16  [MMD*MMD];
__device__ __align__(16) __half g_w116  [HIDD*MMD];
__device__ __align__(16) __half g_w216  [(size_t)HIDD*HIDD];

// ---------------- helpers ----------------
__device__ __forceinline__ uint32_t smem_to_u32(const void* p) {
    uint32_t a;
    asm("{ .reg .u64 t; cvta.to.shared.u64 t, %1; cvt.u32.u64 %0, t; }" : "=r"(a) : "l"(p));
    return a;
}
#define SWZ(o) ((o) ^ (((o) >> 3) & 0x70))

__device__ __forceinline__ void cp16(uint32_t dst, const void* src, uint32_t sz) {
    asm volatile("cp.async.cg.shared.global [%0], [%1], 16, %2;\n" :: "r"(dst), "l"(src), "r"(sz));
}
#define CP_COMMIT() asm volatile("cp.async.commit_group;\n")
#define CP_WAIT(n)  asm volatile("cp.async.wait_group %0;\n" :: "n"(n))

#define LDSM_X4(r0,r1,r2,r3,addr) \
    asm volatile("ldmatrix.sync.aligned.m8n8.x4.shared.b16 {%0,%1,%2,%3}, [%4];" \
        : "=r"(r0), "=r"(r1), "=r"(r2), "=r"(r3) : "r"(addr))
#define LDSM_X4_T(r0,r1,r2,r3,addr) \
    asm volatile("ldmatrix.sync.aligned.m8n8.x4.trans.shared.b16 {%0,%1,%2,%3}, [%4];" \
        : "=r"(r0), "=r"(r1), "=r"(r2), "=r"(r3) : "r"(addr))

#define MMA16816(c, a0,a1,a2,a3, b0,b1) \
    asm volatile("mma.sync.aligned.m16n8k16.row.col.f32.f16.f16.f32 " \
        "{%0,%1,%2,%3},{%4,%5,%6,%7},{%8,%9},{%0,%1,%2,%3};" \
        : "+f"((c)[0]), "+f"((c)[1]), "+f"((c)[2]), "+f"((c)[3]) \
        : "r"(a0), "r"(a1), "r"(a2), "r"(a3), "r"(b0), "r"(b1))

__device__ __forceinline__ float gelu_exact(float v) {
    return 0.5f * v * (1.0f + erff(v * 0.7071067811865476f));
}
__device__ __forceinline__ float softplusf_(float x) {
    return fmaxf(x, 0.0f) + log1pf(expf(-fabsf(x)));
}
__device__ __forceinline__ uint32_t pack_h2(float a, float b) {
    __half2 h = __floats2half2_rn(a, b);
    return *(uint32_t*)&h;
}

// ---------------- split fp32 -> fp16 conversions ----------------
#define N4_IPW (3*MMD*MMD/4)
#define N4_OW  (MMD*MMD/4)
#define N4_W1  (HIDD*MMD/4)
#define N4_W2  (HIDD*HIDD/4)
#define N4_A   (N4_IPW+N4_OW)
#define N4_B   (N4_W1+N4_W2)

// main-stream: ipw + ow (needed by QKV / outproj)
__global__ void __launch_bounds__(256) f2h_a_kernel(
    const float* __restrict__ ipw, __half* __restrict__ ipw16,
    const float* __restrict__ ow,  __half* __restrict__ ow16)
{
    int i = blockIdx.x * blockDim.x + threadIdx.x;
    if (i >= N4_A) return;
    const float* src; __half* dst;
    if (i < N4_IPW) { src = ipw; dst = ipw16; }
    else { i -= N4_IPW; src = ow; dst = ow16; }
    float4 v = ((const float4*)src)[i];
    uint2 p;
    *((__half2*)&p.x) = __floats2half2_rn(v.x, v.y);
    *((__half2*)&p.y) = __floats2half2_rn(v.z, v.w);
    ((uint2*)dst)[i] = p;
}

// side-stream: W1 + W2 (no dependencies; forked at t=0)
__global__ void __launch_bounds__(256) f2h_b_kernel(
    const float* __restrict__ W1, __half* __restrict__ w116,
    const float* __restrict__ W2, __half* __restrict__ w216)
{
    int i = blockIdx.x * blockDim.x + threadIdx.x;
    if (i >= N4_B) return;
    const float* src; __half* dst;
    if (i < N4_W1) { src = W1; dst = w116; }
    else { i -= N4_W1; src = W2; dst = w216; }
    float4 v = ((const float4*)src)[i];
    uint2 p;
    *((__half2*)&p.x) = __floats2half2_rn(v.x, v.y);
    *((__half2*)&p.y) = __floats2half2_rn(v.z, v.w);
    ((uint2*)dst)[i] = p;
}

// ---------------- fused LN(x) + gating + x16 emission: one read of x ----------------
__global__ void __launch_bounds__(256) lnxg_kernel(
    const float* __restrict__ x, const float* __restrict__ g,
    const float* __restrict__ b, const float* __restrict__ pos,
    const float* __restrict__ wg, const float* __restrict__ wn,
    const float* __restrict__ noise,
    __half* __restrict__ kv16, __half* __restrict__ kvp16,
    __half* __restrict__ x16, float* __restrict__ gates)
{
    const int row = blockIdx.x;
    const int prow = row % NQS;
    const int t = threadIdx.x;

    const float4 xv = *(const float4*)(x + (size_t)row * MMD + t * 4);
    float s  = xv.x + xv.y + xv.z + xv.w;
    float ss = xv.x*xv.x + xv.y*xv.y + xv.z*xv.z + xv.w*xv.w;

    float4 wg0 = *(const float4*)(wg + 8*t);
    float4 wg1 = *(const float4*)(wg + 8*t + 4);
    float4 wn0 = *(const float4*)(wn + 8*t);
    float4 wn1 = *(const float4*)(wn + 8*t + 4);
    float d0 = xv.x*wg0.x + xv.y*wg0.z + xv.z*wg1.x + xv.w*wg1.z;
    float d1 = xv.x*wg0.y + xv.y*wg0.w + xv.z*wg1.y + xv.w*wg1.w;
    float d2 = xv.x*wn0.x + xv.y*wn0.z + xv.z*wn1.x + xv.w*wn1.z;
    float d3 = xv.x*wn0.y + xv.y*wn0.w + xv.z*wn1.y + xv.w*wn1.w;

    // emit x16 (free: x already in registers)
    uint2 ox;
    ox.x = pack_h2(xv.x, xv.y); ox.y = pack_h2(xv.z, xv.w);
    *(uint2*)(x16 + (size_t)row * MMD + t * 4) = ox;

    __shared__ float red[6][8];
    float vals[6] = {s, ss, d0, d1, d2, d3};
    #pragma unroll
    for (int j = 0; j < 6; j++)
        #pragma unroll
        for (int o = 16; o; o >>= 1)
            vals[j] += __shfl_xor_sync(0xffffffffu, vals[j], o);
    int wid = t >> 5, lid = t & 31;
    if (lid == 0)
        #pragma unroll
        for (int j = 0; j < 6; j++) red[j][wid] = vals[j];
    __syncthreads();

    float S = 0.f, SS = 0.f;
    #pragma unroll
    for (int w = 0; w < 8; w++) { S += red[0][w]; SS += red[1][w]; }
    float mu = S / MMD;
    float rstd = rsqrtf(SS / MMD - mu * mu + 1e-5f);

    float4 gv = *(const float4*)(g + t * 4);
    float4 bv = *(const float4*)(b + t * 4);
    float4 pv = *(const float4*)(pos + (size_t)prow * MMD + t * 4);
    float v0 = (xv.x - mu) * rstd * gv.x + bv.x;
    float v1 = (xv.y - mu) * rstd * gv.y + bv.y;
    float v2 = (xv.z - mu) * rstd * gv.z + bv.z;
    float v3 = (xv.w - mu) * rstd * gv.w + bv.w;
    uint2 o1, o2;
    o1.x = pack_h2(v0, v1); o1.y = pack_h2(v2, v3);
    o2.x = pack_h2(v0 + pv.x, v1 + pv.y); o2.y = pack_h2(v2 + pv.z, v3 + pv.w);
    *(uint2*)(kv16  + (size_t)row * MMD + t * 4) = o1;
    *(uint2*)(kvp16 + (size_t)row * MMD + t * 4) = o2;

    if (t == 0) {
        float td[4] = {0.f, 0.f, 0.f, 0.f};
        #pragma unroll
        for (int w = 0; w < 8; w++)
            #pragma unroll
            for (int j = 0; j < 4; j++) td[j] += red[2 + j][w];
        float sp0 = softplusf_(td[2]) + 0.01f;
        float sp1 = softplusf_(td[3]) + 0.01f;
        float l0 = td[0] + noise[2*row]   * sp0;
        float l1 = td[1] + noise[2*row+1] * sp1;
        float mx = fmaxf(l0, l1);
        float e0 = expf(l0 - mx), e1 = expf(l1 - mx);
        float is = 1.0f / (e0 + e1);
        float p0 = e0 * is, p1 = e1 * is;
        float inv = 1.0f / (p0 + p1 + 1e-6f);
        gates[2*row]   = p0 * inv;
        gates[2*row+1] = p1 * inv;
    }
}

// ---------------- LN(query) + pos -> fp16, vectorized ----------------
__global__ void __launch_bounds__(256) lnq_kernel(
    const float* __restrict__ q, const float* __restrict__ g,
    const float* __restrict__ b, const float* __restrict__ pos,
    __half* __restrict__ qn16)
{
    const int row = blockIdx.x;
    const int t = threadIdx.x;
    const float4 xv = *(const float4*)(q + (size_t)row * MMD + t * 4);
    float s  = xv.x + xv.y + xv.z + xv.w;
    float ss = xv.x*xv.x + xv.y*xv.y + xv.z*xv.z + xv.w*xv.w;
    __shared__ float red[2][8];
    #pragma unroll
    for (int o = 16; o; o >>= 1) {
        s  += __shfl_xor_sync(0xffffffffu, s,  o);
        ss += __shfl_xor_sync(0xffffffffu, ss, o);
    }
    int wid = t >> 5, lid = t & 31;
    if (lid == 0) { red[0][wid] = s; red[1][wid] = ss; }
    __syncthreads();
    float S = 0.f, SS = 0.f;
    #pragma unroll
    for (int w = 0; w < 8; w++) { S += red[0][w]; SS += red[1][w]; }
    float mu = S / MMD;
    float rstd = rsqrtf(SS / MMD - mu * mu + 1e-5f);
    float4 gv = *(const float4*)(g + t * 4);
    float4 bv = *(const float4*)(b + t * 4);
    float4 pv = *(const float4*)(pos + (size_t)row * MMD + t * 4);
    uint2 o;
    o.x = pack_h2((xv.x - mu) * rstd * gv.x + bv.x + pv.x,
                  (xv.y - mu) * rstd * gv.y + bv.y + pv.y);
    o.y = pack_h2((xv.z - mu) * rstd * gv.z + bv.z + pv.z,
                  (xv.w - mu) * rstd * gv.w + bv.w + pv.w);
    *(uint2*)(qn16 + (size_t)row * MMD + t * 4) = o;
}

// ---------------- fp16 HMMA GEMM 128x128 (256 thr): C = A @ B^T ----------------
// EPI: 1 = fp16 +bias store, 2 = fp16 = g0*gelu(v+bias), 3 = fp16 += g1*gelu(v+bias),
//      4 = fp32 = acc + (g0+g1)*bias
__device__ __forceinline__ void load_stage(
    uint32_t stg, const __half* __restrict__ A, const __half* __restrict__ B,
    int row0, int col0, int M, int K, int kt, int tid)
{
    uint32_t sA = stg;
    uint32_t sB = stg + BM * 128;
    #pragma unroll
    for (int t = 0; t < 4; t++) {
        int op = tid + t * 256;
        int row = op >> 3, c = op & 7;
        int gr = row0 + row;
        uint32_t sz = (gr < M) ? 16u : 0u;
        if (gr >= M) gr = M - 1;
        cp16(sA + SWZ(row * 128 + c * 16), A + (size_t)gr * K + kt + c * 8, sz);
    }
    #pragma unroll
    for (int t = 0; t < 4; t++) {
        int op = tid + t * 256;
        int row = op >> 3, c = op & 7;
        cp16(sB + SWZ(row * 128 + c * 16), B + (size_t)(col0 + row) * K + kt + c * 8, 16u);
    }
}

template<int EPI>
__global__ void __launch_bounds__(256) hgemm(
    const __half* __restrict__ A, const __half* __restrict__ B,
    float* __restrict__ Cf, __half* __restrict__ Ch,
    int M, int N, int K,
    const float* __restrict__ bias, const float* __restrict__ gates)
{
    extern __shared__ char smem[];
    uint32_t sb0 = (smem_to_u32(smem) + 1023) & ~1023u;
    const int tid = threadIdx.x;
    const int lane = tid & 31, warp = tid >> 5;
    const int wm = warp >> 1, wn = warp & 1;
    const int row0 = blockIdx.y * BM, col0 = blockIdx.x * BN;

    const int a_row = wm * 32 + (lane & 15);
    const int a_kh  = (lane >> 4) << 3;
    const int b_row = wn * 64 + ((lane >> 4) << 3) + (lane & 7);
    const int b_kh  = ((lane >> 3) & 1) << 3;

    float acc[2][8][4];
    #pragma unroll
    for (int mi = 0; mi < 2; mi++)
        #pragma unroll
        for (int ni = 0; ni < 8; ni++)
            #pragma unroll
            for (int q = 0; q < 4; q++) acc[mi][ni][q] = 0.f;

    const int nchunk = K / BK;

    #pragma unroll
    for (int j = 0; j < STAGES - 1; j++) {
        load_stage(sb0 + j * STAGE_BYTES, A, B, row0, col0, M, K, j * BK, tid);
        CP_COMMIT();
    }

    for (int i = 0; i < nchunk; i++) {
        if (i + 1 == nchunk) CP_WAIT(0); else CP_WAIT(STAGES - 2);
        __syncthreads();

        uint32_t stg = sb0 + (i % STAGES) * STAGE_BYTES;
        uint32_t sA = stg, sB = stg + BM * 128;

        #pragma unroll
        for (int k16 = 0; k16 < BK / 16; k16++) {
            uint32_t a[2][4], b[4][4];
            #pragma unroll
            for (int mi = 0; mi < 2; mi++) {
                uint32_t addr = sA + SWZ((uint32_t)((a_row + mi * 16) * 128 + (k16 * 16 + a_kh) * 2));
                LDSM_X4(a[mi][0], a[mi][1], a[mi][2], a[mi][3], addr);
            }
            #pragma unroll
            for (int nq = 0; nq < 4; nq++) {
                uint32_t addr = sB + SWZ((uint32_t)((b_row + nq * 16) * 128 + (k16 * 16 + b_kh) * 2));
                LDSM_X4(b[nq][0], b[nq][1], b[nq][2], b[nq][3], addr);
            }
            #pragma unroll
            for (int mi = 0; mi < 2; mi++)
                #pragma unroll
                for (int nq = 0; nq < 4; nq++) {
                    MMA16816(acc[mi][2*nq],   a[mi][0], a[mi][1], a[mi][2], a[mi][3], b[nq][0], b[nq][1]);
                    MMA16816(acc[mi][2*nq+1], a[mi][0], a[mi][1], a[mi][2], a[mi][3], b[nq][2], b[nq][3]);
                }
        }

        int j = i + STAGES - 1;
        if (j < nchunk) {
            load_stage(sb0 + (j % STAGES) * STAGE_BYTES, A, B, row0, col0, M, K, j * BK, tid);
            CP_COMMIT();
        }
    }

    // ---------------- epilogue ----------------
    const int g = lane >> 2;
    const int cpair = (lane & 3) * 2;
    #pragma unroll
    for (int mi = 0; mi < 2; mi++) {
        #pragma unroll
        for (int half = 0; half < 2; half++) {
            int gm = row0 + wm * 32 + mi * 16 + g + half * 8;
            if (gm >= M) continue;
            float gsel = 0.f;
            if (EPI == 2) gsel = gates[2 * gm];
            if (EPI == 3) gsel = gates[2 * gm + 1];
            if (EPI == 4) gsel = gates[2 * gm] + gates[2 * gm + 1];
            #pragma unroll
            for (int ni = 0; ni < 8; ni++) {
                int gn = col0 + wn * 64 + ni * 8 + cpair;
                float a0 = acc[mi][ni][half * 2 + 0];
                float a1 = acc[mi][ni][half * 2 + 1];
                size_t idx = (size_t)gm * N + gn;
                if (EPI == 1) {
                    *(__half2*)(Ch + idx) = __floats2half2_rn(a0 + bias[gn], a1 + bias[gn + 1]);
                } else if (EPI == 2) {
                    *(__half2*)(Ch + idx) = __floats2half2_rn(
                        gsel * gelu_exact(a0 + bias[gn]), gsel * gelu_exact(a1 + bias[gn + 1]));
                } else if (EPI == 3) {
                    float2 o = __half22float2(*(__half2*)(Ch + idx));
                    *(__half2*)(Ch + idx) = __floats2half2_rn(
                        o.x + gsel * gelu_exact(a0 + bias[gn]),
                        o.y + gsel * gelu_exact(a1 + bias[gn + 1]));
                } else {
                    *(float2*)(Cf + idx) = make_float2(a0 + gsel * bias[gn], a1 + gsel * bias[gn + 1]);
                }
            }
        }
    }
}

// ---------------- fused flash attention (R6/R10 layout: separate k16/v16, stride 1024) ----------------
__global__ void __launch_bounds__(256) flash_attn(
    const __half* __restrict__ q16, const __half* __restrict__ k16,
    const __half* __restrict__ v16, __half* __restrict__ attn)
{
    extern __shared__ char smem[];
    uint32_t sb = (smem_to_u32(smem) + 1023) & ~1023u;
    uint32_t sQ = sb;
    uint32_t sK = sb + 32 * 1024;
    uint32_t sV = sb + 64 * 1024;
    const int tid = threadIdx.x;
    const int lane = tid & 31, w = tid >> 5;
    const int z = blockIdx.y, b = z >> 3, h = z & 7;
    const __half* Q = q16 + h * DH;
    const __half* K = k16 + (size_t)b * NQS * MMD + h * DH;
    const __half* V = v16 + (size_t)b * NQS * MMD + h * DH;
    __half* O = attn + (size_t)b * NQS * MMD + h * DH;
    const int row0 = blockIdx.x * 128;

    #pragma unroll
    for (int t = 0; t < 8; t++) {
        int op = tid + t * 256;
        int r = op >> 4, c16 = op & 15;
        int gr = row0 + r; if (gr >= NQS) gr = NQS - 1;
        cp16(sQ + r * 256 + (uint32_t)((c16 ^ (r & 7)) << 4), Q + (size_t)gr * MMD + c16 * 8, 16u);
    }
    auto load_kv = [&](int buf, int kt) {
        uint32_t dK = sK + buf * 16384, dV = sV + buf * 16384;
        #pragma unroll
        for (int t = 0; t < 4; t++) {
            int op = tid + t * 256;
            int r = op >> 4, c16 = op & 15;
            cp16(dK + r * 256 + (uint32_t)((c16 ^ (r & 7)) << 4), K + (size_t)(kt + r) * MMD + c16 * 8, 16u);
        }
        #pragma unroll
        for (int t = 0; t < 4; t++) {
            int op = tid + t * 256;
            int r = op >> 4, c16 = op & 15;
            cp16(dV + r * 256 + (uint32_t)((c16 ^ (r & 7)) << 4), V + (size_t)(kt + r) * MMD + c16 * 8, 16u);
        }
    };
    load_kv(0, 0);
    CP_COMMIT();
    load_kv(1, 64);
    CP_COMMIT();

    const int g = lane >> 2, cq = (lane & 3) * 2;
    const int qrow = w * 16 + (lane & 15);
    const int qh   = lane >> 4;
    const int brsel = ((lane >> 4) << 3) + (lane & 7);
    const int bh    = (lane >> 3) & 1;
    const int v_krow = (lane & 7) + ((lane & 16) >> 1);
    const int v_c16h = (lane >> 3) & 1;

    float oacc[16][4];
    #pragma unroll
    for (int i = 0; i < 16; i++)
        #pragma unroll
        for (int q = 0; q < 4; q++) oacc[i][q] = 0.f;
    float m0 = -1e30f, m1 = -1e30f, l0 = 0.f, l1 = 0.f;
    const float scale = 0.08838834764831845f;

    const int NCH = NQS / 64;   // 9
    for (int i = 0; i < NCH; i++) {
        if (i + 1 < NCH) CP_WAIT(1); else CP_WAIT(0);
        __syncthreads();
        const int buf = i & 1;
        uint32_t bK = sK + buf * 16384, bV = sV + buf * 16384;

        float p[8][4];
        #pragma unroll
        for (int ni = 0; ni < 8; ni++)
            #pragma unroll
            for (int q = 0; q < 4; q++) p[ni][q] = 0.f;
        #pragma unroll
        for (int k16i = 0; k16i < 8; k16i++) {
            uint32_t a0, a1, a2, a3;
            uint32_t qaddr = sQ + qrow * 256 + (uint32_t)(((2 * k16i + qh) ^ (qrow & 7)) << 4);
            LDSM_X4(a0, a1, a2, a3, qaddr);
            #pragma unroll
            for (int nq = 0; nq < 4; nq++) {
                int br = nq * 16 + brsel;
                uint32_t baddr = bK + br * 256 + (uint32_t)(((2 * k16i + bh) ^ (br & 7)) << 4);
                uint32_t b0, b1, b2, b3;
                LDSM_X4(b0, b1, b2, b3, baddr);
                MMA16816(p[2*nq],   a0, a1, a2, a3, b0, b1);
                MMA16816(p[2*nq+1], a0, a1, a2, a3, b2, b3);
            }
        }
        #pragma unroll
        for (int ni = 0; ni < 8; ni++)
            #pragma unroll
            for (int q = 0; q < 4; q++) p[ni][q] *= scale;

        float t0 = -1e30f, t1 = -1e30f;
        #pragma unroll
        for (int ni = 0; ni < 8; ni++) {
            t0 = fmaxf(t0, fmaxf(p[ni][0], p[ni][1]));
            t1 = fmaxf(t1, fmaxf(p[ni][2], p[ni][3]));
        }
        t0 = fmaxf(t0, __shfl_xor_sync(0xffffffffu, t0, 1));
        t0 = fmaxf(t0, __shfl_xor_sync(0xffffffffu, t0, 2));
        t1 = fmaxf(t1, __shfl_xor_sync(0xffffffffu, t1, 1));
        t1 = fmaxf(t1, __shfl_xor_sync(0xffffffffu, t1, 2));
        float nm0 = fmaxf(m0, t0), nm1 = fmaxf(m1, t1);
        float es0 = expf(m0 - nm0), es1 = expf(m1 - nm1);
        float s0 = 0.f, s1 = 0.f;
        #pragma unroll
        for (int ni = 0; ni < 8; ni++) {
            p[ni][0] = expf(p[ni][0] - nm0);
            p[ni][1] = expf(p[ni][1] - nm0);
            p[ni][2] = expf(p[ni][2] - nm1);
            p[ni][3] = expf(p[ni][3] - nm1);
            s0 += p[ni][0] + p[ni][1];
            s1 += p[ni][2] + p[ni][3];
        }
        s0 += __shfl_xor_sync(0xffffffffu, s0, 1);
        s0 += __shfl_xor_sync(0xffffffffu, s0, 2);
        s1 += __shfl_xor_sync(0xffffffffu, s1, 1);
        s1 += __shfl_xor_sync(0xffffffffu, s1, 2);
        l0 = l0 * es0 + s0;
        l1 = l1 * es1 + s1;
        m0 = nm0; m1 = nm1;
        #pragma unroll
        for (int ni = 0; ni < 16; ni++) {
            oacc[ni][0] *= es0; oacc[ni][1] *= es0;
            oacc[ni][2] *= es1; oacc[ni][3] *= es1;
        }

        #pragma unroll
        for (int kk = 0; kk < 4; kk++) {
            uint32_t a0 = pack_h2(p[2*kk][0],   p[2*kk][1]);
            uint32_t a1 = pack_h2(p[2*kk][2],   p[2*kk][3]);
            uint32_t a2 = pack_h2(p[2*kk+1][0], p[2*kk+1][1]);
            uint32_t a3 = pack_h2(p[2*kk+1][2], p[2*kk+1][3]);
            int vrow = kk * 16 + v_krow;
            #pragma unroll
            for (int ng = 0; ng < 8; ng++) {
                int c16 = ng * 2 + v_c16h;
                uint32_t addr = bV + vrow * 256 + (uint32_t)((c16 ^ (vrow & 7)) << 4);
                uint32_t r0, r1, r2, r3;
                LDSM_X4_T(r0, r1, r2, r3, addr);
                MMA16816(oacc[2*ng],   a0, a1, a2, a3, r0, r2);
                MMA16816(oacc[2*ng+1], a0, a1, a2, a3, r1, r3);
            }
        }

        if (i + 2 < NCH) {
            __syncthreads();
            load_kv(buf, (i + 2) * 64);
            CP_COMMIT();
        }
    }

    float inv0 = 1.0f / l0, inv1 = 1.0f / l1;
    int gm0 = row0 + w * 16 + g;
    int gm1 = gm0 + 8;
    #pragma unroll
    for (int ni = 0; ni < 16; ni++) {
        int gn = ni * 8 + cq;
        if (gm0 < NQS)
            *(__half2*)(O + (size_t)gm0 * MMD + gn) = __floats2half2_rn(oacc[ni][0] * inv0, oacc[ni][1] * inv0);
        if (gm1 < NQS)
            *(__half2*)(O + (size_t)gm1 * MMD + gn) = __floats2half2_rn(oacc[ni][2] * inv1, oacc[ni][3] * inv1);
    }
}

// ---------------- launch ----------------
extern "C" void kernel_launch(void* const* d_in, const int* in_sizes, int n_in,
                              void* d_out, int out_size)
{
    const float* x      = (const float*)d_in[0];
    const float* noise  = (const float*)d_in[1];
    const float* W1     = (const float*)d_in[2];
    const float* b1     = (const float*)d_in[3];
    const float* W2     = (const float*)d_in[4];
    const float* b2     = (const float*)d_in[5];
    const float* query  = (const float*)d_in[6];
    const float* pos    = (const float*)d_in[7];
    const float* ln_q_g = (const float*)d_in[8];
    const float* ln_q_b = (const float*)d_in[9];
    const float* ln_kv_g= (const float*)d_in[10];
    const float* ln_kv_b= (const float*)d_in[11];
    const float* ipw    = (const float*)d_in[12];
    const float* ipb    = (const float*)d_in[13];
    const float* ow     = (const float*)d_in[14];
    const float* ob     = (const float*)d_in[15];
    const float* wg     = (const float*)d_in[16];
    const float* wn     = (const float*)d_in[17];
    float* out = (float*)d_out;

    float *gates;
    __half *q16, *k16, *v16;
    __half *x16, *kv16, *kvp16, *qn16, *attn16, *e1in16, *h16, *ipw16, *ow16, *w116, *w216;
    cudaGetSymbolAddress((void**)&q16,    g_qp);
    cudaGetSymbolAddress((void**)&k16,    g_kp);
    cudaGetSymbolAddress((void**)&v16,    g_vp);
    cudaGetSymbolAddress((void**)&gates,  g_gates);
    cudaGetSymbolAddress((void**)&x16,    g_x16);
    cudaGetSymbolAddress((void**)&kv16,   g_kv16);
    cudaGetSymbolAddress((void**)&kvp16,  g_kvp16);
    cudaGetSymbolAddress((void**)&qn16,   g_qn16);
    cudaGetSymbolAddress((void**)&attn16, g_attn16);
    cudaGetSymbolAddress((void**)&e1in16, g_e1in16);
    cudaGetSymbolAddress((void**)&h16,    g_h16);
    cudaGetSymbolAddress((void**)&ipw16,  g_ipw16);
    cudaGetSymbolAddress((void**)&ow16,   g_ow16);
    cudaGetSymbolAddress((void**)&w116,   g_w116);
    cudaGetSymbolAddress((void**)&w216,   g_w216);

    static cudaStream_t s1 = nullptr;
    static cudaEvent_t evFork0 = nullptr, evGates = nullptr, evJoin = nullptr;
    static bool attr_done = false;
    if (!attr_done) {
        cudaFuncSetAttribute(hgemm<1>, cudaFuncAttributeMaxDynamicSharedMemorySize, SMEM_DYN);
        cudaFuncSetAttribute(hgemm<2>, cudaFuncAttributeMaxDynamicSharedMemorySize, SMEM_DYN);
        cudaFuncSetAttribute(hgemm<3>, cudaFuncAttributeMaxDynamicSharedMemorySize, SMEM_DYN);
        cudaFuncSetAttribute(hgemm<4>, cudaFuncAttributeMaxDynamicSharedMemorySize, SMEM_DYN);
        cudaFuncSetAttribute(flash_attn, cudaFuncAttributeMaxDynamicSharedMemorySize, FA_SMEM);
        cudaStreamCreateWithFlags(&s1, cudaStreamNonBlocking);
        cudaEventCreateWithFlags(&evFork0, cudaEventDisableTiming);
        cudaEventCreateWithFlags(&evGates, cudaEventDisableTiming);
        cudaEventCreateWithFlags(&evJoin, cudaEventDisableTiming);
        attr_done = true;
    }

    // fork side stream immediately: W1/W2 conversion has no dependencies
    cudaEventRecord(evFork0, 0);
    cudaStreamWaitEvent(s1, evFork0, 0);
    f2h_b_kernel<<<(N4_B + 255)/256, 256, 0, s1>>>(W1, w116, W2, w216);

    // main: fused LN(x)+gating (+x16 emission)
    lnxg_kernel<<<ROWS, 256>>>(x, ln_kv_g, ln_kv_b, pos, wg, wn, noise, kv16, kvp16, x16, gates);
    cudaEventRecord(evGates, 0);

    // side: expert-0 FC1 (needs x16 + gates from lnxg, W1 from f2h_b)
    cudaStreamWaitEvent(s1, evGates, 0);
    hgemm<2><<<dim3(32, 72), 256, SMEM_DYN, s1>>>(x16, w116, nullptr, h16, ROWS, HIDD, MMD, b1, gates);
    cudaEventRecord(evJoin, s1);

    // main: attention chain
    lnq_kernel<<<NQS, 256>>>(query, ln_q_g, ln_q_b, pos, qn16);
    f2h_a_kernel<<<(N4_A + 255)/256, 256>>>(ipw, ipw16, ow, ow16);

    hgemm<1><<<dim3(8, 5),  256, SMEM_DYN>>>(qn16,  ipw16,             nullptr, q16, NQS,  MMD, MMD, ipb,         nullptr);
    hgemm<1><<<dim3(8, 72), 256, SMEM_DYN>>>(kvp16, ipw16 + MMD*MMD,   nullptr, k16, ROWS, MMD, MMD, ipb + MMD,   nullptr);
    hgemm<1><<<dim3(8, 72), 256, SMEM_DYN>>>(kv16,  ipw16 + 2*MMD*MMD, nullptr, v16, ROWS, MMD, MMD, ipb + 2*MMD, nullptr);

    flash_attn<<<dim3(5, NBH), 256, FA_SMEM>>>(q16, k16, v16, attn16);

    hgemm<1><<<dim3(8, 72), 256, SMEM_DYN>>>(attn16, ow16, nullptr, e1in16, ROWS, MMD, MMD, ob, nullptr);

    // join: FC1(e1) RMWs h16 written by side-stream FC1(x); FC2 needs w216 from side
    cudaStreamWaitEvent(0, evJoin, 0);
    hgemm<3><<<dim3(32, 72), 256, SMEM_DYN>>>(e1in16, w116, nullptr, h16, ROWS, HIDD, MMD, b1, gates);
    hgemm<4><<<dim3(32, 72), 256, SMEM_DYN>>>(h16,    w216, out, nullptr, ROWS, HIDD, HIDD, b2, gates);
}

// round 13
// speedup vs baseline: 1.0148x; 1.0030x over previous
#include <cuda_runtime.h>
#include <cuda_fp16.h>
#include <math.h>
#include <cstdint>

// ---------------- problem constants ----------------
#define NQS   576
#define BATCH 16
#define MMD   1024
#define HIDD  4096
#define ROWS  (BATCH*NQS)        // 9216
#define HEADS 8
#define DH    128
#define NBH   (BATCH*HEADS)      // 128

// ---------------- HMMA GEMM tiling (128x128, 256 thr, 2 CTA/SM) ----------------
#define BM 128
#define BN 128
#define BK 64
#define STAGES 3
#define STAGE_BYTES ((BM+BN)*128)                    // 32 KB
#define SMEM_DYN (STAGES*STAGE_BYTES + 2048)
#define FA_SMEM (96*1024 + 1024)

// ---------------- scratch (device globals) ----------------
__device__ __align__(16) float  g_qp [NQS*MMD];              // fp16 q
__device__ __align__(16) float  g_kp [ROWS*MMD];             // fp16 k
__device__ __align__(16) float  g_vp [ROWS*MMD];             // fp16 v
__device__ __align__(16) float  g_gates[ROWS*2];
__device__ __align__(16) __half g_x16   [ROWS*MMD];
__device__ __align__(16) __half g_kv16  [ROWS*MMD];
__device__ __align__(16) __half g_kvp16 [ROWS*MMD];
__device__ __align__(16) __half g_qn16  [NQS*MMD];
__device__ __align__(16) __half g_attn16[ROWS*MMD];
__device__ __align__(16) __half g_e1in16[ROWS*MMD];
__device__ __align__(16) __half g_h16   [(size_t)ROWS*HIDD];
__device__ __align__(16) __half g_ipw16 [3*MMD*MMD];
__device__ __align__(16) __half g_ow16  [MMD*MMD];
__device__ __align__(16) __half g_w116  [HIDD*MMD];
__device__ __align__(16) __half g_w216  [(size_t)HIDD*HIDD];

// ---------------- helpers ----------------
__device__ __forceinline__ uint32_t smem_to_u32(const void* p) {
    uint32_t a;
    asm("{ .reg .u64 t; cvta.to.shared.u64 t, %1; cvt.u32.u64 %0, t; }" : "=r"(a) : "l"(p));
    return a;
}
#define SWZ(o) ((o) ^ (((o) >> 3) & 0x70))

__device__ __forceinline__ void cp16(uint32_t dst, const void* src, uint32_t sz) {
    asm volatile("cp.async.cg.shared.global [%0], [%1], 16, %2;\n" :: "r"(dst), "l"(src), "r"(sz));
}
#define CP_COMMIT() asm volatile("cp.async.commit_group;\n")
#define CP_WAIT(n)  asm volatile("cp.async.wait_group %0;\n" :: "n"(n))

#define LDSM_X4(r0,r1,r2,r3,addr) \
    asm volatile("ldmatrix.sync.aligned.m8n8.x4.shared.b16 {%0,%1,%2,%3}, [%4];" \
        : "=r"(r0), "=r"(r1), "=r"(r2), "=r"(r3) : "r"(addr))
#define LDSM_X4_T(r0,r1,r2,r3,addr) \
    asm volatile("ldmatrix.sync.aligned.m8n8.x4.trans.shared.b16 {%0,%1,%2,%3}, [%4];" \
        : "=r"(r0), "=r"(r1), "=r"(r2), "=r"(r3) : "r"(addr))

#define MMA16816(c, a0,a1,a2,a3, b0,b1) \
    asm volatile("mma.sync.aligned.m16n8k16.row.col.f32.f16.f16.f32 " \
        "{%0,%1,%2,%3},{%4,%5,%6,%7},{%8,%9},{%0,%1,%2,%3};" \
        : "+f"((c)[0]), "+f"((c)[1]), "+f"((c)[2]), "+f"((c)[3]) \
        : "r"(a0), "r"(a1), "r"(a2), "r"(a3), "r"(b0), "r"(b1))

__device__ __forceinline__ float gelu_exact(float v) {
    return 0.5f * v * (1.0f + erff(v * 0.7071067811865476f));
}
__device__ __forceinline__ float softplusf_(float x) {
    return fmaxf(x, 0.0f) + log1pf(expf(-fabsf(x)));
}
__device__ __forceinline__ uint32_t pack_h2(float a, float b) {
    __half2 h = __floats2half2_rn(a, b);
    return *(uint32_t*)&h;
}

// ---------------- split fp32 -> fp16 conversions ----------------
#define N4_IPW (3*MMD*MMD/4)
#define N4_OW  (MMD*MMD/4)
#define N4_W1  (HIDD*MMD/4)
#define N4_W2  (HIDD*HIDD/4)
#define N4_A   (N4_IPW+N4_OW)
#define N4_B   (N4_W1+N4_W2)

// main-stream: ipw + ow
__global__ void __launch_bounds__(256) f2h_a_kernel(
    const float* __restrict__ ipw, __half* __restrict__ ipw16,
    const float* __restrict__ ow,  __half* __restrict__ ow16)
{
    int i = blockIdx.x * blockDim.x + threadIdx.x;
    if (i >= N4_A) return;
    const float* src; __half* dst;
    if (i < N4_IPW) { src = ipw; dst = ipw16; }
    else { i -= N4_IPW; src = ow; dst = ow16; }
    float4 v = ((const float4*)src)[i];
    uint2 p;
    *((__half2*)&p.x) = __floats2half2_rn(v.x, v.y);
    *((__half2*)&p.y) = __floats2half2_rn(v.z, v.w);
    ((uint2*)dst)[i] = p;
}

// side-stream: W1 + W2 (forked at t=0)
__global__ void __launch_bounds__(256) f2h_b_kernel(
    const float* __restrict__ W1, __half* __restrict__ w116,
    const float* __restrict__ W2, __half* __restrict__ w216)
{
    int i = blockIdx.x * blockDim.x + threadIdx.x;
    if (i >= N4_B) return;
    const float* src; __half* dst;
    if (i < N4_W1) { src = W1; dst = w116; }
    else { i -= N4_W1; src = W2; dst = w216; }
    float4 v = ((const float4*)src)[i];
    uint2 p;
    *((__half2*)&p.x) = __floats2half2_rn(v.x, v.y);
    *((__half2*)&p.y) = __floats2half2_rn(v.z, v.w);
    ((uint2*)dst)[i] = p;
}

// ---------------- fused LN(x) + gating + x16 emission: one read of x ----------------
__global__ void __launch_bounds__(256) lnxg_kernel(
    const float* __restrict__ x, const float* __restrict__ g,
    const float* __restrict__ b, const float* __restrict__ pos,
    const float* __restrict__ wg, const float* __restrict__ wn,
    const float* __restrict__ noise,
    __half* __restrict__ kv16, __half* __restrict__ kvp16,
    __half* __restrict__ x16, float* __restrict__ gates)
{
    const int row = blockIdx.x;
    const int prow = row % NQS;
    const int t = threadIdx.x;

    const float4 xv = *(const float4*)(x + (size_t)row * MMD + t * 4);
    float s  = xv.x + xv.y + xv.z + xv.w;
    float ss = xv.x*xv.x + xv.y*xv.y + xv.z*xv.z + xv.w*xv.w;

    float4 wg0 = *(const float4*)(wg + 8*t);
    float4 wg1 = *(const float4*)(wg + 8*t + 4);
    float4 wn0 = *(const float4*)(wn + 8*t);
    float4 wn1 = *(const float4*)(wn + 8*t + 4);
    float d0 = xv.x*wg0.x + xv.y*wg0.z + xv.z*wg1.x + xv.w*wg1.z;
    float d1 = xv.x*wg0.y + xv.y*wg0.w + xv.z*wg1.y + xv.w*wg1.w;
    float d2 = xv.x*wn0.x + xv.y*wn0.z + xv.z*wn1.x + xv.w*wn1.z;
    float d3 = xv.x*wn0.y + xv.y*wn0.w + xv.z*wn1.y + xv.w*wn1.w;

    uint2 ox;
    ox.x = pack_h2(xv.x, xv.y); ox.y = pack_h2(xv.z, xv.w);
    *(uint2*)(x16 + (size_t)row * MMD + t * 4) = ox;

    __shared__ float red[6][8];
    float vals[6] = {s, ss, d0, d1, d2, d3};
    #pragma unroll
    for (int j = 0; j < 6; j++)
        #pragma unroll
        for (int o = 16; o; o >>= 1)
            vals[j] += __shfl_xor_sync(0xffffffffu, vals[j], o);
    int wid = t >> 5, lid = t & 31;
    if (lid == 0)
        #pragma unroll
        for (int j = 0; j < 6; j++) red[j][wid] = vals[j];
    __syncthreads();

    float S = 0.f, SS = 0.f;
    #pragma unroll
    for (int w = 0; w < 8; w++) { S += red[0][w]; SS += red[1][w]; }
    float mu = S / MMD;
    float rstd = rsqrtf(SS / MMD - mu * mu + 1e-5f);

    float4 gv = *(const float4*)(g + t * 4);
    float4 bv = *(const float4*)(b + t * 4);
    float4 pv = *(const float4*)(pos + (size_t)prow * MMD + t * 4);
    float v0 = (xv.x - mu) * rstd * gv.x + bv.x;
    float v1 = (xv.y - mu) * rstd * gv.y + bv.y;
    float v2 = (xv.z - mu) * rstd * gv.z + bv.z;
    float v3 = (xv.w - mu) * rstd * gv.w + bv.w;
    uint2 o1, o2;
    o1.x = pack_h2(v0, v1); o1.y = pack_h2(v2, v3);
    o2.x = pack_h2(v0 + pv.x, v1 + pv.y); o2.y = pack_h2(v2 + pv.z, v3 + pv.w);
    *(uint2*)(kv16  + (size_t)row * MMD + t * 4) = o1;
    *(uint2*)(kvp16 + (size_t)row * MMD + t * 4) = o2;

    if (t == 0) {
        float td[4] = {0.f, 0.f, 0.f, 0.f};
        #pragma unroll
        for (int w = 0; w < 8; w++)
            #pragma unroll
            for (int j = 0; j < 4; j++) td[j] += red[2 + j][w];
        float sp0 = softplusf_(td[2]) + 0.01f;
        float sp1 = softplusf_(td[3]) + 0.01f;
        float l0 = td[0] + noise[2*row]   * sp0;
        float l1 = td[1] + noise[2*row+1] * sp1;
        float mx = fmaxf(l0, l1);
        float e0 = expf(l0 - mx), e1 = expf(l1 - mx);
        float is = 1.0f / (e0 + e1);
        float p0 = e0 * is, p1 = e1 * is;
        float inv = 1.0f / (p0 + p1 + 1e-6f);
        gates[2*row]   = p0 * inv;
        gates[2*row+1] = p1 * inv;
    }
}

// ---------------- LN(query) + pos -> fp16, vectorized ----------------
__global__ void __launch_bounds__(256) lnq_kernel(
    const float* __restrict__ q, const float* __restrict__ g,
    const float* __restrict__ b, const float* __restrict__ pos,
    __half* __restrict__ qn16)
{
    const int row = blockIdx.x;
    const int t = threadIdx.x;
    const float4 xv = *(const float4*)(q + (size_t)row * MMD + t * 4);
    float s  = xv.x + xv.y + xv.z + xv.w;
    float ss = xv.x*xv.x + xv.y*xv.y + xv.z*xv.z + xv.w*xv.w;
    __shared__ float red[2][8];
    #pragma unroll
    for (int o = 16; o; o >>= 1) {
        s  += __shfl_xor_sync(0xffffffffu, s,  o);
        ss += __shfl_xor_sync(0xffffffffu, ss, o);
    }
    int wid = t >> 5, lid = t & 31;
    if (lid == 0) { red[0][wid] = s; red[1][wid] = ss; }
    __syncthreads();
    float S = 0.f, SS = 0.f;
    #pragma unroll
    for (int w = 0; w < 8; w++) { S += red[0][w]; SS += red[1][w]; }
    float mu = S / MMD;
    float rstd = rsqrtf(SS / MMD - mu * mu + 1e-5f);
    float4 gv = *(const float4*)(g + t * 4);
    float4 bv = *(const float4*)(b + t * 4);
    float4 pv = *(const float4*)(pos + (size_t)row * MMD + t * 4);
    uint2 o;
    o.x = pack_h2((xv.x - mu) * rstd * gv.x + bv.x + pv.x,
                  (xv.y - mu) * rstd * gv.y + bv.y + pv.y);
    o.y = pack_h2((xv.z - mu) * rstd * gv.z + bv.z + pv.z,
                  (xv.w - mu) * rstd * gv.w + bv.w + pv.w);
    *(uint2*)(qn16 + (size_t)row * MMD + t * 4) = o;
}

// ---------------- fp16 HMMA GEMM 128x128 (256 thr): C = A @ B^T ----------------
// EPI: 1 = fp16 +bias store, 2 = fp16 = g0*gelu(v+bias), 3 = fp16 += g1*gelu(v+bias),
//      4 = fp32 = acc + (g0+g1)*bias
__device__ __forceinline__ void load_stage(
    uint32_t stg, const __half* __restrict__ A, const __half* __restrict__ B,
    int row0, int col0, int M, int K, int kt, int tid)
{
    uint32_t sA = stg;
    uint32_t sB = stg + BM * 128;
    #pragma unroll
    for (int t = 0; t < 4; t++) {
        int op = tid + t * 256;
        int row = op >> 3, c = op & 7;
        int gr = row0 + row;
        uint32_t sz = (gr < M) ? 16u : 0u;
        if (gr >= M) gr = M - 1;
        cp16(sA + SWZ(row * 128 + c * 16), A + (size_t)gr * K + kt + c * 8, sz);
    }
    #pragma unroll
    for (int t = 0; t < 4; t++) {
        int op = tid + t * 256;
        int row = op >> 3, c = op & 7;
        cp16(sB + SWZ(row * 128 + c * 16), B + (size_t)(col0 + row) * K + kt + c * 8, 16u);
    }
}

template<int EPI>
__global__ void __launch_bounds__(256) hgemm(
    const __half* __restrict__ A, const __half* __restrict__ B,
    float* __restrict__ Cf, __half* __restrict__ Ch,
    int M, int N, int K,
    const float* __restrict__ bias, const float* __restrict__ gates)
{
    extern __shared__ char smem[];
    uint32_t sb0 = (smem_to_u32(smem) + 1023) & ~1023u;
    const int tid = threadIdx.x;
    const int lane = tid & 31, warp = tid >> 5;
    const int wm = warp >> 1, wn = warp & 1;
    const int row0 = blockIdx.y * BM, col0 = blockIdx.x * BN;

    const int a_row = wm * 32 + (lane & 15);
    const int a_kh  = (lane >> 4) << 3;
    const int b_row = wn * 64 + ((lane >> 4) << 3) + (lane & 7);
    const int b_kh  = ((lane >> 3) & 1) << 3;

    float acc[2][8][4];
    #pragma unroll
    for (int mi = 0; mi < 2; mi++)
        #pragma unroll
        for (int ni = 0; ni < 8; ni++)
            #pragma unroll
            for (int q = 0; q < 4; q++) acc[mi][ni][q] = 0.f;

    const int nchunk = K / BK;

    #pragma unroll
    for (int j = 0; j < STAGES - 1; j++) {
        load_stage(sb0 + j * STAGE_BYTES, A, B, row0, col0, M, K, j * BK, tid);
        CP_COMMIT();
    }

    for (int i = 0; i < nchunk; i++) {
        if (i + 1 == nchunk) CP_WAIT(0); else CP_WAIT(STAGES - 2);
        __syncthreads();

        // prefetch stage i+2 EARLY: its buffer (i+2)%3 was last read in
        // iteration i-1, which the barrier above just drained. Issuing the
        // cp.asyncs here lets the DMA overlap this iteration's MMA burst.
        int j = i + STAGES - 1;
        if (j < nchunk) {
            load_stage(sb0 + (j % STAGES) * STAGE_BYTES, A, B, row0, col0, M, K, j * BK, tid);
            CP_COMMIT();
        }

        uint32_t stg = sb0 + (i % STAGES) * STAGE_BYTES;
        uint32_t sA = stg, sB = stg + BM * 128;

        #pragma unroll
        for (int k16 = 0; k16 < BK / 16; k16++) {
            uint32_t a[2][4], b[4][4];
            #pragma unroll
            for (int mi = 0; mi < 2; mi++) {
                uint32_t addr = sA + SWZ((uint32_t)((a_row + mi * 16) * 128 + (k16 * 16 + a_kh) * 2));
                LDSM_X4(a[mi][0], a[mi][1], a[mi][2], a[mi][3], addr);
            }
            #pragma unroll
            for (int nq = 0; nq < 4; nq++) {
                uint32_t addr = sB + SWZ((uint32_t)((b_row + nq * 16) * 128 + (k16 * 16 + b_kh) * 2));
                LDSM_X4(b[nq][0], b[nq][1], b[nq][2], b[nq][3], addr);
            }
            #pragma unroll
            for (int mi = 0; mi < 2; mi++)
                #pragma unroll
                for (int nq = 0; nq < 4; nq++) {
                    MMA16816(acc[mi][2*nq],   a[mi][0], a[mi][1], a[mi][2], a[mi][3], b[nq][0], b[nq][1]);
                    MMA16816(acc[mi][2*nq+1], a[mi][0], a[mi][1], a[mi][2], a[mi][3], b[nq][2], b[nq][3]);
                }
        }
    }

    // ---------------- epilogue ----------------
    const int g = lane >> 2;
    const int cpair = (lane & 3) * 2;
    #pragma unroll
    for (int mi = 0; mi < 2; mi++) {
        #pragma unroll
        for (int half = 0; half < 2; half++) {
            int gm = row0 + wm * 32 + mi * 16 + g + half * 8;
            if (gm >= M) continue;
            float gsel = 0.f;
            if (EPI == 2) gsel = gates[2 * gm];
            if (EPI == 3) gsel = gates[2 * gm + 1];
            if (EPI == 4) gsel = gates[2 * gm] + gates[2 * gm + 1];
            #pragma unroll
            for (int ni = 0; ni < 8; ni++) {
                int gn = col0 + wn * 64 + ni * 8 + cpair;
                float a0 = acc[mi][ni][half * 2 + 0];
                float a1 = acc[mi][ni][half * 2 + 1];
                size_t idx = (size_t)gm * N + gn;
                if (EPI == 1) {
                    *(__half2*)(Ch + idx) = __floats2half2_rn(a0 + bias[gn], a1 + bias[gn + 1]);
                } else if (EPI == 2) {
                    *(__half2*)(Ch + idx) = __floats2half2_rn(
                        gsel * gelu_exact(a0 + bias[gn]), gsel * gelu_exact(a1 + bias[gn + 1]));
                } else if (EPI == 3) {
                    float2 o = __half22float2(*(__half2*)(Ch + idx));
                    *(__half2*)(Ch + idx) = __floats2half2_rn(
                        o.x + gsel * gelu_exact(a0 + bias[gn]),
                        o.y + gsel * gelu_exact(a1 + bias[gn + 1]));
                } else {
                    *(float2*)(Cf + idx) = make_float2(a0 + gsel * bias[gn], a1 + gsel * bias[gn + 1]);
                }
            }
        }
    }
}

// ---------------- fused flash attention (separate k16/v16, stride 1024) ----------------
__global__ void __launch_bounds__(256) flash_attn(
    const __half* __restrict__ q16, const __half* __restrict__ k16,
    const __half* __restrict__ v16, __half* __restrict__ attn)
{
    extern __shared__ char smem[];
    uint32_t sb = (smem_to_u32(smem) + 1023) & ~1023u;
    uint32_t sQ = sb;
    uint32_t sK = sb + 32 * 1024;
    uint32_t sV = sb + 64 * 1024;
    const int tid = threadIdx.x;
    const int lane = tid & 31, w = tid >> 5;
    const int z = blockIdx.y, b = z >> 3, h = z & 7;
    const __half* Q = q16 + h * DH;
    const __half* K = k16 + (size_t)b * NQS * MMD + h * DH;
    const __half* V = v16 + (size_t)b * NQS * MMD + h * DH;
    __half* O = attn + (size_t)b * NQS * MMD + h * DH;
    const int row0 = blockIdx.x * 128;

    #pragma unroll
    for (int t = 0; t < 8; t++) {
        int op = tid + t * 256;
        int r = op >> 4, c16 = op & 15;
        int gr = row0 + r; if (gr >= NQS) gr = NQS - 1;
        cp16(sQ + r * 256 + (uint32_t)((c16 ^ (r & 7)) << 4), Q + (size_t)gr * MMD + c16 * 8, 16u);
    }
    auto load_kv = [&](int buf, int kt) {
        uint32_t dK = sK + buf * 16384, dV = sV + buf * 16384;
        #pragma unroll
        for (int t = 0; t < 4; t++) {
            int op = tid + t * 256;
            int r = op >> 4, c16 = op & 15;
            cp16(dK + r * 256 + (uint32_t)((c16 ^ (r & 7)) << 4), K + (size_t)(kt + r) * MMD + c16 * 8, 16u);
        }
        #pragma unroll
        for (int t = 0; t < 4; t++) {
            int op = tid + t * 256;
            int r = op >> 4, c16 = op & 15;
            cp16(dV + r * 256 + (uint32_t)((c16 ^ (r & 7)) << 4), V + (size_t)(kt + r) * MMD + c16 * 8, 16u);
        }
    };
    load_kv(0, 0);
    CP_COMMIT();
    load_kv(1, 64);
    CP_COMMIT();

    const int g = lane >> 2, cq = (lane & 3) * 2;
    const int qrow = w * 16 + (lane & 15);
    const int qh   = lane >> 4;
    const int brsel = ((lane >> 4) << 3) + (lane & 7);
    const int bh    = (lane >> 3) & 1;
    const int v_krow = (lane & 7) + ((lane & 16) >> 1);
    const int v_c16h = (lane >> 3) & 1;

    float oacc[16][4];
    #pragma unroll
    for (int i = 0; i < 16; i++)
        #pragma unroll
        for (int q = 0; q < 4; q++) oacc[i][q] = 0.f;
    float m0 = -1e30f, m1 = -1e30f, l0 = 0.f, l1 = 0.f;
    const float scale = 0.08838834764831845f;

    const int NCH = NQS / 64;   // 9
    for (int i = 0; i < NCH; i++) {
        if (i + 1 < NCH) CP_WAIT(1); else CP_WAIT(0);
        __syncthreads();
        const int buf = i & 1;
        uint32_t bK = sK + buf * 16384, bV = sV + buf * 16384;

        float p[8][4];
        #pragma unroll
        for (int ni = 0; ni < 8; ni++)
            #pragma unroll
            for (int q = 0; q < 4; q++) p[ni][q] = 0.f;
        #pragma unroll
        for (int k16i = 0; k16i < 8; k16i++) {
            uint32_t a0, a1, a2, a3;
            uint32_t qaddr = sQ + qrow * 256 + (uint32_t)(((2 * k16i + qh) ^ (qrow & 7)) << 4);
            LDSM_X4(a0, a1, a2, a3, qaddr);
            #pragma unroll
            for (int nq = 0; nq < 4; nq++) {
                int br = nq * 16 + brsel;
                uint32_t baddr = bK + br * 256 + (uint32_t)(((2 * k16i + bh) ^ (br & 7)) << 4);
                uint32_t b0, b1, b2, b3;
                LDSM_X4(b0, b1, b2, b3, baddr);
                MMA16816(p[2*nq],   a0, a1, a2, a3, b0, b1);
                MMA16816(p[2*nq+1], a0, a1, a2, a3, b2, b3);
            }
        }
        #pragma unroll
        for (int ni = 0; ni < 8; ni++)
            #pragma unroll
            for (int q = 0; q < 4; q++) p[ni][q] *= scale;

        float t0 = -1e30f, t1 = -1e30f;
        #pragma unroll
        for (int ni = 0; ni < 8; ni++) {
            t0 = fmaxf(t0, fmaxf(p[ni][0], p[ni][1]));
            t1 = fmaxf(t1, fmaxf(p[ni][2], p[ni][3]));
        }
        t0 = fmaxf(t0, __shfl_xor_sync(0xffffffffu, t0, 1));
        t0 = fmaxf(t0, __shfl_xor_sync(0xffffffffu, t0, 2));
        t1 = fmaxf(t1, __shfl_xor_sync(0xffffffffu, t1, 1));
        t1 = fmaxf(t1, __shfl_xor_sync(0xffffffffu, t1, 2));
        float nm0 = fmaxf(m0, t0), nm1 = fmaxf(m1, t1);
        float es0 = expf(m0 - nm0), es1 = expf(m1 - nm1);
        float s0 = 0.f, s1 = 0.f;
        #pragma unroll
        for (int ni = 0; ni < 8; ni++) {
            p[ni][0] = expf(p[ni][0] - nm0);
            p[ni][1] = expf(p[ni][1] - nm0);
            p[ni][2] = expf(p[ni][2] - nm1);
            p[ni][3] = expf(p[ni][3] - nm1);
            s0 += p[ni][0] + p[ni][1];
            s1 += p[ni][2] + p[ni][3];
        }
        s0 += __shfl_xor_sync(0xffffffffu, s0, 1);
        s0 += __shfl_xor_sync(0xffffffffu, s0, 2);
        s1 += __shfl_xor_sync(0xffffffffu, s1, 1);
        s1 += __shfl_xor_sync(0xffffffffu, s1, 2);
        l0 = l0 * es0 + s0;
        l1 = l1 * es1 + s1;
        m0 = nm0; m1 = nm1;
        #pragma unroll
        for (int ni = 0; ni < 16; ni++) {
            oacc[ni][0] *= es0; oacc[ni][1] *= es0;
            oacc[ni][2] *= es1; oacc[ni][3] *= es1;
        }

        #pragma unroll
        for (int kk = 0; kk < 4; kk++) {
            uint32_t a0 = pack_h2(p[2*kk][0],   p[2*kk][1]);
            uint32_t a1 = pack_h2(p[2*kk][2],   p[2*kk][3]);
            uint32_t a2 = pack_h2(p[2*kk+1][0], p[2*kk+1][1]);
            uint32_t a3 = pack_h2(p[2*kk+1][2], p[2*kk+1][3]);
            int vrow = kk * 16 + v_krow;
            #pragma unroll
            for (int ng = 0; ng < 8; ng++) {
                int c16 = ng * 2 + v_c16h;
                uint32_t addr = bV + vrow * 256 + (uint32_t)((c16 ^ (vrow & 7)) << 4);
                uint32_t r0, r1, r2, r3;
                LDSM_X4_T(r0, r1, r2, r3, addr);
                MMA16816(oacc[2*ng],   a0, a1, a2, a3, r0, r2);
                MMA16816(oacc[2*ng+1], a0, a1, a2, a3, r1, r3);
            }
        }

        if (i + 2 < NCH) {
            __syncthreads();
            load_kv(buf, (i + 2) * 64);
            CP_COMMIT();
        }
    }

    float inv0 = 1.0f / l0, inv1 = 1.0f / l1;
    int gm0 = row0 + w * 16 + g;
    int gm1 = gm0 + 8;
    #pragma unroll
    for (int ni = 0; ni < 16; ni++) {
        int gn = ni * 8 + cq;
        if (gm0 < NQS)
            *(__half2*)(O + (size_t)gm0 * MMD + gn) = __floats2half2_rn(oacc[ni][0] * inv0, oacc[ni][1] * inv0);
        if (gm1 < NQS)
            *(__half2*)(O + (size_t)gm1 * MMD + gn) = __floats2half2_rn(oacc[ni][2] * inv1, oacc[ni][3] * inv1);
    }
}

// ---------------- launch ----------------
extern "C" void kernel_launch(void* const* d_in, const int* in_sizes, int n_in,
                              void* d_out, int out_size)
{
    const float* x      = (const float*)d_in[0];
    const float* noise  = (const float*)d_in[1];
    const float* W1     = (const float*)d_in[2];
    const float* b1     = (const float*)d_in[3];
    const float* W2     = (const float*)d_in[4];
    const float* b2     = (const float*)d_in[5];
    const float* query  = (const float*)d_in[6];
    const float* pos    = (const float*)d_in[7];
    const float* ln_q_g = (const float*)d_in[8];
    const float* ln_q_b = (const float*)d_in[9];
    const float* ln_kv_g= (const float*)d_in[10];
    const float* ln_kv_b= (const float*)d_in[11];
    const float* ipw    = (const float*)d_in[12];
    const float* ipb    = (const float*)d_in[13];
    const float* ow     = (const float*)d_in[14];
    const float* ob     = (const float*)d_in[15];
    const float* wg     = (const float*)d_in[16];
    const float* wn     = (const float*)d_in[17];
    float* out = (float*)d_out;

    float *gates;
    __half *q16, *k16, *v16;
    __half *x16, *kv16, *kvp16, *qn16, *attn16, *e1in16, *h16, *ipw16, *ow16, *w116, *w216;
    cudaGetSymbolAddress((void**)&q16,    g_qp);
    cudaGetSymbolAddress((void**)&k16,    g_kp);
    cudaGetSymbolAddress((void**)&v16,    g_vp);
    cudaGetSymbolAddress((void**)&gates,  g_gates);
    cudaGetSymbolAddress((void**)&x16,    g_x16);
    cudaGetSymbolAddress((void**)&kv16,   g_kv16);
    cudaGetSymbolAddress((void**)&kvp16,  g_kvp16);
    cudaGetSymbolAddress((void**)&qn16,   g_qn16);
    cudaGetSymbolAddress((void**)&attn16, g_attn16);
    cudaGetSymbolAddress((void**)&e1in16, g_e1in16);
    cudaGetSymbolAddress((void**)&h16,    g_h16);
    cudaGetSymbolAddress((void**)&ipw16,  g_ipw16);
    cudaGetSymbolAddress((void**)&ow16,   g_ow16);
    cudaGetSymbolAddress((void**)&w116,   g_w116);
    cudaGetSymbolAddress((void**)&w216,   g_w216);

    static cudaStream_t s1 = nullptr, s2 = nullptr;
    static cudaEvent_t evFork0 = nullptr, evGates = nullptr, evJoin = nullptr;
    static cudaEvent_t evQin = nullptr, evQdone = nullptr;
    static bool attr_done = false;
    if (!attr_done) {
        cudaFuncSetAttribute(hgemm<1>, cudaFuncAttributeMaxDynamicSharedMemorySize, SMEM_DYN);
        cudaFuncSetAttribute(hgemm<2>, cudaFuncAttributeMaxDynamicSharedMemorySize, SMEM_DYN);
        cudaFuncSetAttribute(hgemm<3>, cudaFuncAttributeMaxDynamicSharedMemorySize, SMEM_DYN);
        cudaFuncSetAttribute(hgemm<4>, cudaFuncAttributeMaxDynamicSharedMemorySize, SMEM_DYN);
        cudaFuncSetAttribute(flash_attn, cudaFuncAttributeMaxDynamicSharedMemorySize, FA_SMEM);
        cudaStreamCreateWithFlags(&s1, cudaStreamNonBlocking);
        cudaStreamCreateWithFlags(&s2, cudaStreamNonBlocking);
        cudaEventCreateWithFlags(&evFork0, cudaEventDisableTiming);
        cudaEventCreateWithFlags(&evGates, cudaEventDisableTiming);
        cudaEventCreateWithFlags(&evJoin, cudaEventDisableTiming);
        cudaEventCreateWithFlags(&evQin, cudaEventDisableTiming);
        cudaEventCreateWithFlags(&evQdone, cudaEventDisableTiming);
        attr_done = true;
    }

    // fork side stream immediately: W1/W2 conversion has no dependencies
    cudaEventRecord(evFork0, 0);
    cudaStreamWaitEvent(s1, evFork0, 0);
    f2h_b_kernel<<<(N4_B + 255)/256, 256, 0, s1>>>(W1, w116, W2, w216);

    // main: fused LN(x)+gating (+x16 emission)
    lnxg_kernel<<<ROWS, 256>>>(x, ln_kv_g, ln_kv_b, pos, wg, wn, noise, kv16, kvp16, x16, gates);
    cudaEventRecord(evGates, 0);

    // side s1: expert-0 FC1 (needs x16 + gates from lnxg, W1 from f2h_b)
    cudaStreamWaitEvent(s1, evGates, 0);
    hgemm<2><<<dim3(32, 72), 256, SMEM_DYN, s1>>>(x16, w116, nullptr, h16, ROWS, HIDD, MMD, b1, gates);
    cudaEventRecord(evJoin, s1);

    // main: prologue for attention
    lnq_kernel<<<NQS, 256>>>(query, ln_q_g, ln_q_b, pos, qn16);
    f2h_a_kernel<<<(N4_A + 255)/256, 256>>>(ipw, ipw16, ow, ow16);
    cudaEventRecord(evQin, 0);

    // side s2: Q projection (only 40 CTAs; overlap with K/V projections)
    cudaStreamWaitEvent(s2, evQin, 0);
    hgemm<1><<<dim3(8, 5), 256, SMEM_DYN, s2>>>(qn16, ipw16, nullptr, q16, NQS, MMD, MMD, ipb, nullptr);
    cudaEventRecord(evQdone, s2);

    // main: K/V projections
    hgemm<1><<<dim3(8, 72), 256, SMEM_DYN>>>(kvp16, ipw16 + MMD*MMD,   nullptr, k16, ROWS, MMD, MMD, ipb + MMD,   nullptr);
    hgemm<1><<<dim3(8, 72), 256, SMEM_DYN>>>(kv16,  ipw16 + 2*MMD*MMD, nullptr, v16, ROWS, MMD, MMD, ipb + 2*MMD, nullptr);

    cudaStreamWaitEvent(0, evQdone, 0);
    flash_attn<<<dim3(5, NBH), 256, FA_SMEM>>>(q16, k16, v16, attn16);

    hgemm<1><<<dim3(8, 72), 256, SMEM_DYN>>>(attn16, ow16, nullptr, e1in16, ROWS, MMD, MMD, ob, nullptr);

    // join: FC1(e1) RMWs h16 written by side-stream FC1(x); FC2 needs w216 from side
    cudaStreamWaitEvent(0, evJoin, 0);
    hgemm<3><<<dim3(32, 72), 256, SMEM_DYN>>>(e1in16, w116, nullptr, h16, ROWS, HIDD, MMD, b1, gates);
    hgemm<4><<<dim3(32, 72), 256, SMEM_DYN>>>(h16,    w216, out, nullptr, ROWS, HIDD, HIDD, b2, gates);
}

// round 14
// speedup vs baseline: 1.0411x; 1.0259x over previous
#include <cuda_runtime.h>
#include <cuda_fp16.h>
#include <math.h>
#include <cstdint>

// ---------------- problem constants ----------------
#define NQS   576
#define BATCH 16
#define MMD   1024
#define HIDD  4096
#define ROWS  (BATCH*NQS)        // 9216
#define HEADS 8
#define DH    128
#define NBH   (BATCH*HEADS)      // 128

// ---------------- HMMA GEMM tiling (128x128, 256 thr, 2 CTA/SM) ----------------
#define BM 128
#define BN 128
#define BK 64
#define STAGES 3
#define STAGE_BYTES ((BM+BN)*128)                    // 32 KB
#define SMEM_DYN (STAGES*STAGE_BYTES + 2048)
#define FA_SMEM (96*1024 + 1024)

// ---------------- scratch (device globals) ----------------
__device__ __align__(16) float  g_qp [NQS*MMD];              // fp16 q
__device__ __align__(16) float  g_kp [ROWS*MMD];             // fp16 k
__device__ __align__(16) float  g_vp [ROWS*MMD];             // fp16 v
__device__ __align__(16) float  g_gates[ROWS*2];
__device__ __align__(16) float  g_b1p [HIDD];
__device__ __align__(16) __half g_x16   [ROWS*MMD];
__device__ __align__(16) __half g_kv16  [ROWS*MMD];
__device__ __align__(16) __half g_kvp16 [ROWS*MMD];
__device__ __align__(16) __half g_qn16  [NQS*MMD];
__device__ __align__(16) __half g_attn16[ROWS*MMD];
__device__ __align__(16) __half g_w1p16 [HIDD*MMD];          // W1 @ ow  (folded weight)
__device__ __align__(16) __half g_h16   [(size_t)ROWS*HIDD];
__device__ __align__(16) __half g_ipw16 [3*MMD*MMD];
__device__ __align__(16) __half g_owT16 [MMD*MMD];           // ow transposed, fp16
__device__ __align__(16) __half g_w116  [HIDD*MMD];
__device__ __align__(16) __half g_w216  [(size_t)HIDD*HIDD];

// ---------------- helpers ----------------
__device__ __forceinline__ uint32_t smem_to_u32(const void* p) {
    uint32_t a;
    asm("{ .reg .u64 t; cvta.to.shared.u64 t, %1; cvt.u32.u64 %0, t; }" : "=r"(a) : "l"(p));
    return a;
}
#define SWZ(o) ((o) ^ (((o) >> 3) & 0x70))

__device__ __forceinline__ void cp16(uint32_t dst, const void* src, uint32_t sz) {
    asm volatile("cp.async.cg.shared.global [%0], [%1], 16, %2;\n" :: "r"(dst), "l"(src), "r"(sz));
}
#define CP_COMMIT() asm volatile("cp.async.commit_group;\n")
#define CP_WAIT(n)  asm volatile("cp.async.wait_group %0;\n" :: "n"(n))

#define LDSM_X4(r0,r1,r2,r3,addr) \
    asm volatile("ldmatrix.sync.aligned.m8n8.x4.shared.b16 {%0,%1,%2,%3}, [%4];" \
        : "=r"(r0), "=r"(r1), "=r"(r2), "=r"(r3) : "r"(addr))
#define LDSM_X4_T(r0,r1,r2,r3,addr) \
    asm volatile("ldmatrix.sync.aligned.m8n8.x4.trans.shared.b16 {%0,%1,%2,%3}, [%4];" \
        : "=r"(r0), "=r"(r1), "=r"(r2), "=r"(r3) : "r"(addr))

#define MMA16816(c, a0,a1,a2,a3, b0,b1) \
    asm volatile("mma.sync.aligned.m16n8k16.row.col.f32.f16.f16.f32 " \
        "{%0,%1,%2,%3},{%4,%5,%6,%7},{%8,%9},{%0,%1,%2,%3};" \
        : "+f"((c)[0]), "+f"((c)[1]), "+f"((c)[2]), "+f"((c)[3]) \
        : "r"(a0), "r"(a1), "r"(a2), "r"(a3), "r"(b0), "r"(b1))

__device__ __forceinline__ float gelu_exact(float v) {
    return 0.5f * v * (1.0f + erff(v * 0.7071067811865476f));
}
__device__ __forceinline__ float softplusf_(float x) {
    return fmaxf(x, 0.0f) + log1pf(expf(-fabsf(x)));
}
__device__ __forceinline__ uint32_t pack_h2(float a, float b) {
    __half2 h = __floats2half2_rn(a, b);
    return *(uint32_t*)&h;
}

// ---------------- fp32 -> fp16 conversions ----------------
#define N4_IPW (3*MMD*MMD/4)
#define N4_W1  (HIDD*MMD/4)
#define N4_W2  (HIDD*HIDD/4)
#define N4_B   (N4_W1+N4_W2)

// main-stream: ipw only
__global__ void __launch_bounds__(256) f2h_a_kernel(
    const float* __restrict__ ipw, __half* __restrict__ ipw16)
{
    int i = blockIdx.x * blockDim.x + threadIdx.x;
    if (i >= N4_IPW) return;
    float4 v = ((const float4*)ipw)[i];
    uint2 p;
    *((__half2*)&p.x) = __floats2half2_rn(v.x, v.y);
    *((__half2*)&p.y) = __floats2half2_rn(v.z, v.w);
    ((uint2*)ipw16)[i] = p;
}

// side-stream: W1 + W2 (forked at t=0)
__global__ void __launch_bounds__(256) f2h_b_kernel(
    const float* __restrict__ W1, __half* __restrict__ w116,
    const float* __restrict__ W2, __half* __restrict__ w216)
{
    int i = blockIdx.x * blockDim.x + threadIdx.x;
    if (i >= N4_B) return;
    const float* src; __half* dst;
    if (i < N4_W1) { src = W1; dst = w116; }
    else { i -= N4_W1; src = W2; dst = w216; }
    float4 v = ((const float4*)src)[i];
    uint2 p;
    *((__half2*)&p.x) = __floats2half2_rn(v.x, v.y);
    *((__half2*)&p.y) = __floats2half2_rn(v.z, v.w);
    ((uint2*)dst)[i] = p;
}

// side-stream: ow (fp32) -> owT (fp16, transposed): owT[k][j] = ow[j][k]
__global__ void __launch_bounds__(256) owT_kernel(
    const float* __restrict__ ow, __half* __restrict__ owT)
{
    __shared__ float tile[32][33];
    const int bx = blockIdx.x * 32, by = blockIdx.y * 32;
    const int tx = threadIdx.x & 31, ty = threadIdx.x >> 5;  // 32x8
    #pragma unroll
    for (int r = 0; r < 32; r += 8)
        tile[ty + r][tx] = ow[(size_t)(by + ty + r) * MMD + bx + tx];
    __syncthreads();
    #pragma unroll
    for (int r = 0; r < 32; r += 8)
        owT[(size_t)(bx + ty + r) * MMD + by + tx] = __float2half_rn(tile[tx][ty + r]);
}

// side-stream: b1p[i] = b1[i] + sum_j W1[i][j] * ob[j]
__global__ void __launch_bounds__(128) b1p_kernel(
    const float* __restrict__ W1, const float* __restrict__ b1,
    const float* __restrict__ ob, float* __restrict__ b1p)
{
    const int i = blockIdx.x;
    float s = 0.f;
    for (int j = threadIdx.x; j < MMD; j += 128)
        s += W1[(size_t)i * MMD + j] * ob[j];
    __shared__ float red[4];
    #pragma unroll
    for (int o = 16; o; o >>= 1) s += __shfl_xor_sync(0xffffffffu, s, o);
    if ((threadIdx.x & 31) == 0) red[threadIdx.x >> 5] = s;
    __syncthreads();
    if (threadIdx.x == 0)
        b1p[i] = b1[i] + red[0] + red[1] + red[2] + red[3];
}

// ---------------- fused LN(x) + gating + x16 emission: one read of x ----------------
__global__ void __launch_bounds__(256) lnxg_kernel(
    const float* __restrict__ x, const float* __restrict__ g,
    const float* __restrict__ b, const float* __restrict__ pos,
    const float* __restrict__ wg, const float* __restrict__ wn,
    const float* __restrict__ noise,
    __half* __restrict__ kv16, __half* __restrict__ kvp16,
    __half* __restrict__ x16, float* __restrict__ gates)
{
    const int row = blockIdx.x;
    const int prow = row % NQS;
    const int t = threadIdx.x;

    const float4 xv = *(const float4*)(x + (size_t)row * MMD + t * 4);
    float s  = xv.x + xv.y + xv.z + xv.w;
    float ss = xv.x*xv.x + xv.y*xv.y + xv.z*xv.z + xv.w*xv.w;

    float4 wg0 = *(const float4*)(wg + 8*t);
    float4 wg1 = *(const float4*)(wg + 8*t + 4);
    float4 wn0 = *(const float4*)(wn + 8*t);
    float4 wn1 = *(const float4*)(wn + 8*t + 4);
    float d0 = xv.x*wg0.x + xv.y*wg0.z + xv.z*wg1.x + xv.w*wg1.z;
    float d1 = xv.x*wg0.y + xv.y*wg0.w + xv.z*wg1.y + xv.w*wg1.w;
    float d2 = xv.x*wn0.x + xv.y*wn0.z + xv.z*wn1.x + xv.w*wn1.z;
    float d3 = xv.x*wn0.y + xv.y*wn0.w + xv.z*wn1.y + xv.w*wn1.w;

    uint2 ox;
    ox.x = pack_h2(xv.x, xv.y); ox.y = pack_h2(xv.z, xv.w);
    *(uint2*)(x16 + (size_t)row * MMD + t * 4) = ox;

    __shared__ float red[6][8];
    float vals[6] = {s, ss, d0, d1, d2, d3};
    #pragma unroll
    for (int j = 0; j < 6; j++)
        #pragma unroll
        for (int o = 16; o; o >>= 1)
            vals[j] += __shfl_xor_sync(0xffffffffu, vals[j], o);
    int wid = t >> 5, lid = t & 31;
    if (lid == 0)
        #pragma unroll
        for (int j = 0; j < 6; j++) red[j][wid] = vals[j];
    __syncthreads();

    float S = 0.f, SS = 0.f;
    #pragma unroll
    for (int w = 0; w < 8; w++) { S += red[0][w]; SS += red[1][w]; }
    float mu = S / MMD;
    float rstd = rsqrtf(SS / MMD - mu * mu + 1e-5f);

    float4 gv = *(const float4*)(g + t * 4);
    float4 bv = *(const float4*)(b + t * 4);
    float4 pv = *(const float4*)(pos + (size_t)prow * MMD + t * 4);
    float v0 = (xv.x - mu) * rstd * gv.x + bv.x;
    float v1 = (xv.y - mu) * rstd * gv.y + bv.y;
    float v2 = (xv.z - mu) * rstd * gv.z + bv.z;
    float v3 = (xv.w - mu) * rstd * gv.w + bv.w;
    uint2 o1, o2;
    o1.x = pack_h2(v0, v1); o1.y = pack_h2(v2, v3);
    o2.x = pack_h2(v0 + pv.x, v1 + pv.y); o2.y = pack_h2(v2 + pv.z, v3 + pv.w);
    *(uint2*)(kv16  + (size_t)row * MMD + t * 4) = o1;
    *(uint2*)(kvp16 + (size_t)row * MMD + t * 4) = o2;

    if (t == 0) {
        float td[4] = {0.f, 0.f, 0.f, 0.f};
        #pragma unroll
        for (int w = 0; w < 8; w++)
            #pragma unroll
            for (int j = 0; j < 4; j++) td[j] += red[2 + j][w];
        float sp0 = softplusf_(td[2]) + 0.01f;
        float sp1 = softplusf_(td[3]) + 0.01f;
        float l0 = td[0] + noise[2*row]   * sp0;
        float l1 = td[1] + noise[2*row+1] * sp1;
        float mx = fmaxf(l0, l1);
        float e0 = expf(l0 - mx), e1 = expf(l1 - mx);
        float is = 1.0f / (e0 + e1);
        float p0 = e0 * is, p1 = e1 * is;
        float inv = 1.0f / (p0 + p1 + 1e-6f);
        gates[2*row]   = p0 * inv;
        gates[2*row+1] = p1 * inv;
    }
}

// ---------------- LN(query) + pos -> fp16, vectorized ----------------
__global__ void __launch_bounds__(256) lnq_kernel(
    const float* __restrict__ q, const float* __restrict__ g,
    const float* __restrict__ b, const float* __restrict__ pos,
    __half* __restrict__ qn16)
{
    const int row = blockIdx.x;
    const int t = threadIdx.x;
    const float4 xv = *(const float4*)(q + (size_t)row * MMD + t * 4);
    float s  = xv.x + xv.y + xv.z + xv.w;
    float ss = xv.x*xv.x + xv.y*xv.y + xv.z*xv.z + xv.w*xv.w;
    __shared__ float red[2][8];
    #pragma unroll
    for (int o = 16; o; o >>= 1) {
        s  += __shfl_xor_sync(0xffffffffu, s,  o);
        ss += __shfl_xor_sync(0xffffffffu, ss, o);
    }
    int wid = t >> 5, lid = t & 31;
    if (lid == 0) { red[0][wid] = s; red[1][wid] = ss; }
    __syncthreads();
    float S = 0.f, SS = 0.f;
    #pragma unroll
    for (int w = 0; w < 8; w++) { S += red[0][w]; SS += red[1][w]; }
    float mu = S / MMD;
    float rstd = rsqrtf(SS / MMD - mu * mu + 1e-5f);
    float4 gv = *(const float4*)(g + t * 4);
    float4 bv = *(const float4*)(b + t * 4);
    float4 pv = *(const float4*)(pos + (size_t)row * MMD + t * 4);
    uint2 o;
    o.x = pack_h2((xv.x - mu) * rstd * gv.x + bv.x + pv.x,
                  (xv.y - mu) * rstd * gv.y + bv.y + pv.y);
    o.y = pack_h2((xv.z - mu) * rstd * gv.z + bv.z + pv.z,
                  (xv.w - mu) * rstd * gv.w + bv.w + pv.w);
    *(uint2*)(qn16 + (size_t)row * MMD + t * 4) = o;
}

// ---------------- fp16 HMMA GEMM 128x128 (256 thr): C = A @ B^T ----------------
// EPI: 0 = fp16 plain store, 1 = fp16 +bias store, 2 = fp16 = g0*gelu(v+bias),
//      3 = fp16 += g1*gelu(v+bias), 4 = fp32 = acc + (g0+g1)*bias
__device__ __forceinline__ void load_stage(
    uint32_t stg, const __half* __restrict__ A, const __half* __restrict__ B,
    int row0, int col0, int M, int K, int kt, int tid)
{
    uint32_t sA = stg;
    uint32_t sB = stg + BM * 128;
    #pragma unroll
    for (int t = 0; t < 4; t++) {
        int op = tid + t * 256;
        int row = op >> 3, c = op & 7;
        int gr = row0 + row;
        uint32_t sz = (gr < M) ? 16u : 0u;
        if (gr >= M) gr = M - 1;
        cp16(sA + SWZ(row * 128 + c * 16), A + (size_t)gr * K + kt + c * 8, sz);
    }
    #pragma unroll
    for (int t = 0; t < 4; t++) {
        int op = tid + t * 256;
        int row = op >> 3, c = op & 7;
        cp16(sB + SWZ(row * 128 + c * 16), B + (size_t)(col0 + row) * K + kt + c * 8, 16u);
    }
}

template<int EPI>
__global__ void __launch_bounds__(256) hgemm(
    const __half* __restrict__ A, const __half* __restrict__ B,
    float* __restrict__ Cf, __half* __restrict__ Ch,
    int M, int N, int K,
    const float* __restrict__ bias, const float* __restrict__ gates)
{
    extern __shared__ char smem[];
    uint32_t sb0 = (smem_to_u32(smem) + 1023) & ~1023u;
    const int tid = threadIdx.x;
    const int lane = tid & 31, warp = tid >> 5;
    const int wm = warp >> 1, wn = warp & 1;
    const int row0 = blockIdx.y * BM, col0 = blockIdx.x * BN;

    const int a_row = wm * 32 + (lane & 15);
    const int a_kh  = (lane >> 4) << 3;
    const int b_row = wn * 64 + ((lane >> 4) << 3) + (lane & 7);
    const int b_kh  = ((lane >> 3) & 1) << 3;

    float acc[2][8][4];
    #pragma unroll
    for (int mi = 0; mi < 2; mi++)
        #pragma unroll
        for (int ni = 0; ni < 8; ni++)
            #pragma unroll
            for (int q = 0; q < 4; q++) acc[mi][ni][q] = 0.f;

    const int nchunk = K / BK;

    #pragma unroll
    for (int j = 0; j < STAGES - 1; j++) {
        load_stage(sb0 + j * STAGE_BYTES, A, B, row0, col0, M, K, j * BK, tid);
        CP_COMMIT();
    }

    for (int i = 0; i < nchunk; i++) {
        if (i + 1 == nchunk) CP_WAIT(0); else CP_WAIT(STAGES - 2);
        __syncthreads();

        int j = i + STAGES - 1;
        if (j < nchunk) {
            load_stage(sb0 + (j % STAGES) * STAGE_BYTES, A, B, row0, col0, M, K, j * BK, tid);
            CP_COMMIT();
        }

        uint32_t stg = sb0 + (i % STAGES) * STAGE_BYTES;
        uint32_t sA = stg, sB = stg + BM * 128;

        #pragma unroll
        for (int k16 = 0; k16 < BK / 16; k16++) {
            uint32_t a[2][4], b[4][4];
            #pragma unroll
            for (int mi = 0; mi < 2; mi++) {
                uint32_t addr = sA + SWZ((uint32_t)((a_row + mi * 16) * 128 + (k16 * 16 + a_kh) * 2));
                LDSM_X4(a[mi][0], a[mi][1], a[mi][2], a[mi][3], addr);
            }
            #pragma unroll
            for (int nq = 0; nq < 4; nq++) {
                uint32_t addr = sB + SWZ((uint32_t)((b_row + nq * 16) * 128 + (k16 * 16 + b_kh) * 2));
                LDSM_X4(b[nq][0], b[nq][1], b[nq][2], b[nq][3], addr);
            }
            #pragma unroll
            for (int mi = 0; mi < 2; mi++)
                #pragma unroll
                for (int nq = 0; nq < 4; nq++) {
                    MMA16816(acc[mi][2*nq],   a[mi][0], a[mi][1], a[mi][2], a[mi][3], b[nq][0], b[nq][1]);
                    MMA16816(acc[mi][2*nq+1], a[mi][0], a[mi][1], a[mi][2], a[mi][3], b[nq][2], b[nq][3]);
                }
        }
    }

    // ---------------- epilogue ----------------
    const int g = lane >> 2;
    const int cpair = (lane & 3) * 2;
    #pragma unroll
    for (int mi = 0; mi < 2; mi++) {
        #pragma unroll
        for (int half = 0; half < 2; half++) {
            int gm = row0 + wm * 32 + mi * 16 + g + half * 8;
            if (gm >= M) continue;
            float gsel = 0.f;
            if (EPI == 2) gsel = gates[2 * gm];
            if (EPI == 3) gsel = gates[2 * gm + 1];
            if (EPI == 4) gsel = gates[2 * gm] + gates[2 * gm + 1];
            #pragma unroll
            for (int ni = 0; ni < 8; ni++) {
                int gn = col0 + wn * 64 + ni * 8 + cpair;
                float a0 = acc[mi][ni][half * 2 + 0];
                float a1 = acc[mi][ni][half * 2 + 1];
                size_t idx = (size_t)gm * N + gn;
                if (EPI == 0) {
                    *(__half2*)(Ch + idx) = __floats2half2_rn(a0, a1);
                } else if (EPI == 1) {
                    *(__half2*)(Ch + idx) = __floats2half2_rn(a0 + bias[gn], a1 + bias[gn + 1]);
                } else if (EPI == 2) {
                    *(__half2*)(Ch + idx) = __floats2half2_rn(
                        gsel * gelu_exact(a0 + bias[gn]), gsel * gelu_exact(a1 + bias[gn + 1]));
                } else if (EPI == 3) {
                    float2 o = __half22float2(*(__half2*)(Ch + idx));
                    *(__half2*)(Ch + idx) = __floats2half2_rn(
                        o.x + gsel * gelu_exact(a0 + bias[gn]),
                        o.y + gsel * gelu_exact(a1 + bias[gn + 1]));
                } else {
                    *(float2*)(Cf + idx) = make_float2(a0 + gsel * bias[gn], a1 + gsel * bias[gn + 1]);
                }
            }
        }
    }
}

// ---------------- fused flash attention (separate k16/v16, stride 1024) ----------------
__global__ void __launch_bounds__(256) flash_attn(
    const __half* __restrict__ q16, const __half* __restrict__ k16,
    const __half* __restrict__ v16, __half* __restrict__ attn)
{
    extern __shared__ char smem[];
    uint32_t sb = (smem_to_u32(smem) + 1023) & ~1023u;
    uint32_t sQ = sb;
    uint32_t sK = sb + 32 * 1024;
    uint32_t sV = sb + 64 * 1024;
    const int tid = threadIdx.x;
    const int lane = tid & 31, w = tid >> 5;
    const int z = blockIdx.y, b = z >> 3, h = z & 7;
    const __half* Q = q16 + h * DH;
    const __half* K = k16 + (size_t)b * NQS * MMD + h * DH;
    const __half* V = v16 + (size_t)b * NQS * MMD + h * DH;
    __half* O = attn + (size_t)b * NQS * MMD + h * DH;
    const int row0 = blockIdx.x * 128;

    #pragma unroll
    for (int t = 0; t < 8; t++) {
        int op = tid + t * 256;
        int r = op >> 4, c16 = op & 15;
        int gr = row0 + r; if (gr >= NQS) gr = NQS - 1;
        cp16(sQ + r * 256 + (uint32_t)((c16 ^ (r & 7)) << 4), Q + (size_t)gr * MMD + c16 * 8, 16u);
    }
    auto load_kv = [&](int buf, int kt) {
        uint32_t dK = sK + buf * 16384, dV = sV + buf * 16384;
        #pragma unroll
        for (int t = 0; t < 4; t++) {
            int op = tid + t * 256;
            int r = op >> 4, c16 = op & 15;
            cp16(dK + r * 256 + (uint32_t)((c16 ^ (r & 7)) << 4), K + (size_t)(kt + r) * MMD + c16 * 8, 16u);
        }
        #pragma unroll
        for (int t = 0; t < 4; t++) {
            int op = tid + t * 256;
            int r = op >> 4, c16 = op & 15;
            cp16(dV + r * 256 + (uint32_t)((c16 ^ (r & 7)) << 4), V + (size_t)(kt + r) * MMD + c16 * 8, 16u);
        }
    };
    load_kv(0, 0);
    CP_COMMIT();
    load_kv(1, 64);
    CP_COMMIT();

    const int g = lane >> 2, cq = (lane & 3) * 2;
    const int qrow = w * 16 + (lane & 15);
    const int qh   = lane >> 4;
    const int brsel = ((lane >> 4) << 3) + (lane & 7);
    const int bh    = (lane >> 3) & 1;
    const int v_krow = (lane & 7) + ((lane & 16) >> 1);
    const int v_c16h = (lane >> 3) & 1;

    float oacc[16][4];
    #pragma unroll
    for (int i = 0; i < 16; i++)
        #pragma unroll
        for (int q = 0; q < 4; q++) oacc[i][q] = 0.f;
    float m0 = -1e30f, m1 = -1e30f, l0 = 0.f, l1 = 0.f;
    const float scale = 0.08838834764831845f;

    const int NCH = NQS / 64;   // 9
    for (int i = 0; i < NCH; i++) {
        if (i + 1 < NCH) CP_WAIT(1); else CP_WAIT(0);
        __syncthreads();
        const int buf = i & 1;
        uint32_t bK = sK + buf * 16384, bV = sV + buf * 16384;

        float p[8][4];
        #pragma unroll
        for (int ni = 0; ni < 8; ni++)
            #pragma unroll
            for (int q = 0; q < 4; q++) p[ni][q] = 0.f;
        #pragma unroll
        for (int k16i = 0; k16i < 8; k16i++) {
            uint32_t a0, a1, a2, a3;
            uint32_t qaddr = sQ + qrow * 256 + (uint32_t)(((2 * k16i + qh) ^ (qrow & 7)) << 4);
            LDSM_X4(a0, a1, a2, a3, qaddr);
            #pragma unroll
            for (int nq = 0; nq < 4; nq++) {
                int br = nq * 16 + brsel;
                uint32_t baddr = bK + br * 256 + (uint32_t)(((2 * k16i + bh) ^ (br & 7)) << 4);
                uint32_t b0, b1, b2, b3;
                LDSM_X4(b0, b1, b2, b3, baddr);
                MMA16816(p[2*nq],   a0, a1, a2, a3, b0, b1);
                MMA16816(p[2*nq+1], a0, a1, a2, a3, b2, b3);
            }
        }
        #pragma unroll
        for (int ni = 0; ni < 8; ni++)
            #pragma unroll
            for (int q = 0; q < 4; q++) p[ni][q] *= scale;

        float t0 = -1e30f, t1 = -1e30f;
        #pragma unroll
        for (int ni = 0; ni < 8; ni++) {
            t0 = fmaxf(t0, fmaxf(p[ni][0], p[ni][1]));
            t1 = fmaxf(t1, fmaxf(p[ni][2], p[ni][3]));
        }
        t0 = fmaxf(t0, __shfl_xor_sync(0xffffffffu, t0, 1));
        t0 = fmaxf(t0, __shfl_xor_sync(0xffffffffu, t0, 2));
        t1 = fmaxf(t1, __shfl_xor_sync(0xffffffffu, t1, 1));
        t1 = fmaxf(t1, __shfl_xor_sync(0xffffffffu, t1, 2));
        float nm0 = fmaxf(m0, t0), nm1 = fmaxf(m1, t1);
        float es0 = expf(m0 - nm0), es1 = expf(m1 - nm1);
        float s0 = 0.f, s1 = 0.f;
        #pragma unroll
        for (int ni = 0; ni < 8; ni++) {
            p[ni][0] = expf(p[ni][0] - nm0);
            p[ni][1] = expf(p[ni][1] - nm0);
            p[ni][2] = expf(p[ni][2] - nm1);
            p[ni][3] = expf(p[ni][3] - nm1);
            s0 += p[ni][0] + p[ni][1];
            s1 += p[ni][2] + p[ni][3];
        }
        s0 += __shfl_xor_sync(0xffffffffu, s0, 1);
        s0 += __shfl_xor_sync(0xffffffffu, s0, 2);
        s1 += __shfl_xor_sync(0xffffffffu, s1, 1);
        s1 += __shfl_xor_sync(0xffffffffu, s1, 2);
        l0 = l0 * es0 + s0;
        l1 = l1 * es1 + s1;
        m0 = nm0; m1 = nm1;
        #pragma unroll
        for (int ni = 0; ni < 16; ni++) {
            oacc[ni][0] *= es0; oacc[ni][1] *= es0;
            oacc[ni][2] *= es1; oacc[ni][3] *= es1;
        }

        #pragma unroll
        for (int kk = 0; kk < 4; kk++) {
            uint32_t a0 = pack_h2(p[2*kk][0],   p[2*kk][1]);
            uint32_t a1 = pack_h2(p[2*kk][2],   p[2*kk][3]);
            uint32_t a2 = pack_h2(p[2*kk+1][0], p[2*kk+1][1]);
            uint32_t a3 = pack_h2(p[2*kk+1][2], p[2*kk+1][3]);
            int vrow = kk * 16 + v_krow;
            #pragma unroll
            for (int ng = 0; ng < 8; ng++) {
                int c16 = ng * 2 + v_c16h;
                uint32_t addr = bV + vrow * 256 + (uint32_t)((c16 ^ (vrow & 7)) << 4);
                uint32_t r0, r1, r2, r3;
                LDSM_X4_T(r0, r1, r2, r3, addr);
                MMA16816(oacc[2*ng],   a0, a1, a2, a3, r0, r2);
                MMA16816(oacc[2*ng+1], a0, a1, a2, a3, r1, r3);
            }
        }

        if (i + 2 < NCH) {
            __syncthreads();
            load_kv(buf, (i + 2) * 64);
            CP_COMMIT();
        }
    }

    float inv0 = 1.0f / l0, inv1 = 1.0f / l1;
    int gm0 = row0 + w * 16 + g;
    int gm1 = gm0 + 8;
    #pragma unroll
    for (int ni = 0; ni < 16; ni++) {
        int gn = ni * 8 + cq;
        if (gm0 < NQS)
            *(__half2*)(O + (size_t)gm0 * MMD + gn) = __floats2half2_rn(oacc[ni][0] * inv0, oacc[ni][1] * inv0);
        if (gm1 < NQS)
            *(__half2*)(O + (size_t)gm1 * MMD + gn) = __floats2half2_rn(oacc[ni][2] * inv1, oacc[ni][3] * inv1);
    }
}

// ---------------- launch ----------------
extern "C" void kernel_launch(void* const* d_in, const int* in_sizes, int n_in,
                              void* d_out, int out_size)
{
    const float* x      = (const float*)d_in[0];
    const float* noise  = (const float*)d_in[1];
    const float* W1     = (const float*)d_in[2];
    const float* b1     = (const float*)d_in[3];
    const float* W2     = (const float*)d_in[4];
    const float* b2     = (const float*)d_in[5];
    const float* query  = (const float*)d_in[6];
    const float* pos    = (const float*)d_in[7];
    const float* ln_q_g = (const float*)d_in[8];
    const float* ln_q_b = (const float*)d_in[9];
    const float* ln_kv_g= (const float*)d_in[10];
    const float* ln_kv_b= (const float*)d_in[11];
    const float* ipw    = (const float*)d_in[12];
    const float* ipb    = (const float*)d_in[13];
    const float* ow     = (const float*)d_in[14];
    const float* ob     = (const float*)d_in[15];
    const float* wg     = (const float*)d_in[16];
    const float* wn     = (const float*)d_in[17];
    float* out = (float*)d_out;

    float *gates, *b1p;
    __half *q16, *k16, *v16;
    __half *x16, *kv16, *kvp16, *qn16, *attn16, *w1p16, *h16, *ipw16, *owT16, *w116, *w216;
    cudaGetSymbolAddress((void**)&q16,    g_qp);
    cudaGetSymbolAddress((void**)&k16,    g_kp);
    cudaGetSymbolAddress((void**)&v16,    g_vp);
    cudaGetSymbolAddress((void**)&gates,  g_gates);
    cudaGetSymbolAddress((void**)&b1p,    g_b1p);
    cudaGetSymbolAddress((void**)&x16,    g_x16);
    cudaGetSymbolAddress((void**)&kv16,   g_kv16);
    cudaGetSymbolAddress((void**)&kvp16,  g_kvp16);
    cudaGetSymbolAddress((void**)&qn16,   g_qn16);
    cudaGetSymbolAddress((void**)&attn16, g_attn16);
    cudaGetSymbolAddress((void**)&w1p16,  g_w1p16);
    cudaGetSymbolAddress((void**)&h16,    g_h16);
    cudaGetSymbolAddress((void**)&ipw16,  g_ipw16);
    cudaGetSymbolAddress((void**)&owT16,  g_owT16);
    cudaGetSymbolAddress((void**)&w116,   g_w116);
    cudaGetSymbolAddress((void**)&w216,   g_w216);

    static cudaStream_t s1 = nullptr, s2 = nullptr;
    static cudaEvent_t evFork0 = nullptr, evGates = nullptr, evJoin = nullptr;
    static cudaEvent_t evQin = nullptr, evQdone = nullptr;
    static bool attr_done = false;
    if (!attr_done) {
        cudaFuncSetAttribute(hgemm<0>, cudaFuncAttributeMaxDynamicSharedMemorySize, SMEM_DYN);
        cudaFuncSetAttribute(hgemm<1>, cudaFuncAttributeMaxDynamicSharedMemorySize, SMEM_DYN);
        cudaFuncSetAttribute(hgemm<2>, cudaFuncAttributeMaxDynamicSharedMemorySize, SMEM_DYN);
        cudaFuncSetAttribute(hgemm<3>, cudaFuncAttributeMaxDynamicSharedMemorySize, SMEM_DYN);
        cudaFuncSetAttribute(hgemm<4>, cudaFuncAttributeMaxDynamicSharedMemorySize, SMEM_DYN);
        cudaFuncSetAttribute(flash_attn, cudaFuncAttributeMaxDynamicSharedMemorySize, FA_SMEM);
        cudaStreamCreateWithFlags(&s1, cudaStreamNonBlocking);
        cudaStreamCreateWithFlags(&s2, cudaStreamNonBlocking);
        cudaEventCreateWithFlags(&evFork0, cudaEventDisableTiming);
        cudaEventCreateWithFlags(&evGates, cudaEventDisableTiming);
        cudaEventCreateWithFlags(&evJoin, cudaEventDisableTiming);
        cudaEventCreateWithFlags(&evQin, cudaEventDisableTiming);
        cudaEventCreateWithFlags(&evQdone, cudaEventDisableTiming);
        attr_done = true;
    }

    // ---- side stream s1 (weights-only prologue; forked at t=0) ----
    cudaEventRecord(evFork0, 0);
    cudaStreamWaitEvent(s1, evFork0, 0);
    f2h_b_kernel<<<(N4_B + 255)/256, 256, 0, s1>>>(W1, w116, W2, w216);
    owT_kernel<<<dim3(32, 32), 256, 0, s1>>>(ow, owT16);
    // W1' = W1 @ ow  (folded weight for expert-1 FC1)
    hgemm<0><<<dim3(MMD/BN, HIDD/BM), 256, SMEM_DYN, s1>>>(w116, owT16, nullptr, w1p16, HIDD, MMD, MMD, nullptr, nullptr);
    b1p_kernel<<<HIDD, 128, 0, s1>>>(W1, b1, ob, b1p);

    // main: fused LN(x)+gating (+x16 emission)
    lnxg_kernel<<<ROWS, 256>>>(x, ln_kv_g, ln_kv_b, pos, wg, wn, noise, kv16, kvp16, x16, gates);
    cudaEventRecord(evGates, 0);

    // side s1: expert-0 FC1 (needs x16 + gates from lnxg, W1 from f2h_b)
    cudaStreamWaitEvent(s1, evGates, 0);
    hgemm<2><<<dim3(32, 72), 256, SMEM_DYN, s1>>>(x16, w116, nullptr, h16, ROWS, HIDD, MMD, b1, gates);
    cudaEventRecord(evJoin, s1);

    // main: prologue for attention
    lnq_kernel<<<NQS, 256>>>(query, ln_q_g, ln_q_b, pos, qn16);
    f2h_a_kernel<<<(N4_IPW + 255)/256, 256>>>(ipw, ipw16);
    cudaEventRecord(evQin, 0);

    // side s2: Q projection (small; overlap with K/V projections)
    cudaStreamWaitEvent(s2, evQin, 0);
    hgemm<1><<<dim3(8, 5), 256, SMEM_DYN, s2>>>(qn16, ipw16, nullptr, q16, NQS, MMD, MMD, ipb, nullptr);
    cudaEventRecord(evQdone, s2);

    // main: K/V projections
    hgemm<1><<<dim3(8, 72), 256, SMEM_DYN>>>(kvp16, ipw16 + MMD*MMD,   nullptr, k16, ROWS, MMD, MMD, ipb + MMD,   nullptr);
    hgemm<1><<<dim3(8, 72), 256, SMEM_DYN>>>(kv16,  ipw16 + 2*MMD*MMD, nullptr, v16, ROWS, MMD, MMD, ipb + 2*MMD, nullptr);

    cudaStreamWaitEvent(0, evQdone, 0);
    flash_attn<<<dim3(5, NBH), 256, FA_SMEM>>>(q16, k16, v16, attn16);

    // join: FC1(e1) uses folded weight W1' (outproj eliminated) and RMWs h16
    cudaStreamWaitEvent(0, evJoin, 0);
    hgemm<3><<<dim3(32, 72), 256, SMEM_DYN>>>(attn16, w1p16, nullptr, h16, ROWS, HIDD, MMD, b1p, gates);
    hgemm<4><<<dim3(32, 72), 256, SMEM_DYN>>>(h16,    w216,  out, nullptr, ROWS, HIDD, HIDD, b2, gates);
}

// round 15
// speedup vs baseline: 1.0440x; 1.0028x over previous
#include <cuda_runtime.h>
#include <cuda_fp16.h>
#include <math.h>
#include <cstdint>

// ---------------- problem constants ----------------
#define NQS   576
#define BATCH 16
#define MMD   1024
#define HIDD  4096
#define ROWS  (BATCH*NQS)        // 9216
#define HEADS 8
#define DH    128
#define NBH   (BATCH*HEADS)      // 128
#define HROWS (ROWS/2)           // 4608 (row-chunk for FC1e1/FC2 pipeline)

// ---------------- HMMA GEMM tiling (128x128, 256 thr, 2 CTA/SM) ----------------
#define BM 128
#define BN 128
#define BK 64
#define STAGES 3
#define STAGE_BYTES ((BM+BN)*128)                    // 32 KB
#define SMEM_DYN (STAGES*STAGE_BYTES + 2048)
#define FA_SMEM (96*1024 + 1024)

// ---------------- scratch (device globals) ----------------
__device__ __align__(16) float  g_qp [NQS*MMD];              // fp16 q
__device__ __align__(16) float  g_kp [ROWS*MMD];             // fp16 k
__device__ __align__(16) float  g_vp [ROWS*MMD];             // fp16 v
__device__ __align__(16) float  g_gates[ROWS*2];
__device__ __align__(16) float  g_b1p [HIDD];
__device__ __align__(16) __half g_x16   [ROWS*MMD];
__device__ __align__(16) __half g_kv16  [ROWS*MMD];
__device__ __align__(16) __half g_kvp16 [ROWS*MMD];
__device__ __align__(16) __half g_qn16  [NQS*MMD];
__device__ __align__(16) __half g_attn16[ROWS*MMD];
__device__ __align__(16) __half g_w1p16 [HIDD*MMD];          // W1 @ ow (folded)
__device__ __align__(16) __half g_h16   [(size_t)ROWS*HIDD];
__device__ __align__(16) __half g_ipw16 [3*MMD*MMD];
__device__ __align__(16) __half g_owT16 [MMD*MMD];           // ow transposed fp16
__device__ __align__(16) __half g_w116  [HIDD*MMD];
__device__ __align__(16) __half g_w216  [(size_t)HIDD*HIDD];

// ---------------- helpers ----------------
__device__ __forceinline__ uint32_t smem_to_u32(const void* p) {
    uint32_t a;
    asm("{ .reg .u64 t; cvta.to.shared.u64 t, %1; cvt.u32.u64 %0, t; }" : "=r"(a) : "l"(p));
    return a;
}
#define SWZ(o) ((o) ^ (((o) >> 3) & 0x70))

__device__ __forceinline__ void cp16(uint32_t dst, const void* src, uint32_t sz) {
    asm volatile("cp.async.cg.shared.global [%0], [%1], 16, %2;\n" :: "r"(dst), "l"(src), "r"(sz));
}
#define CP_COMMIT() asm volatile("cp.async.commit_group;\n")
#define CP_WAIT(n)  asm volatile("cp.async.wait_group %0;\n" :: "n"(n))

#define LDSM_X4(r0,r1,r2,r3,addr) \
    asm volatile("ldmatrix.sync.aligned.m8n8.x4.shared.b16 {%0,%1,%2,%3}, [%4];" \
        : "=r"(r0), "=r"(r1), "=r"(r2), "=r"(r3) : "r"(addr))
#define LDSM_X4_T(r0,r1,r2,r3,addr) \
    asm volatile("ldmatrix.sync.aligned.m8n8.x4.trans.shared.b16 {%0,%1,%2,%3}, [%4];" \
        : "=r"(r0), "=r"(r1), "=r"(r2), "=r"(r3) : "r"(addr))

#define MMA16816(c, a0,a1,a2,a3, b0,b1) \
    asm volatile("mma.sync.aligned.m16n8k16.row.col.f32.f16.f16.f32 " \
        "{%0,%1,%2,%3},{%4,%5,%6,%7},{%8,%9},{%0,%1,%2,%3};" \
        : "+f"((c)[0]), "+f"((c)[1]), "+f"((c)[2]), "+f"((c)[3]) \
        : "r"(a0), "r"(a1), "r"(a2), "r"(a3), "r"(b0), "r"(b1))

__device__ __forceinline__ float gelu_exact(float v) {
    return 0.5f * v * (1.0f + erff(v * 0.7071067811865476f));
}
__device__ __forceinline__ float softplusf_(float x) {
    return fmaxf(x, 0.0f) + log1pf(expf(-fabsf(x)));
}
__device__ __forceinline__ uint32_t pack_h2(float a, float b) {
    __half2 h = __floats2half2_rn(a, b);
    return *(uint32_t*)&h;
}

// ---------------- fp32 -> fp16 conversions ----------------
#define N4_IPW (3*MMD*MMD/4)
#define N4_W1  (HIDD*MMD/4)
#define N4_W2  (HIDD*HIDD/4)
#define N4_B   (N4_W1+N4_W2)

__global__ void __launch_bounds__(256) f2h_a_kernel(
    const float* __restrict__ ipw, __half* __restrict__ ipw16)
{
    int i = blockIdx.x * blockDim.x + threadIdx.x;
    if (i >= N4_IPW) return;
    float4 v = ((const float4*)ipw)[i];
    uint2 p;
    *((__half2*)&p.x) = __floats2half2_rn(v.x, v.y);
    *((__half2*)&p.y) = __floats2half2_rn(v.z, v.w);
    ((uint2*)ipw16)[i] = p;
}

__global__ void __launch_bounds__(256) f2h_b_kernel(
    const float* __restrict__ W1, __half* __restrict__ w116,
    const float* __restrict__ W2, __half* __restrict__ w216)
{
    int i = blockIdx.x * blockDim.x + threadIdx.x;
    if (i >= N4_B) return;
    const float* src; __half* dst;
    if (i < N4_W1) { src = W1; dst = w116; }
    else { i -= N4_W1; src = W2; dst = w216; }
    float4 v = ((const float4*)src)[i];
    uint2 p;
    *((__half2*)&p.x) = __floats2half2_rn(v.x, v.y);
    *((__half2*)&p.y) = __floats2half2_rn(v.z, v.w);
    ((uint2*)dst)[i] = p;
}

// side-stream: ow (fp32) -> owT (fp16, transposed)
__global__ void __launch_bounds__(256) owT_kernel(
    const float* __restrict__ ow, __half* __restrict__ owT)
{
    __shared__ float tile[32][33];
    const int bx = blockIdx.x * 32, by = blockIdx.y * 32;
    const int tx = threadIdx.x & 31, ty = threadIdx.x >> 5;
    #pragma unroll
    for (int r = 0; r < 32; r += 8)
        tile[ty + r][tx] = ow[(size_t)(by + ty + r) * MMD + bx + tx];
    __syncthreads();
    #pragma unroll
    for (int r = 0; r < 32; r += 8)
        owT[(size_t)(bx + ty + r) * MMD + by + tx] = __float2half_rn(tile[tx][ty + r]);
}

// side-stream: b1p[i] = b1[i] + sum_j W1[i][j] * ob[j]
__global__ void __launch_bounds__(128) b1p_kernel(
    const float* __restrict__ W1, const float* __restrict__ b1,
    const float* __restrict__ ob, float* __restrict__ b1p)
{
    const int i = blockIdx.x;
    float s = 0.f;
    for (int j = threadIdx.x; j < MMD; j += 128)
        s += W1[(size_t)i * MMD + j] * ob[j];
    __shared__ float red[4];
    #pragma unroll
    for (int o = 16; o; o >>= 1) s += __shfl_xor_sync(0xffffffffu, s, o);
    if ((threadIdx.x & 31) == 0) red[threadIdx.x >> 5] = s;
    __syncthreads();
    if (threadIdx.x == 0)
        b1p[i] = b1[i] + red[0] + red[1] + red[2] + red[3];
}

// ---------------- fused LN(x) + gating + x16 emission ----------------
__global__ void __launch_bounds__(256) lnxg_kernel(
    const float* __restrict__ x, const float* __restrict__ g,
    const float* __restrict__ b, const float* __restrict__ pos,
    const float* __restrict__ wg, const float* __restrict__ wn,
    const float* __restrict__ noise,
    __half* __restrict__ kv16, __half* __restrict__ kvp16,
    __half* __restrict__ x16, float* __restrict__ gates)
{
    const int row = blockIdx.x;
    const int prow = row % NQS;
    const int t = threadIdx.x;

    const float4 xv = *(const float4*)(x + (size_t)row * MMD + t * 4);
    float s  = xv.x + xv.y + xv.z + xv.w;
    float ss = xv.x*xv.x + xv.y*xv.y + xv.z*xv.z + xv.w*xv.w;

    float4 wg0 = *(const float4*)(wg + 8*t);
    float4 wg1 = *(const float4*)(wg + 8*t + 4);
    float4 wn0 = *(const float4*)(wn + 8*t);
    float4 wn1 = *(const float4*)(wn + 8*t + 4);
    float d0 = xv.x*wg0.x + xv.y*wg0.z + xv.z*wg1.x + xv.w*wg1.z;
    float d1 = xv.x*wg0.y + xv.y*wg0.w + xv.z*wg1.y + xv.w*wg1.w;
    float d2 = xv.x*wn0.x + xv.y*wn0.z + xv.z*wn1.x + xv.w*wn1.z;
    float d3 = xv.x*wn0.y + xv.y*wn0.w + xv.z*wn1.y + xv.w*wn1.w;

    uint2 ox;
    ox.x = pack_h2(xv.x, xv.y); ox.y = pack_h2(xv.z, xv.w);
    *(uint2*)(x16 + (size_t)row * MMD + t * 4) = ox;

    __shared__ float red[6][8];
    float vals[6] = {s, ss, d0, d1, d2, d3};
    #pragma unroll
    for (int j = 0; j < 6; j++)
        #pragma unroll
        for (int o = 16; o; o >>= 1)
            vals[j] += __shfl_xor_sync(0xffffffffu, vals[j], o);
    int wid = t >> 5, lid = t & 31;
    if (lid == 0)
        #pragma unroll
        for (int j = 0; j < 6; j++) red[j][wid] = vals[j];
    __syncthreads();

    float S = 0.f, SS = 0.f;
    #pragma unroll
    for (int w = 0; w < 8; w++) { S += red[0][w]; SS += red[1][w]; }
    float mu = S / MMD;
    float rstd = rsqrtf(SS / MMD - mu * mu + 1e-5f);

    float4 gv = *(const float4*)(g + t * 4);
    float4 bv = *(const float4*)(b + t * 4);
    float4 pv = *(const float4*)(pos + (size_t)prow * MMD + t * 4);
    float v0 = (xv.x - mu) * rstd * gv.x + bv.x;
    float v1 = (xv.y - mu) * rstd * gv.y + bv.y;
    float v2 = (xv.z - mu) * rstd * gv.z + bv.z;
    float v3 = (xv.w - mu) * rstd * gv.w + bv.w;
    uint2 o1, o2;
    o1.x = pack_h2(v0, v1); o1.y = pack_h2(v2, v3);
    o2.x = pack_h2(v0 + pv.x, v1 + pv.y); o2.y = pack_h2(v2 + pv.z, v3 + pv.w);
    *(uint2*)(kv16  + (size_t)row * MMD + t * 4) = o1;
    *(uint2*)(kvp16 + (size_t)row * MMD + t * 4) = o2;

    if (t == 0) {
        float td[4] = {0.f, 0.f, 0.f, 0.f};
        #pragma unroll
        for (int w = 0; w < 8; w++)
            #pragma unroll
            for (int j = 0; j < 4; j++) td[j] += red[2 + j][w];
        float sp0 = softplusf_(td[2]) + 0.01f;
        float sp1 = softplusf_(td[3]) + 0.01f;
        float l0 = td[0] + noise[2*row]   * sp0;
        float l1 = td[1] + noise[2*row+1] * sp1;
        float mx = fmaxf(l0, l1);
        float e0 = expf(l0 - mx), e1 = expf(l1 - mx);
        float is = 1.0f / (e0 + e1);
        float p0 = e0 * is, p1 = e1 * is;
        float inv = 1.0f / (p0 + p1 + 1e-6f);
        gates[2*row]   = p0 * inv;
        gates[2*row+1] = p1 * inv;
    }
}

// ---------------- LN(query) + pos -> fp16 ----------------
__global__ void __launch_bounds__(256) lnq_kernel(
    const float* __restrict__ q, const float* __restrict__ g,
    const float* __restrict__ b, const float* __restrict__ pos,
    __half* __restrict__ qn16)
{
    const int row = blockIdx.x;
    const int t = threadIdx.x;
    const float4 xv = *(const float4*)(q + (size_t)row * MMD + t * 4);
    float s  = xv.x + xv.y + xv.z + xv.w;
    float ss = xv.x*xv.x + xv.y*xv.y + xv.z*xv.z + xv.w*xv.w;
    __shared__ float red[2][8];
    #pragma unroll
    for (int o = 16; o; o >>= 1) {
        s  += __shfl_xor_sync(0xffffffffu, s,  o);
        ss += __shfl_xor_sync(0xffffffffu, ss, o);
    }
    int wid = t >> 5, lid = t & 31;
    if (lid == 0) { red[0][wid] = s; red[1][wid] = ss; }
    __syncthreads();
    float S = 0.f, SS = 0.f;
    #pragma unroll
    for (int w = 0; w < 8; w++) { S += red[0][w]; SS += red[1][w]; }
    float mu = S / MMD;
    float rstd = rsqrtf(SS / MMD - mu * mu + 1e-5f);
    float4 gv = *(const float4*)(g + t * 4);
    float4 bv = *(const float4*)(b + t * 4);
    float4 pv = *(const float4*)(pos + (size_t)row * MMD + t * 4);
    uint2 o;
    o.x = pack_h2((xv.x - mu) * rstd * gv.x + bv.x + pv.x,
                  (xv.y - mu) * rstd * gv.y + bv.y + pv.y);
    o.y = pack_h2((xv.z - mu) * rstd * gv.z + bv.z + pv.z,
                  (xv.w - mu) * rstd * gv.w + bv.w + pv.w);
    *(uint2*)(qn16 + (size_t)row * MMD + t * 4) = o;
}

// ---------------- fp16 HMMA GEMM 128x128 (256 thr): C = A @ B^T ----------------
// EPI: 0 = fp16 plain, 1 = fp16 +bias, 2 = fp16 = g0*gelu(v+bias),
//      3 = fp16 += g1*gelu(v+bias), 4 = fp32 = acc + (g0+g1)*bias
__device__ __forceinline__ void load_stage(
    uint32_t stg, const __half* __restrict__ A, const __half* __restrict__ B,
    int row0, int col0, int M, int K, int kt, int tid)
{
    uint32_t sA = stg;
    uint32_t sB = stg + BM * 128;
    #pragma unroll
    for (int t = 0; t < 4; t++) {
        int op = tid + t * 256;
        int row = op >> 3, c = op & 7;
        int gr = row0 + row;
        uint32_t sz = (gr < M) ? 16u : 0u;
        if (gr >= M) gr = M - 1;
        cp16(sA + SWZ(row * 128 + c * 16), A + (size_t)gr * K + kt + c * 8, sz);
    }
    #pragma unroll
    for (int t = 0; t < 4; t++) {
        int op = tid + t * 256;
        int row = op >> 3, c = op & 7;
        cp16(sB + SWZ(row * 128 + c * 16), B + (size_t)(col0 + row) * K + kt + c * 8, 16u);
    }
}

template<int EPI>
__global__ void __launch_bounds__(256) hgemm(
    const __half* __restrict__ A, const __half* __restrict__ B,
    float* __restrict__ Cf, __half* __restrict__ Ch,
    int M, int N, int K,
    const float* __restrict__ bias, const float* __restrict__ gates)
{
    extern __shared__ char smem[];
    uint32_t sb0 = (smem_to_u32(smem) + 1023) & ~1023u;
    const int tid = threadIdx.x;
    const int lane = tid & 31, warp = tid >> 5;
    const int wm = warp >> 1, wn = warp & 1;
    const int row0 = blockIdx.y * BM, col0 = blockIdx.x * BN;

    const int a_row = wm * 32 + (lane & 15);
    const int a_kh  = (lane >> 4) << 3;
    const int b_row = wn * 64 + ((lane >> 4) << 3) + (lane & 7);
    const int b_kh  = ((lane >> 3) & 1) << 3;

    float acc[2][8][4];
    #pragma unroll
    for (int mi = 0; mi < 2; mi++)
        #pragma unroll
        for (int ni = 0; ni < 8; ni++)
            #pragma unroll
            for (int q = 0; q < 4; q++) acc[mi][ni][q] = 0.f;

    const int nchunk = K / BK;

    #pragma unroll
    for (int j = 0; j < STAGES - 1; j++) {
        load_stage(sb0 + j * STAGE_BYTES, A, B, row0, col0, M, K, j * BK, tid);
        CP_COMMIT();
    }

    for (int i = 0; i < nchunk; i++) {
        if (i + 1 == nchunk) CP_WAIT(0); else CP_WAIT(STAGES - 2);
        __syncthreads();

        int j = i + STAGES - 1;
        if (j < nchunk) {
            load_stage(sb0 + (j % STAGES) * STAGE_BYTES, A, B, row0, col0, M, K, j * BK, tid);
            CP_COMMIT();
        }

        uint32_t stg = sb0 + (i % STAGES) * STAGE_BYTES;
        uint32_t sA = stg, sB = stg + BM * 128;

        #pragma unroll
        for (int k16 = 0; k16 < BK / 16; k16++) {
            uint32_t a[2][4], b[4][4];
            #pragma unroll
            for (int mi = 0; mi < 2; mi++) {
                uint32_t addr = sA + SWZ((uint32_t)((a_row + mi * 16) * 128 + (k16 * 16 + a_kh) * 2));
                LDSM_X4(a[mi][0], a[mi][1], a[mi][2], a[mi][3], addr);
            }
            #pragma unroll
            for (int nq = 0; nq < 4; nq++) {
                uint32_t addr = sB + SWZ((uint32_t)((b_row + nq * 16) * 128 + (k16 * 16 + b_kh) * 2));
                LDSM_X4(b[nq][0], b[nq][1], b[nq][2], b[nq][3], addr);
            }
            #pragma unroll
            for (int mi = 0; mi < 2; mi++)
                #pragma unroll
                for (int nq = 0; nq < 4; nq++) {
                    MMA16816(acc[mi][2*nq],   a[mi][0], a[mi][1], a[mi][2], a[mi][3], b[nq][0], b[nq][1]);
                    MMA16816(acc[mi][2*nq+1], a[mi][0], a[mi][1], a[mi][2], a[mi][3], b[nq][2], b[nq][3]);
                }
        }
    }

    // ---------------- epilogue ----------------
    const int g = lane >> 2;
    const int cpair = (lane & 3) * 2;
    #pragma unroll
    for (int mi = 0; mi < 2; mi++) {
        #pragma unroll
        for (int half = 0; half < 2; half++) {
            int gm = row0 + wm * 32 + mi * 16 + g + half * 8;
            if (gm >= M) continue;
            float gsel = 0.f;
            if (EPI == 2) gsel = gates[2 * gm];
            if (EPI == 3) gsel = gates[2 * gm + 1];
            if (EPI == 4) gsel = gates[2 * gm] + gates[2 * gm + 1];
            #pragma unroll
            for (int ni = 0; ni < 8; ni++) {
                int gn = col0 + wn * 64 + ni * 8 + cpair;
                float a0 = acc[mi][ni][half * 2 + 0];
                float a1 = acc[mi][ni][half * 2 + 1];
                size_t idx = (size_t)gm * N + gn;
                if (EPI == 0) {
                    *(__half2*)(Ch + idx) = __floats2half2_rn(a0, a1);
                } else if (EPI == 1) {
                    *(__half2*)(Ch + idx) = __floats2half2_rn(a0 + bias[gn], a1 + bias[gn + 1]);
                } else if (EPI == 2) {
                    *(__half2*)(Ch + idx) = __floats2half2_rn(
                        gsel * gelu_exact(a0 + bias[gn]), gsel * gelu_exact(a1 + bias[gn + 1]));
                } else if (EPI == 3) {
                    float2 o = __half22float2(*(__half2*)(Ch + idx));
                    *(__half2*)(Ch + idx) = __floats2half2_rn(
                        o.x + gsel * gelu_exact(a0 + bias[gn]),
                        o.y + gsel * gelu_exact(a1 + bias[gn + 1]));
                } else {
                    *(float2*)(Cf + idx) = make_float2(a0 + gsel * bias[gn], a1 + gsel * bias[gn + 1]);
                }
            }
        }
    }
}

// ---------------- fused flash attention ----------------
__global__ void __launch_bounds__(256) flash_attn(
    const __half* __restrict__ q16, const __half* __restrict__ k16,
    const __half* __restrict__ v16, __half* __restrict__ attn)
{
    extern __shared__ char smem[];
    uint32_t sb = (smem_to_u32(smem) + 1023) & ~1023u;
    uint32_t sQ = sb;
    uint32_t sK = sb + 32 * 1024;
    uint32_t sV = sb + 64 * 1024;
    const int tid = threadIdx.x;
    const int lane = tid & 31, w = tid >> 5;
    const int z = blockIdx.y, b = z >> 3, h = z & 7;
    const __half* Q = q16 + h * DH;
    const __half* K = k16 + (size_t)b * NQS * MMD + h * DH;
    const __half* V = v16 + (size_t)b * NQS * MMD + h * DH;
    __half* O = attn + (size_t)b * NQS * MMD + h * DH;
    const int row0 = blockIdx.x * 128;

    #pragma unroll
    for (int t = 0; t < 8; t++) {
        int op = tid + t * 256;
        int r = op >> 4, c16 = op & 15;
        int gr = row0 + r; if (gr >= NQS) gr = NQS - 1;
        cp16(sQ + r * 256 + (uint32_t)((c16 ^ (r & 7)) << 4), Q + (size_t)gr * MMD + c16 * 8, 16u);
    }
    auto load_kv = [&](int buf, int kt) {
        uint32_t dK = sK + buf * 16384, dV = sV + buf * 16384;
        #pragma unroll
        for (int t = 0; t < 4; t++) {
            int op = tid + t * 256;
            int r = op >> 4, c16 = op & 15;
            cp16(dK + r * 256 + (uint32_t)((c16 ^ (r & 7)) << 4), K + (size_t)(kt + r) * MMD + c16 * 8, 16u);
        }
        #pragma unroll
        for (int t = 0; t < 4; t++) {
            int op = tid + t * 256;
            int r = op >> 4, c16 = op & 15;
            cp16(dV + r * 256 + (uint32_t)((c16 ^ (r & 7)) << 4), V + (size_t)(kt + r) * MMD + c16 * 8, 16u);
        }
    };
    load_kv(0, 0);
    CP_COMMIT();
    load_kv(1, 64);
    CP_COMMIT();

    const int g = lane >> 2, cq = (lane & 3) * 2;
    const int qrow = w * 16 + (lane & 15);
    const int qh   = lane >> 4;
    const int brsel = ((lane >> 4) << 3) + (lane & 7);
    const int bh    = (lane >> 3) & 1;
    const int v_krow = (lane & 7) + ((lane & 16) >> 1);
    const int v_c16h = (lane >> 3) & 1;

    float oacc[16][4];
    #pragma unroll
    for (int i = 0; i < 16; i++)
        #pragma unroll
        for (int q = 0; q < 4; q++) oacc[i][q] = 0.f;
    float m0 = -1e30f, m1 = -1e30f, l0 = 0.f, l1 = 0.f;
    const float scale = 0.08838834764831845f;

    const int NCH = NQS / 64;   // 9
    for (int i = 0; i < NCH; i++) {
        if (i + 1 < NCH) CP_WAIT(1); else CP_WAIT(0);
        __syncthreads();
        const int buf = i & 1;
        uint32_t bK = sK + buf * 16384, bV = sV + buf * 16384;

        float p[8][4];
        #pragma unroll
        for (int ni = 0; ni < 8; ni++)
            #pragma unroll
            for (int q = 0; q < 4; q++) p[ni][q] = 0.f;
        #pragma unroll
        for (int k16i = 0; k16i < 8; k16i++) {
            uint32_t a0, a1, a2, a3;
            uint32_t qaddr = sQ + qrow * 256 + (uint32_t)(((2 * k16i + qh) ^ (qrow & 7)) << 4);
            LDSM_X4(a0, a1, a2, a3, qaddr);
            #pragma unroll
            for (int nq = 0; nq < 4; nq++) {
                int br = nq * 16 + brsel;
                uint32_t baddr = bK + br * 256 + (uint32_t)(((2 * k16i + bh) ^ (br & 7)) << 4);
                uint32_t b0, b1, b2, b3;
                LDSM_X4(b0, b1, b2, b3, baddr);
                MMA16816(p[2*nq],   a0, a1, a2, a3, b0, b1);
                MMA16816(p[2*nq+1], a0, a1, a2, a3, b2, b3);
            }
        }
        #pragma unroll
        for (int ni = 0; ni < 8; ni++)
            #pragma unroll
            for (int q = 0; q < 4; q++) p[ni][q] *= scale;

        float t0 = -1e30f, t1 = -1e30f;
        #pragma unroll
        for (int ni = 0; ni < 8; ni++) {
            t0 = fmaxf(t0, fmaxf(p[ni][0], p[ni][1]));
            t1 = fmaxf(t1, fmaxf(p[ni][2], p[ni][3]));
        }
        t0 = fmaxf(t0, __shfl_xor_sync(0xffffffffu, t0, 1));
        t0 = fmaxf(t0, __shfl_xor_sync(0xffffffffu, t0, 2));
        t1 = fmaxf(t1, __shfl_xor_sync(0xffffffffu, t1, 1));
        t1 = fmaxf(t1, __shfl_xor_sync(0xffffffffu, t1, 2));
        float nm0 = fmaxf(m0, t0), nm1 = fmaxf(m1, t1);
        float es0 = expf(m0 - nm0), es1 = expf(m1 - nm1);
        float s0 = 0.f, s1 = 0.f;
        #pragma unroll
        for (int ni = 0; ni < 8; ni++) {
            p[ni][0] = expf(p[ni][0] - nm0);
            p[ni][1] = expf(p[ni][1] - nm0);
            p[ni][2] = expf(p[ni][2] - nm1);
            p[ni][3] = expf(p[ni][3] - nm1);
            s0 += p[ni][0] + p[ni][1];
            s1 += p[ni][2] + p[ni][3];
        }
        s0 += __shfl_xor_sync(0xffffffffu, s0, 1);
        s0 += __shfl_xor_sync(0xffffffffu, s0, 2);
        s1 += __shfl_xor_sync(0xffffffffu, s1, 1);
        s1 += __shfl_xor_sync(0xffffffffu, s1, 2);
        l0 = l0 * es0 + s0;
        l1 = l1 * es1 + s1;
        m0 = nm0; m1 = nm1;
        #pragma unroll
        for (int ni = 0; ni < 16; ni++) {
            oacc[ni][0] *= es0; oacc[ni][1] *= es0;
            oacc[ni][2] *= es1; oacc[ni][3] *= es1;
        }

        #pragma unroll
        for (int kk = 0; kk < 4; kk++) {
            uint32_t a0 = pack_h2(p[2*kk][0],   p[2*kk][1]);
            uint32_t a1 = pack_h2(p[2*kk][2],   p[2*kk][3]);
            uint32_t a2 = pack_h2(p[2*kk+1][0], p[2*kk+1][1]);
            uint32_t a3 = pack_h2(p[2*kk+1][2], p[2*kk+1][3]);
            int vrow = kk * 16 + v_krow;
            #pragma unroll
            for (int ng = 0; ng < 8; ng++) {
                int c16 = ng * 2 + v_c16h;
                uint32_t addr = bV + vrow * 256 + (uint32_t)((c16 ^ (vrow & 7)) << 4);
                uint32_t r0, r1, r2, r3;
                LDSM_X4_T(r0, r1, r2, r3, addr);
                MMA16816(oacc[2*ng],   a0, a1, a2, a3, r0, r2);
                MMA16816(oacc[2*ng+1], a0, a1, a2, a3, r1, r3);
            }
        }

        if (i + 2 < NCH) {
            __syncthreads();
            load_kv(buf, (i + 2) * 64);
            CP_COMMIT();
        }
    }

    float inv0 = 1.0f / l0, inv1 = 1.0f / l1;
    int gm0 = row0 + w * 16 + g;
    int gm1 = gm0 + 8;
    #pragma unroll
    for (int ni = 0; ni < 16; ni++) {
        int gn = ni * 8 + cq;
        if (gm0 < NQS)
            *(__half2*)(O + (size_t)gm0 * MMD + gn) = __floats2half2_rn(oacc[ni][0] * inv0, oacc[ni][1] * inv0);
        if (gm1 < NQS)
            *(__half2*)(O + (size_t)gm1 * MMD + gn) = __floats2half2_rn(oacc[ni][2] * inv1, oacc[ni][3] * inv1);
    }
}

// ---------------- launch ----------------
extern "C" void kernel_launch(void* const* d_in, const int* in_sizes, int n_in,
                              void* d_out, int out_size)
{
    const float* x      = (const float*)d_in[0];
    const float* noise  = (const float*)d_in[1];
    const float* W1     = (const float*)d_in[2];
    const float* b1     = (const float*)d_in[3];
    const float* W2     = (const float*)d_in[4];
    const float* b2     = (const float*)d_in[5];
    const float* query  = (const float*)d_in[6];
    const float* pos    = (const float*)d_in[7];
    const float* ln_q_g = (const float*)d_in[8];
    const float* ln_q_b = (const float*)d_in[9];
    const float* ln_kv_g= (const float*)d_in[10];
    const float* ln_kv_b= (const float*)d_in[11];
    const float* ipw    = (const float*)d_in[12];
    const float* ipb    = (const float*)d_in[13];
    const float* ow     = (const float*)d_in[14];
    const float* ob     = (const float*)d_in[15];
    const float* wg     = (const float*)d_in[16];
    const float* wn     = (const float*)d_in[17];
    float* out = (float*)d_out;

    float *gates, *b1p;
    __half *q16, *k16, *v16;
    __half *x16, *kv16, *kvp16, *qn16, *attn16, *w1p16, *h16, *ipw16, *owT16, *w116, *w216;
    cudaGetSymbolAddress((void**)&q16,    g_qp);
    cudaGetSymbolAddress((void**)&k16,    g_kp);
    cudaGetSymbolAddress((void**)&v16,    g_vp);
    cudaGetSymbolAddress((void**)&gates,  g_gates);
    cudaGetSymbolAddress((void**)&b1p,    g_b1p);
    cudaGetSymbolAddress((void**)&x16,    g_x16);
    cudaGetSymbolAddress((void**)&kv16,   g_kv16);
    cudaGetSymbolAddress((void**)&kvp16,  g_kvp16);
    cudaGetSymbolAddress((void**)&qn16,   g_qn16);
    cudaGetSymbolAddress((void**)&attn16, g_attn16);
    cudaGetSymbolAddress((void**)&w1p16,  g_w1p16);
    cudaGetSymbolAddress((void**)&h16,    g_h16);
    cudaGetSymbolAddress((void**)&ipw16,  g_ipw16);
    cudaGetSymbolAddress((void**)&owT16,  g_owT16);
    cudaGetSymbolAddress((void**)&w116,   g_w116);
    cudaGetSymbolAddress((void**)&w216,   g_w216);

    static cudaStream_t s1 = nullptr, s2 = nullptr;
    static cudaEvent_t evFork0 = nullptr, evGates = nullptr, evJoin = nullptr;
    static cudaEvent_t evQin = nullptr, evQdone = nullptr;
    static cudaEvent_t evC0 = nullptr, evF0 = nullptr;
    static bool attr_done = false;
    if (!attr_done) {
        cudaFuncSetAttribute(hgemm<0>, cudaFuncAttributeMaxDynamicSharedMemorySize, SMEM_DYN);
        cudaFuncSetAttribute(hgemm<1>, cudaFuncAttributeMaxDynamicSharedMemorySize, SMEM_DYN);
        cudaFuncSetAttribute(hgemm<2>, cudaFuncAttributeMaxDynamicSharedMemorySize, SMEM_DYN);
        cudaFuncSetAttribute(hgemm<3>, cudaFuncAttributeMaxDynamicSharedMemorySize, SMEM_DYN);
        cudaFuncSetAttribute(hgemm<4>, cudaFuncAttributeMaxDynamicSharedMemorySize, SMEM_DYN);
        cudaFuncSetAttribute(flash_attn, cudaFuncAttributeMaxDynamicSharedMemorySize, FA_SMEM);
        cudaStreamCreateWithFlags(&s1, cudaStreamNonBlocking);
        cudaStreamCreateWithFlags(&s2, cudaStreamNonBlocking);
        cudaEventCreateWithFlags(&evFork0, cudaEventDisableTiming);
        cudaEventCreateWithFlags(&evGates, cudaEventDisableTiming);
        cudaEventCreateWithFlags(&evJoin, cudaEventDisableTiming);
        cudaEventCreateWithFlags(&evQin, cudaEventDisableTiming);
        cudaEventCreateWithFlags(&evQdone, cudaEventDisableTiming);
        cudaEventCreateWithFlags(&evC0, cudaEventDisableTiming);
        cudaEventCreateWithFlags(&evF0, cudaEventDisableTiming);
        attr_done = true;
    }

    // ---- side stream s1 (weights-only prologue; forked at t=0) ----
    cudaEventRecord(evFork0, 0);
    cudaStreamWaitEvent(s1, evFork0, 0);
    f2h_b_kernel<<<(N4_B + 255)/256, 256, 0, s1>>>(W1, w116, W2, w216);
    owT_kernel<<<dim3(32, 32), 256, 0, s1>>>(ow, owT16);
    hgemm<0><<<dim3(MMD/BN, HIDD/BM), 256, SMEM_DYN, s1>>>(w116, owT16, nullptr, w1p16, HIDD, MMD, MMD, nullptr, nullptr);
    b1p_kernel<<<HIDD, 128, 0, s1>>>(W1, b1, ob, b1p);

    // main: fused LN(x)+gating (+x16 emission)
    lnxg_kernel<<<ROWS, 256>>>(x, ln_kv_g, ln_kv_b, pos, wg, wn, noise, kv16, kvp16, x16, gates);
    cudaEventRecord(evGates, 0);

    // side s1: expert-0 FC1
    cudaStreamWaitEvent(s1, evGates, 0);
    hgemm<2><<<dim3(32, 72), 256, SMEM_DYN, s1>>>(x16, w116, nullptr, h16, ROWS, HIDD, MMD, b1, gates);
    cudaEventRecord(evJoin, s1);

    // main: prologue for attention
    lnq_kernel<<<NQS, 256>>>(query, ln_q_g, ln_q_b, pos, qn16);
    f2h_a_kernel<<<(N4_IPW + 255)/256, 256>>>(ipw, ipw16);
    cudaEventRecord(evQin, 0);

    // side s2: Q projection
    cudaStreamWaitEvent(s2, evQin, 0);
    hgemm<1><<<dim3(8, 5), 256, SMEM_DYN, s2>>>(qn16, ipw16, nullptr, q16, NQS, MMD, MMD, ipb, nullptr);
    cudaEventRecord(evQdone, s2);

    // main: K/V projections
    hgemm<1><<<dim3(8, 72), 256, SMEM_DYN>>>(kvp16, ipw16 + MMD*MMD,   nullptr, k16, ROWS, MMD, MMD, ipb + MMD,   nullptr);
    hgemm<1><<<dim3(8, 72), 256, SMEM_DYN>>>(kv16,  ipw16 + 2*MMD*MMD, nullptr, v16, ROWS, MMD, MMD, ipb + 2*MMD, nullptr);

    cudaStreamWaitEvent(0, evQdone, 0);
    flash_attn<<<dim3(5, NBH), 256, FA_SMEM>>>(q16, k16, v16, attn16);

    // ---- pipelined tail: FC1e1 (folded W1') and FC2 in two row-halves ----
    cudaStreamWaitEvent(0, evJoin, 0);
    // FC1e1 half 0 (rows 0..4607)
    hgemm<3><<<dim3(32, 36), 256, SMEM_DYN>>>(attn16, w1p16, nullptr, h16, HROWS, HIDD, MMD, b1p, gates);
    cudaEventRecord(evC0, 0);
    // FC2 half 0 on side stream (overlaps FC1e1 half 1)
    cudaStreamWaitEvent(s1, evC0, 0);
    hgemm<4><<<dim3(32, 36), 256, SMEM_DYN, s1>>>(h16, w216, out, nullptr, HROWS, HIDD, HIDD, b2, gates);
    cudaEventRecord(evF0, s1);
    // FC1e1 half 1 (rows 4608..9215) on main
    hgemm<3><<<dim3(32, 36), 256, SMEM_DYN>>>(attn16 + (size_t)HROWS * MMD, w1p16, nullptr,
                                              h16 + (size_t)HROWS * HIDD, HROWS, HIDD, MMD,
                                              b1p, gates + 2 * HROWS);
    // FC2 half 1 on main
    hgemm<4><<<dim3(32, 36), 256, SMEM_DYN>>>(h16 + (size_t)HROWS * HIDD, w216,
                                              out + (size_t)HROWS * HIDD, nullptr,
                                              HROWS, HIDD, HIDD, b2, gates + 2 * HROWS);
    // join side stream back into main so the capture graph is fully connected
    cudaStreamWaitEvent(0, evF0, 0);
}

// round 16
// speedup vs baseline: 1.0454x; 1.0013x over previous
#include <cuda_runtime.h>
#include <cuda_fp16.h>
#include <math.h>
#include <cstdint>

// ---------------- problem constants ----------------
#define NQS   576
#define BATCH 16
#define MMD   1024
#define HIDD  4096
#define ROWS  (BATCH*NQS)        // 9216
#define HEADS 8
#define DH    128
#define NBH   (BATCH*HEADS)      // 128
#define HROWS (ROWS/2)           // 4608 (row-chunk for FC1e1/FC2 pipeline)

// ---------------- HMMA GEMM tiling (128x128, 256 thr, 2 CTA/SM) ----------------
#define BM 128
#define BN 128
#define BK 64
#define STAGES 3
#define STAGE_BYTES ((BM+BN)*128)                    // 32 KB
#define SMEM_DYN (STAGES*STAGE_BYTES + 2048)
#define FA_SMEM (96*1024 + 1024)

// ---------------- scratch (device globals) ----------------
__device__ __align__(16) float  g_qp [NQS*MMD];              // fp16 q
__device__ __align__(16) float  g_kp [ROWS*MMD];             // fp16 k
__device__ __align__(16) float  g_vp [ROWS*MMD];             // fp16 v
__device__ __align__(16) float  g_gates[ROWS*2];
__device__ __align__(16) float  g_b1p [HIDD];
__device__ __align__(16) __half g_x16   [ROWS*MMD];
__device__ __align__(16) __half g_kv16  [ROWS*MMD];
__device__ __align__(16) __half g_kvp16 [ROWS*MMD];
__device__ __align__(16) __half g_qn16  [NQS*MMD];
__device__ __align__(16) __half g_attn16[ROWS*MMD];
__device__ __align__(16) __half g_w1p16 [HIDD*MMD];          // W1 @ ow (folded)
__device__ __align__(16) __half g_h16   [(size_t)ROWS*HIDD];
__device__ __align__(16) __half g_ipw16 [3*MMD*MMD];
__device__ __align__(16) __half g_owT16 [MMD*MMD];           // ow transposed fp16
__device__ __align__(16) __half g_w116  [HIDD*MMD];
__device__ __align__(16) __half g_w216  [(size_t)HIDD*HIDD];

// ---------------- helpers ----------------
__device__ __forceinline__ uint32_t smem_to_u32(const void* p) {
    uint32_t a;
    asm("{ .reg .u64 t; cvta.to.shared.u64 t, %1; cvt.u32.u64 %0, t; }" : "=r"(a) : "l"(p));
    return a;
}
#define SWZ(o) ((o) ^ (((o) >> 3) & 0x70))

__device__ __forceinline__ void cp16(uint32_t dst, const void* src, uint32_t sz) {
    asm volatile("cp.async.cg.shared.global [%0], [%1], 16, %2;\n" :: "r"(dst), "l"(src), "r"(sz));
}
#define CP_COMMIT() asm volatile("cp.async.commit_group;\n")
#define CP_WAIT(n)  asm volatile("cp.async.wait_group %0;\n" :: "n"(n))

#define LDSM_X4(r0,r1,r2,r3,addr) \
    asm volatile("ldmatrix.sync.aligned.m8n8.x4.shared.b16 {%0,%1,%2,%3}, [%4];" \
        : "=r"(r0), "=r"(r1), "=r"(r2), "=r"(r3) : "r"(addr))
#define LDSM_X4_T(r0,r1,r2,r3,addr) \
    asm volatile("ldmatrix.sync.aligned.m8n8.x4.trans.shared.b16 {%0,%1,%2,%3}, [%4];" \
        : "=r"(r0), "=r"(r1), "=r"(r2), "=r"(r3) : "r"(addr))

#define MMA16816(c, a0,a1,a2,a3, b0,b1) \
    asm volatile("mma.sync.aligned.m16n8k16.row.col.f32.f16.f16.f32 " \
        "{%0,%1,%2,%3},{%4,%5,%6,%7},{%8,%9},{%0,%1,%2,%3};" \
        : "+f"((c)[0]), "+f"((c)[1]), "+f"((c)[2]), "+f"((c)[3]) \
        : "r"(a0), "r"(a1), "r"(a2), "r"(a3), "r"(b0), "r"(b1))

__device__ __forceinline__ float gelu_exact(float v) {
    return 0.5f * v * (1.0f + erff(v * 0.7071067811865476f));
}
__device__ __forceinline__ float softplusf_(float x) {
    return fmaxf(x, 0.0f) + log1pf(expf(-fabsf(x)));
}
__device__ __forceinline__ uint32_t pack_h2(float a, float b) {
    __half2 h = __floats2half2_rn(a, b);
    return *(uint32_t*)&h;
}

// ---------------- fp32 -> fp16 conversions ----------------
#define N4_IPW (3*MMD*MMD/4)
#define N4_W1  (HIDD*MMD/4)
#define N4_W2  (HIDD*HIDD/4)
#define N4_B   (N4_W1+N4_W2)

__global__ void __launch_bounds__(256) f2h_a_kernel(
    const float* __restrict__ ipw, __half* __restrict__ ipw16)
{
    int i = blockIdx.x * blockDim.x + threadIdx.x;
    if (i >= N4_IPW) return;
    float4 v = ((const float4*)ipw)[i];
    uint2 p;
    *((__half2*)&p.x) = __floats2half2_rn(v.x, v.y);
    *((__half2*)&p.y) = __floats2half2_rn(v.z, v.w);
    ((uint2*)ipw16)[i] = p;
}

__global__ void __launch_bounds__(256) f2h_b_kernel(
    const float* __restrict__ W1, __half* __restrict__ w116,
    const float* __restrict__ W2, __half* __restrict__ w216)
{
    int i = blockIdx.x * blockDim.x + threadIdx.x;
    if (i >= N4_B) return;
    const float* src; __half* dst;
    if (i < N4_W1) { src = W1; dst = w116; }
    else { i -= N4_W1; src = W2; dst = w216; }
    float4 v = ((const float4*)src)[i];
    uint2 p;
    *((__half2*)&p.x) = __floats2half2_rn(v.x, v.y);
    *((__half2*)&p.y) = __floats2half2_rn(v.z, v.w);
    ((uint2*)dst)[i] = p;
}

// side-stream: ow (fp32) -> owT (fp16, transposed)
__global__ void __launch_bounds__(256) owT_kernel(
    const float* __restrict__ ow, __half* __restrict__ owT)
{
    __shared__ float tile[32][33];
    const int bx = blockIdx.x * 32, by = blockIdx.y * 32;
    const int tx = threadIdx.x & 31, ty = threadIdx.x >> 5;
    #pragma unroll
    for (int r = 0; r < 32; r += 8)
        tile[ty + r][tx] = ow[(size_t)(by + ty + r) * MMD + bx + tx];
    __syncthreads();
    #pragma unroll
    for (int r = 0; r < 32; r += 8)
        owT[(size_t)(bx + ty + r) * MMD + by + tx] = __float2half_rn(tile[tx][ty + r]);
}

// side-stream: b1p[i] = b1[i] + sum_j W1[i][j] * ob[j]
__global__ void __launch_bounds__(128) b1p_kernel(
    const float* __restrict__ W1, const float* __restrict__ b1,
    const float* __restrict__ ob, float* __restrict__ b1p)
{
    const int i = blockIdx.x;
    float s = 0.f;
    for (int j = threadIdx.x; j < MMD; j += 128)
        s += W1[(size_t)i * MMD + j] * ob[j];
    __shared__ float red[4];
    #pragma unroll
    for (int o = 16; o; o >>= 1) s += __shfl_xor_sync(0xffffffffu, s, o);
    if ((threadIdx.x & 31) == 0) red[threadIdx.x >> 5] = s;
    __syncthreads();
    if (threadIdx.x == 0)
        b1p[i] = b1[i] + red[0] + red[1] + red[2] + red[3];
}

// ---------------- fused LN(x) + gating + x16 emission ----------------
__global__ void __launch_bounds__(256) lnxg_kernel(
    const float* __restrict__ x, const float* __restrict__ g,
    const float* __restrict__ b, const float* __restrict__ pos,
    const float* __restrict__ wg, const float* __restrict__ wn,
    const float* __restrict__ noise,
    __half* __restrict__ kv16, __half* __restrict__ kvp16,
    __half* __restrict__ x16, float* __restrict__ gates)
{
    const int row = blockIdx.x;
    const int prow = row % NQS;
    const int t = threadIdx.x;

    const float4 xv = *(const float4*)(x + (size_t)row * MMD + t * 4);
    float s  = xv.x + xv.y + xv.z + xv.w;
    float ss = xv.x*xv.x + xv.y*xv.y + xv.z*xv.z + xv.w*xv.w;

    float4 wg0 = *(const float4*)(wg + 8*t);
    float4 wg1 = *(const float4*)(wg + 8*t + 4);
    float4 wn0 = *(const float4*)(wn + 8*t);
    float4 wn1 = *(const float4*)(wn + 8*t + 4);
    float d0 = xv.x*wg0.x + xv.y*wg0.z + xv.z*wg1.x + xv.w*wg1.z;
    float d1 = xv.x*wg0.y + xv.y*wg0.w + xv.z*wg1.y + xv.w*wg1.w;
    float d2 = xv.x*wn0.x + xv.y*wn0.z + xv.z*wn1.x + xv.w*wn1.z;
    float d3 = xv.x*wn0.y + xv.y*wn0.w + xv.z*wn1.y + xv.w*wn1.w;

    uint2 ox;
    ox.x = pack_h2(xv.x, xv.y); ox.y = pack_h2(xv.z, xv.w);
    *(uint2*)(x16 + (size_t)row * MMD + t * 4) = ox;

    __shared__ float red[6][8];
    float vals[6] = {s, ss, d0, d1, d2, d3};
    #pragma unroll
    for (int j = 0; j < 6; j++)
        #pragma unroll
        for (int o = 16; o; o >>= 1)
            vals[j] += __shfl_xor_sync(0xffffffffu, vals[j], o);
    int wid = t >> 5, lid = t & 31;
    if (lid == 0)
        #pragma unroll
        for (int j = 0; j < 6; j++) red[j][wid] = vals[j];
    __syncthreads();

    float S = 0.f, SS = 0.f;
    #pragma unroll
    for (int w = 0; w < 8; w++) { S += red[0][w]; SS += red[1][w]; }
    float mu = S / MMD;
    float rstd = rsqrtf(SS / MMD - mu * mu + 1e-5f);

    float4 gv = *(const float4*)(g + t * 4);
    float4 bv = *(const float4*)(b + t * 4);
    float4 pv = *(const float4*)(pos + (size_t)prow * MMD + t * 4);
    float v0 = (xv.x - mu) * rstd * gv.x + bv.x;
    float v1 = (xv.y - mu) * rstd * gv.y + bv.y;
    float v2 = (xv.z - mu) * rstd * gv.z + bv.z;
    float v3 = (xv.w - mu) * rstd * gv.w + bv.w;
    uint2 o1, o2;
    o1.x = pack_h2(v0, v1); o1.y = pack_h2(v2, v3);
    o2.x = pack_h2(v0 + pv.x, v1 + pv.y); o2.y = pack_h2(v2 + pv.z, v3 + pv.w);
    *(uint2*)(kv16  + (size_t)row * MMD + t * 4) = o1;
    *(uint2*)(kvp16 + (size_t)row * MMD + t * 4) = o2;

    if (t == 0) {
        float td[4] = {0.f, 0.f, 0.f, 0.f};
        #pragma unroll
        for (int w = 0; w < 8; w++)
            #pragma unroll
            for (int j = 0; j < 4; j++) td[j] += red[2 + j][w];
        float sp0 = softplusf_(td[2]) + 0.01f;
        float sp1 = softplusf_(td[3]) + 0.01f;
        float l0 = td[0] + noise[2*row]   * sp0;
        float l1 = td[1] + noise[2*row+1] * sp1;
        float mx = fmaxf(l0, l1);
        float e0 = expf(l0 - mx), e1 = expf(l1 - mx);
        float is = 1.0f / (e0 + e1);
        float p0 = e0 * is, p1 = e1 * is;
        float inv = 1.0f / (p0 + p1 + 1e-6f);
        gates[2*row]   = p0 * inv;
        gates[2*row+1] = p1 * inv;
    }
}

// ---------------- LN(query) + pos -> fp16 ----------------
__global__ void __launch_bounds__(256) lnq_kernel(
    const float* __restrict__ q, const float* __restrict__ g,
    const float* __restrict__ b, const float* __restrict__ pos,
    __half* __restrict__ qn16)
{
    const int row = blockIdx.x;
    const int t = threadIdx.x;
    const float4 xv = *(const float4*)(q + (size_t)row * MMD + t * 4);
    float s  = xv.x + xv.y + xv.z + xv.w;
    float ss = xv.x*xv.x + xv.y*xv.y + xv.z*xv.z + xv.w*xv.w;
    __shared__ float red[2][8];
    #pragma unroll
    for (int o = 16; o; o >>= 1) {
        s  += __shfl_xor_sync(0xffffffffu, s,  o);
        ss += __shfl_xor_sync(0xffffffffu, ss, o);
    }
    int wid = t >> 5, lid = t & 31;
    if (lid == 0) { red[0][wid] = s; red[1][wid] = ss; }
    __syncthreads();
    float S = 0.f, SS = 0.f;
    #pragma unroll
    for (int w = 0; w < 8; w++) { S += red[0][w]; SS += red[1][w]; }
    float mu = S / MMD;
    float rstd = rsqrtf(SS / MMD - mu * mu + 1e-5f);
    float4 gv = *(const float4*)(g + t * 4);
    float4 bv = *(const float4*)(b + t * 4);
    float4 pv = *(const float4*)(pos + (size_t)row * MMD + t * 4);
    uint2 o;
    o.x = pack_h2((xv.x - mu) * rstd * gv.x + bv.x + pv.x,
                  (xv.y - mu) * rstd * gv.y + bv.y + pv.y);
    o.y = pack_h2((xv.z - mu) * rstd * gv.z + bv.z + pv.z,
                  (xv.w - mu) * rstd * gv.w + bv.w + pv.w);
    *(uint2*)(qn16 + (size_t)row * MMD + t * 4) = o;
}

// ---------------- fp16 HMMA GEMM 128x128 (256 thr): C = A @ B^T ----------------
// EPI: 0 = fp16 plain, 1 = fp16 +bias, 2 = fp16 = g0*gelu(v+bias),
//      3 = fp16 += g1*gelu(v+bias), 4 = fp32 = acc + (g0+g1)*bias
__device__ __forceinline__ void load_stage(
    uint32_t stg, const __half* __restrict__ A, const __half* __restrict__ B,
    int row0, int col0, int M, int K, int kt, int tid)
{
    uint32_t sA = stg;
    uint32_t sB = stg + BM * 128;
    #pragma unroll
    for (int t = 0; t < 4; t++) {
        int op = tid + t * 256;
        int row = op >> 3, c = op & 7;
        int gr = row0 + row;
        uint32_t sz = (gr < M) ? 16u : 0u;
        if (gr >= M) gr = M - 1;
        cp16(sA + SWZ(row * 128 + c * 16), A + (size_t)gr * K + kt + c * 8, sz);
    }
    #pragma unroll
    for (int t = 0; t < 4; t++) {
        int op = tid + t * 256;
        int row = op >> 3, c = op & 7;
        cp16(sB + SWZ(row * 128 + c * 16), B + (size_t)(col0 + row) * K + kt + c * 8, 16u);
    }
}

template<int EPI>
__global__ void __launch_bounds__(256) hgemm(
    const __half* __restrict__ A, const __half* __restrict__ B,
    float* __restrict__ Cf, __half* __restrict__ Ch,
    int M, int N, int K,
    const float* __restrict__ bias, const float* __restrict__ gates)
{
    extern __shared__ char smem[];
    uint32_t sb0 = (smem_to_u32(smem) + 1023) & ~1023u;
    const int tid = threadIdx.x;
    const int lane = tid & 31, warp = tid >> 5;
    const int wm = warp >> 1, wn = warp & 1;
    const int row0 = blockIdx.y * BM, col0 = blockIdx.x * BN;

    const int a_row = wm * 32 + (lane & 15);
    const int a_kh  = (lane >> 4) << 3;
    const int b_row = wn * 64 + ((lane >> 4) << 3) + (lane & 7);
    const int b_kh  = ((lane >> 3) & 1) << 3;

    float acc[2][8][4];
    #pragma unroll
    for (int mi = 0; mi < 2; mi++)
        #pragma unroll
        for (int ni = 0; ni < 8; ni++)
            #pragma unroll
            for (int q = 0; q < 4; q++) acc[mi][ni][q] = 0.f;

    const int nchunk = K / BK;

    #pragma unroll
    for (int j = 0; j < STAGES - 1; j++) {
        load_stage(sb0 + j * STAGE_BYTES, A, B, row0, col0, M, K, j * BK, tid);
        CP_COMMIT();
    }

    for (int i = 0; i < nchunk; i++) {
        if (i + 1 == nchunk) CP_WAIT(0); else CP_WAIT(STAGES - 2);
        __syncthreads();

        int j = i + STAGES - 1;
        if (j < nchunk) {
            load_stage(sb0 + (j % STAGES) * STAGE_BYTES, A, B, row0, col0, M, K, j * BK, tid);
            CP_COMMIT();
        }

        uint32_t stg = sb0 + (i % STAGES) * STAGE_BYTES;
        uint32_t sA = stg, sB = stg + BM * 128;

        #pragma unroll
        for (int k16 = 0; k16 < BK / 16; k16++) {
            uint32_t a[2][4], b[4][4];
            #pragma unroll
            for (int mi = 0; mi < 2; mi++) {
                uint32_t addr = sA + SWZ((uint32_t)((a_row + mi * 16) * 128 + (k16 * 16 + a_kh) * 2));
                LDSM_X4(a[mi][0], a[mi][1], a[mi][2], a[mi][3], addr);
            }
            #pragma unroll
            for (int nq = 0; nq < 4; nq++) {
                uint32_t addr = sB + SWZ((uint32_t)((b_row + nq * 16) * 128 + (k16 * 16 + b_kh) * 2));
                LDSM_X4(b[nq][0], b[nq][1], b[nq][2], b[nq][3], addr);
            }
            #pragma unroll
            for (int mi = 0; mi < 2; mi++)
                #pragma unroll
                for (int nq = 0; nq < 4; nq++) {
                    MMA16816(acc[mi][2*nq],   a[mi][0], a[mi][1], a[mi][2], a[mi][3], b[nq][0], b[nq][1]);
                    MMA16816(acc[mi][2*nq+1], a[mi][0], a[mi][1], a[mi][2], a[mi][3], b[nq][2], b[nq][3]);
                }
        }
    }

    // ---------------- epilogue ----------------
    const int g = lane >> 2;
    const int cpair = (lane & 3) * 2;
    #pragma unroll
    for (int mi = 0; mi < 2; mi++) {
        #pragma unroll
        for (int half = 0; half < 2; half++) {
            int gm = row0 + wm * 32 + mi * 16 + g + half * 8;
            if (gm >= M) continue;
            float gsel = 0.f;
            if (EPI == 2) gsel = gates[2 * gm];
            if (EPI == 3) gsel = gates[2 * gm + 1];
            if (EPI == 4) gsel = gates[2 * gm] + gates[2 * gm + 1];
            #pragma unroll
            for (int ni = 0; ni < 8; ni++) {
                int gn = col0 + wn * 64 + ni * 8 + cpair;
                float a0 = acc[mi][ni][half * 2 + 0];
                float a1 = acc[mi][ni][half * 2 + 1];
                size_t idx = (size_t)gm * N + gn;
                if (EPI == 0) {
                    *(__half2*)(Ch + idx) = __floats2half2_rn(a0, a1);
                } else if (EPI == 1) {
                    *(__half2*)(Ch + idx) = __floats2half2_rn(a0 + bias[gn], a1 + bias[gn + 1]);
                } else if (EPI == 2) {
                    *(__half2*)(Ch + idx) = __floats2half2_rn(
                        gsel * gelu_exact(a0 + bias[gn]), gsel * gelu_exact(a1 + bias[gn + 1]));
                } else if (EPI == 3) {
                    float2 o = __half22float2(*(__half2*)(Ch + idx));
                    *(__half2*)(Ch + idx) = __floats2half2_rn(
                        o.x + gsel * gelu_exact(a0 + bias[gn]),
                        o.y + gsel * gelu_exact(a1 + bias[gn + 1]));
                } else {
                    *(float2*)(Cf + idx) = make_float2(a0 + gsel * bias[gn], a1 + gsel * bias[gn + 1]);
                }
            }
        }
    }
}

// ---------------- fused flash attention ----------------
__global__ void __launch_bounds__(256) flash_attn(
    const __half* __restrict__ q16, const __half* __restrict__ k16,
    const __half* __restrict__ v16, __half* __restrict__ attn)
{
    extern __shared__ char smem[];
    uint32_t sb = (smem_to_u32(smem) + 1023) & ~1023u;
    uint32_t sQ = sb;
    uint32_t sK = sb + 32 * 1024;
    uint32_t sV = sb + 64 * 1024;
    const int tid = threadIdx.x;
    const int lane = tid & 31, w = tid >> 5;
    const int z = blockIdx.y, b = z >> 3, h = z & 7;
    const __half* Q = q16 + h * DH;
    const __half* K = k16 + (size_t)b * NQS * MMD + h * DH;
    const __half* V = v16 + (size_t)b * NQS * MMD + h * DH;
    __half* O = attn + (size_t)b * NQS * MMD + h * DH;
    const int row0 = blockIdx.x * 128;

    #pragma unroll
    for (int t = 0; t < 8; t++) {
        int op = tid + t * 256;
        int r = op >> 4, c16 = op & 15;
        int gr = row0 + r; if (gr >= NQS) gr = NQS - 1;
        cp16(sQ + r * 256 + (uint32_t)((c16 ^ (r & 7)) << 4), Q + (size_t)gr * MMD + c16 * 8, 16u);
    }
    auto load_kv = [&](int buf, int kt) {
        uint32_t dK = sK + buf * 16384, dV = sV + buf * 16384;
        #pragma unroll
        for (int t = 0; t < 4; t++) {
            int op = tid + t * 256;
            int r = op >> 4, c16 = op & 15;
            cp16(dK + r * 256 + (uint32_t)((c16 ^ (r & 7)) << 4), K + (size_t)(kt + r) * MMD + c16 * 8, 16u);
        }
        #pragma unroll
        for (int t = 0; t < 4; t++) {
            int op = tid + t * 256;
            int r = op >> 4, c16 = op & 15;
            cp16(dV + r * 256 + (uint32_t)((c16 ^ (r & 7)) << 4), V + (size_t)(kt + r) * MMD + c16 * 8, 16u);
        }
    };
    load_kv(0, 0);
    CP_COMMIT();
    load_kv(1, 64);
    CP_COMMIT();

    const int g = lane >> 2, cq = (lane & 3) * 2;
    const int qrow = w * 16 + (lane & 15);
    const int qh   = lane >> 4;
    const int brsel = ((lane >> 4) << 3) + (lane & 7);
    const int bh    = (lane >> 3) & 1;
    const int v_krow = (lane & 7) + ((lane & 16) >> 1);
    const int v_c16h = (lane >> 3) & 1;

    float oacc[16][4];
    #pragma unroll
    for (int i = 0; i < 16; i++)
        #pragma unroll
        for (int q = 0; q < 4; q++) oacc[i][q] = 0.f;
    float m0 = -1e30f, m1 = -1e30f, l0 = 0.f, l1 = 0.f;
    const float scale = 0.08838834764831845f;

    const int NCH = NQS / 64;   // 9
    for (int i = 0; i < NCH; i++) {
        if (i + 1 < NCH) CP_WAIT(1); else CP_WAIT(0);
        __syncthreads();
        const int buf = i & 1;
        uint32_t bK = sK + buf * 16384, bV = sV + buf * 16384;

        float p[8][4];
        #pragma unroll
        for (int ni = 0; ni < 8; ni++)
            #pragma unroll
            for (int q = 0; q < 4; q++) p[ni][q] = 0.f;
        #pragma unroll
        for (int k16i = 0; k16i < 8; k16i++) {
            uint32_t a0, a1, a2, a3;
            uint32_t qaddr = sQ + qrow * 256 + (uint32_t)(((2 * k16i + qh) ^ (qrow & 7)) << 4);
            LDSM_X4(a0, a1, a2, a3, qaddr);
            #pragma unroll
            for (int nq = 0; nq < 4; nq++) {
                int br = nq * 16 + brsel;
                uint32_t baddr = bK + br * 256 + (uint32_t)(((2 * k16i + bh) ^ (br & 7)) << 4);
                uint32_t b0, b1, b2, b3;
                LDSM_X4(b0, b1, b2, b3, baddr);
                MMA16816(p[2*nq],   a0, a1, a2, a3, b0, b1);
                MMA16816(p[2*nq+1], a0, a1, a2, a3, b2, b3);
            }
        }
        #pragma unroll
        for (int ni = 0; ni < 8; ni++)
            #pragma unroll
            for (int q = 0; q < 4; q++) p[ni][q] *= scale;

        float t0 = -1e30f, t1 = -1e30f;
        #pragma unroll
        for (int ni = 0; ni < 8; ni++) {
            t0 = fmaxf(t0, fmaxf(p[ni][0], p[ni][1]));
            t1 = fmaxf(t1, fmaxf(p[ni][2], p[ni][3]));
        }
        t0 = fmaxf(t0, __shfl_xor_sync(0xffffffffu, t0, 1));
        t0 = fmaxf(t0, __shfl_xor_sync(0xffffffffu, t0, 2));
        t1 = fmaxf(t1, __shfl_xor_sync(0xffffffffu, t1, 1));
        t1 = fmaxf(t1, __shfl_xor_sync(0xffffffffu, t1, 2));
        float nm0 = fmaxf(m0, t0), nm1 = fmaxf(m1, t1);
        float es0 = expf(m0 - nm0), es1 = expf(m1 - nm1);
        float s0 = 0.f, s1 = 0.f;
        #pragma unroll
        for (int ni = 0; ni < 8; ni++) {
            p[ni][0] = expf(p[ni][0] - nm0);
            p[ni][1] = expf(p[ni][1] - nm0);
            p[ni][2] = expf(p[ni][2] - nm1);
            p[ni][3] = expf(p[ni][3] - nm1);
            s0 += p[ni][0] + p[ni][1];
            s1 += p[ni][2] + p[ni][3];
        }
        s0 += __shfl_xor_sync(0xffffffffu, s0, 1);
        s0 += __shfl_xor_sync(0xffffffffu, s0, 2);
        s1 += __shfl_xor_sync(0xffffffffu, s1, 1);
        s1 += __shfl_xor_sync(0xffffffffu, s1, 2);
        l0 = l0 * es0 + s0;
        l1 = l1 * es1 + s1;
        m0 = nm0; m1 = nm1;
        #pragma unroll
        for (int ni = 0; ni < 16; ni++) {
            oacc[ni][0] *= es0; oacc[ni][1] *= es0;
            oacc[ni][2] *= es1; oacc[ni][3] *= es1;
        }

        #pragma unroll
        for (int kk = 0; kk < 4; kk++) {
            uint32_t a0 = pack_h2(p[2*kk][0],   p[2*kk][1]);
            uint32_t a1 = pack_h2(p[2*kk][2],   p[2*kk][3]);
            uint32_t a2 = pack_h2(p[2*kk+1][0], p[2*kk+1][1]);
            uint32_t a3 = pack_h2(p[2*kk+1][2], p[2*kk+1][3]);
            int vrow = kk * 16 + v_krow;
            #pragma unroll
            for (int ng = 0; ng < 8; ng++) {
                int c16 = ng * 2 + v_c16h;
                uint32_t addr = bV + vrow * 256 + (uint32_t)((c16 ^ (vrow & 7)) << 4);
                uint32_t r0, r1, r2, r3;
                LDSM_X4_T(r0, r1, r2, r3, addr);
                MMA16816(oacc[2*ng],   a0, a1, a2, a3, r0, r2);
                MMA16816(oacc[2*ng+1], a0, a1, a2, a3, r1, r3);
            }
        }

        if (i + 2 < NCH) {
            __syncthreads();
            load_kv(buf, (i + 2) * 64);
            CP_COMMIT();
        }
    }

    float inv0 = 1.0f / l0, inv1 = 1.0f / l1;
    int gm0 = row0 + w * 16 + g;
    int gm1 = gm0 + 8;
    #pragma unroll
    for (int ni = 0; ni < 16; ni++) {
        int gn = ni * 8 + cq;
        if (gm0 < NQS)
            *(__half2*)(O + (size_t)gm0 * MMD + gn) = __floats2half2_rn(oacc[ni][0] * inv0, oacc[ni][1] * inv0);
        if (gm1 < NQS)
            *(__half2*)(O + (size_t)gm1 * MMD + gn) = __floats2half2_rn(oacc[ni][2] * inv1, oacc[ni][3] * inv1);
    }
}

// ---------------- launch ----------------
extern "C" void kernel_launch(void* const* d_in, const int* in_sizes, int n_in,
                              void* d_out, int out_size)
{
    const float* x      = (const float*)d_in[0];
    const float* noise  = (const float*)d_in[1];
    const float* W1     = (const float*)d_in[2];
    const float* b1     = (const float*)d_in[3];
    const float* W2     = (const float*)d_in[4];
    const float* b2     = (const float*)d_in[5];
    const float* query  = (const float*)d_in[6];
    const float* pos    = (const float*)d_in[7];
    const float* ln_q_g = (const float*)d_in[8];
    const float* ln_q_b = (const float*)d_in[9];
    const float* ln_kv_g= (const float*)d_in[10];
    const float* ln_kv_b= (const float*)d_in[11];
    const float* ipw    = (const float*)d_in[12];
    const float* ipb    = (const float*)d_in[13];
    const float* ow     = (const float*)d_in[14];
    const float* ob     = (const float*)d_in[15];
    const float* wg     = (const float*)d_in[16];
    const float* wn     = (const float*)d_in[17];
    float* out = (float*)d_out;

    float *gates, *b1p;
    __half *q16, *k16, *v16;
    __half *x16, *kv16, *kvp16, *qn16, *attn16, *w1p16, *h16, *ipw16, *owT16, *w116, *w216;
    cudaGetSymbolAddress((void**)&q16,    g_qp);
    cudaGetSymbolAddress((void**)&k16,    g_kp);
    cudaGetSymbolAddress((void**)&v16,    g_vp);
    cudaGetSymbolAddress((void**)&gates,  g_gates);
    cudaGetSymbolAddress((void**)&b1p,    g_b1p);
    cudaGetSymbolAddress((void**)&x16,    g_x16);
    cudaGetSymbolAddress((void**)&kv16,   g_kv16);
    cudaGetSymbolAddress((void**)&kvp16,  g_kvp16);
    cudaGetSymbolAddress((void**)&qn16,   g_qn16);
    cudaGetSymbolAddress((void**)&attn16, g_attn16);
    cudaGetSymbolAddress((void**)&w1p16,  g_w1p16);
    cudaGetSymbolAddress((void**)&h16,    g_h16);
    cudaGetSymbolAddress((void**)&ipw16,  g_ipw16);
    cudaGetSymbolAddress((void**)&owT16,  g_owT16);
    cudaGetSymbolAddress((void**)&w116,   g_w116);
    cudaGetSymbolAddress((void**)&w216,   g_w216);

    static cudaStream_t s1 = nullptr, s2 = nullptr;
    static cudaEvent_t evFork0 = nullptr, evGates = nullptr, evJoin = nullptr;
    static cudaEvent_t evQin = nullptr, evQdone = nullptr;
    static cudaEvent_t evC0 = nullptr, evF0 = nullptr;
    static bool attr_done = false;
    if (!attr_done) {
        cudaFuncSetAttribute(hgemm<0>, cudaFuncAttributeMaxDynamicSharedMemorySize, SMEM_DYN);
        cudaFuncSetAttribute(hgemm<1>, cudaFuncAttributeMaxDynamicSharedMemorySize, SMEM_DYN);
        cudaFuncSetAttribute(hgemm<2>, cudaFuncAttributeMaxDynamicSharedMemorySize, SMEM_DYN);
        cudaFuncSetAttribute(hgemm<3>, cudaFuncAttributeMaxDynamicSharedMemorySize, SMEM_DYN);
        cudaFuncSetAttribute(hgemm<4>, cudaFuncAttributeMaxDynamicSharedMemorySize, SMEM_DYN);
        cudaFuncSetAttribute(flash_attn, cudaFuncAttributeMaxDynamicSharedMemorySize, FA_SMEM);
        cudaStreamCreateWithFlags(&s1, cudaStreamNonBlocking);
        cudaStreamCreateWithFlags(&s2, cudaStreamNonBlocking);
        cudaEventCreateWithFlags(&evFork0, cudaEventDisableTiming);
        cudaEventCreateWithFlags(&evGates, cudaEventDisableTiming);
        cudaEventCreateWithFlags(&evJoin, cudaEventDisableTiming);
        cudaEventCreateWithFlags(&evQin, cudaEventDisableTiming);
        cudaEventCreateWithFlags(&evQdone, cudaEventDisableTiming);
        cudaEventCreateWithFlags(&evC0, cudaEventDisableTiming);
        cudaEventCreateWithFlags(&evF0, cudaEventDisableTiming);
        attr_done = true;
    }

    // ---- side stream s1 (weights-only prologue; forked at t=0) ----
    cudaEventRecord(evFork0, 0);
    cudaStreamWaitEvent(s1, evFork0, 0);
    f2h_b_kernel<<<(N4_B + 255)/256, 256, 0, s1>>>(W1, w116, W2, w216);
    owT_kernel<<<dim3(32, 32), 256, 0, s1>>>(ow, owT16);
    hgemm<0><<<dim3(MMD/BN, HIDD/BM), 256, SMEM_DYN, s1>>>(w116, owT16, nullptr, w1p16, HIDD, MMD, MMD, nullptr, nullptr);
    b1p_kernel<<<HIDD, 128, 0, s1>>>(W1, b1, ob, b1p);

    // main: fused LN(x)+gating (+x16 emission)
    lnxg_kernel<<<ROWS, 256>>>(x, ln_kv_g, ln_kv_b, pos, wg, wn, noise, kv16, kvp16, x16, gates);
    cudaEventRecord(evGates, 0);

    // side s1: expert-0 FC1
    cudaStreamWaitEvent(s1, evGates, 0);
    hgemm<2><<<dim3(32, 72), 256, SMEM_DYN, s1>>>(x16, w116, nullptr, h16, ROWS, HIDD, MMD, b1, gates);
    cudaEventRecord(evJoin, s1);

    // main: prologue for attention
    lnq_kernel<<<NQS, 256>>>(query, ln_q_g, ln_q_b, pos, qn16);
    f2h_a_kernel<<<(N4_IPW + 255)/256, 256>>>(ipw, ipw16);
    cudaEventRecord(evQin, 0);

    // side s2: Q projection
    cudaStreamWaitEvent(s2, evQin, 0);
    hgemm<1><<<dim3(8, 5), 256, SMEM_DYN, s2>>>(qn16, ipw16, nullptr, q16, NQS, MMD, MMD, ipb, nullptr);
    cudaEventRecord(evQdone, s2);

    // main: K/V projections
    hgemm<1><<<dim3(8, 72), 256, SMEM_DYN>>>(kvp16, ipw16 + MMD*MMD,   nullptr, k16, ROWS, MMD, MMD, ipb + MMD,   nullptr);
    hgemm<1><<<dim3(8, 72), 256, SMEM_DYN>>>(kv16,  ipw16 + 2*MMD*MMD, nullptr, v16, ROWS, MMD, MMD, ipb + 2*MMD, nullptr);

    cudaStreamWaitEvent(0, evQdone, 0);
    flash_attn<<<dim3(5, NBH), 256, FA_SMEM>>>(q16, k16, v16, attn16);

    // ---- pipelined tail: FC1e1 (folded W1') and FC2 in two row-halves ----
    cudaStreamWaitEvent(0, evJoin, 0);
    // FC1e1 half 0 (rows 0..4607)
    hgemm<3><<<dim3(32, 36), 256, SMEM_DYN>>>(attn16, w1p16, nullptr, h16, HROWS, HIDD, MMD, b1p, gates);
    cudaEventRecord(evC0, 0);
    // FC2 half 0 on side stream (overlaps FC1e1 half 1)
    cudaStreamWaitEvent(s1, evC0, 0);
    hgemm<4><<<dim3(32, 36), 256, SMEM_DYN, s1>>>(h16, w216, out, nullptr, HROWS, HIDD, HIDD, b2, gates);
    cudaEventRecord(evF0, s1);
    // FC1e1 half 1 (rows 4608..9215) on main
    hgemm<3><<<dim3(32, 36), 256, SMEM_DYN>>>(attn16 + (size_t)HROWS * MMD, w1p16, nullptr,
                                              h16 + (size_t)HROWS * HIDD, HROWS, HIDD, MMD,
                                              b1p, gates + 2 * HROWS);
    // FC2 half 1 on main
    hgemm<4><<<dim3(32, 36), 256, SMEM_DYN>>>(h16 + (size_t)HROWS * HIDD, w216,
                                              out + (size_t)HROWS * HIDD, nullptr,
                                              HROWS, HIDD, HIDD, b2, gates + 2 * HROWS);
    // join side stream back into main so the capture graph is fully connected
    cudaStreamWaitEvent(0, evF0, 0);
}